// round 1
// baseline (speedup 1.0000x reference)
#include <cuda_runtime.h>
#include <math.h>

#define BATCH 4
#define SEQ   4096
#define DIM   1024
#define NH    16
#define HD    64
#define BH    (BATCH*NH)          // 64
#define MTOT  (BATCH*SEQ)         // 16384
#define NSPLIT 8
#define LNEPS 1e-5f

// ---------------- scratch (static device globals; no allocation) -------------
__device__ float g_q   [MTOT*DIM];
__device__ float g_k   [MTOT*DIM];
__device__ float g_v   [MTOT*DIM];
__device__ float g_ao  [MTOT*DIM];
__device__ float g_proj[MTOT*DIM];
__device__ float g_part[NSPLIT*BH*2*HD*HD];
__device__ float g_amap[BH*HD*HD];

// ---------------- GEMM: C[m,n] = sum_k A[m,k]*B[n,k] (+bias[n]) --------------
// A: MxK row-major, B: NxK row-major (nn.Linear weight), C: MxN row-major.
// 128x128 block tile, BK=8, 256 threads, 8x8 per-thread microtile.
__global__ __launch_bounds__(256) void sgemm_nt(
    const float* __restrict__ A, const float* __restrict__ B,
    const float* __restrict__ bias, float* __restrict__ C,
    int M, int N, int K)
{
    __shared__ float As[8][128];
    __shared__ float Bs[8][128];
    int tid = threadIdx.x;
    int bm = blockIdx.y * 128;
    int bn = blockIdx.x * 128;

    int lr = tid >> 1;            // 0..127 : tile row loaded by this thread
    int lc = (tid & 1) * 4;       // 0 or 4 : k-offset (float4)
    const float* Aptr = A + (size_t)(bm + lr) * K + lc;
    const float* Bptr = B + (size_t)(bn + lr) * K + lc;

    int ty = tid >> 4;            // 0..15
    int tx = tid & 15;            // 0..15

    float acc[8][8];
#pragma unroll
    for (int i = 0; i < 8; ++i)
#pragma unroll
        for (int j = 0; j < 8; ++j) acc[i][j] = 0.0f;

    for (int k0 = 0; k0 < K; k0 += 8) {
        float4 a4 = *(const float4*)(Aptr + k0);
        float4 b4 = *(const float4*)(Bptr + k0);
        As[lc + 0][lr] = a4.x; As[lc + 1][lr] = a4.y;
        As[lc + 2][lr] = a4.z; As[lc + 3][lr] = a4.w;
        Bs[lc + 0][lr] = b4.x; Bs[lc + 1][lr] = b4.y;
        Bs[lc + 2][lr] = b4.z; Bs[lc + 3][lr] = b4.w;
        __syncthreads();
#pragma unroll
        for (int kk = 0; kk < 8; ++kk) {
            float a[8], b[8];
#pragma unroll
            for (int i = 0; i < 8; ++i) a[i] = As[kk][ty * 8 + i];
#pragma unroll
            for (int j = 0; j < 8; ++j) b[j] = Bs[kk][tx * 8 + j];
#pragma unroll
            for (int i = 0; i < 8; ++i)
#pragma unroll
                for (int j = 0; j < 8; ++j) acc[i][j] = fmaf(a[i], b[j], acc[i][j]);
        }
        __syncthreads();
    }

#pragma unroll
    for (int i = 0; i < 8; ++i) {
        int row = bm + ty * 8 + i;
        float* cp = C + (size_t)row * N + bn + tx * 8;
        if (bias) {
            const float* bp = bias + bn + tx * 8;
#pragma unroll
            for (int j = 0; j < 8; ++j) cp[j] = acc[i][j] + bp[j];
        } else {
#pragma unroll
            for (int j = 0; j < 8; ++j) cp[j] = acc[i][j];
        }
    }
}

// ---------------- per-(b,h) Gram partials: kk = K^T K, kv = K^T V ------------
// grid: (BH, NSPLIT), block 256. Each block handles 512 rows of n.
__global__ __launch_bounds__(256) void kkt_kernel()
{
    int bh = blockIdx.x;          // 0..63
    int split = blockIdx.y;       // 0..7
    int b = bh >> 4, h = bh & 15;
    const float* kbase = g_k + ((size_t)b * SEQ) * DIM + h * HD;
    const float* vbase = g_v + ((size_t)b * SEQ) * DIM + h * HD;

    __shared__ float Ks[64][64];
    __shared__ float Vs[64][64];
    int tid = threadIdx.x;
    int d  = tid >> 2;            // 0..63
    int e0 = (tid & 3) * 16;      // 0,16,32,48

    float akk[16], akv[16];
#pragma unroll
    for (int e = 0; e < 16; ++e) { akk[e] = 0.0f; akv[e] = 0.0f; }

    int nbase = split * (SEQ / NSPLIT);
    for (int t0 = 0; t0 < SEQ / NSPLIT; t0 += 64) {
#pragma unroll
        for (int i = 0; i < 4; ++i) {
            int li = tid + i * 256;       // 0..1023 float4 index
            int r = li >> 4;              // 16 float4 per 64-float row
            int c = (li & 15) * 4;
            size_t off = (size_t)(nbase + t0 + r) * DIM + c;
            float4 kv4 = *(const float4*)(kbase + off);
            float4 vv4 = *(const float4*)(vbase + off);
            Ks[r][c + 0] = kv4.x; Ks[r][c + 1] = kv4.y; Ks[r][c + 2] = kv4.z; Ks[r][c + 3] = kv4.w;
            Vs[r][c + 0] = vv4.x; Vs[r][c + 1] = vv4.y; Vs[r][c + 2] = vv4.z; Vs[r][c + 3] = vv4.w;
        }
        __syncthreads();
#pragma unroll 4
        for (int n = 0; n < 64; ++n) {
            float kd = Ks[n][d];
#pragma unroll
            for (int e = 0; e < 16; ++e) {
                akk[e] = fmaf(kd, Ks[n][e0 + e], akk[e]);
                akv[e] = fmaf(kd, Vs[n][e0 + e], akv[e]);
            }
        }
        __syncthreads();
    }

    float* pkk = g_part + ((size_t)(split * BH + bh) * 2 + 0) * (HD * HD);
    float* pkv = pkk + HD * HD;
#pragma unroll
    for (int e = 0; e < 16; ++e) {
        pkk[d * 64 + e0 + e] = akk[e];
        pkv[d * 64 + e0 + e] = akv[e];
    }
}

// ------- reduce partials, solve (kk+aI) X = ktv, column softmax -> g_amap ----
__global__ __launch_bounds__(256) void solve_kernel(
    const float* __restrict__ alpha_p, const float* __restrict__ temp_p)
{
    int bh = blockIdx.x;
    __shared__ float A[64][65];
    __shared__ float X[64][65];
    int tid = threadIdx.x;

    for (int i = tid; i < 4096; i += 256) {
        float skk = 0.0f, skv = 0.0f;
#pragma unroll
        for (int s = 0; s < NSPLIT; ++s) {
            const float* p = g_part + ((size_t)(s * BH + bh) * 2) * 4096;
            skk += p[i];
            skv += p[4096 + i];
        }
        A[i >> 6][i & 63] = skk;
        X[i >> 6][i & 63] = skv;
    }
    __syncthreads();
    if (tid < 64) A[tid][tid] += alpha_p[0];

    int r  = tid >> 2;
    int c0 = (tid & 3) * 16;
    for (int p = 0; p < 64; ++p) {
        __syncthreads();
        float pinv = 1.0f / A[p][p];
        __syncthreads();
        if (tid < 64)      A[p][tid]      *= pinv;
        else if (tid < 128) X[p][tid - 64] *= pinv;
        __syncthreads();
        float f = (r != p) ? A[r][p] : 0.0f;
        __syncthreads();
        if (r != p) {
#pragma unroll
            for (int c = 0; c < 16; ++c) {
                A[r][c0 + c] = fmaf(-f, A[p][c0 + c], A[r][c0 + c]);
                X[r][c0 + c] = fmaf(-f, X[p][c0 + c], X[r][c0 + c]);
            }
        }
    }
    __syncthreads();

    // softmax over d (rows) for each column e = tid, with / temperature
    if (tid < 64) {
        float invt = 1.0f / temp_p[0];
        float mx = -1e30f;
        for (int d = 0; d < 64; ++d) mx = fmaxf(mx, X[d][tid] * invt);
        float s = 0.0f;
        for (int d = 0; d < 64; ++d) s += expf(X[d][tid] * invt - mx);
        float inv_s = 1.0f / s;
        for (int d = 0; d < 64; ++d)
            g_amap[(size_t)bh * 4096 + d * 64 + tid] =
                expf(X[d][tid] * invt - mx) * inv_s;
    }
}

// ---------------- out = Q @ attn_map per (b,h) -------------------------------
// grid: (SEQ/64, BH), block 256
__global__ __launch_bounds__(256) void qmap_kernel()
{
    int mt = blockIdx.x;          // 0..63
    int bh = blockIdx.y;
    int b = bh >> 4, h = bh & 15;
    __shared__ float Am[64][64];
    __shared__ float Qs[64][65];
    int tid = threadIdx.x;

    for (int i = tid; i < 4096; i += 256)
        Am[i >> 6][i & 63] = g_amap[(size_t)bh * 4096 + i];

    const float* qbase = g_q + ((size_t)b * SEQ + mt * 64) * DIM + h * HD;
#pragma unroll
    for (int i = 0; i < 4; ++i) {
        int li = tid + i * 256;
        int r = li >> 4;
        int c = (li & 15) * 4;
        float4 q4 = *(const float4*)(qbase + (size_t)r * DIM + c);
        Qs[r][c + 0] = q4.x; Qs[r][c + 1] = q4.y; Qs[r][c + 2] = q4.z; Qs[r][c + 3] = q4.w;
    }
    __syncthreads();

    int m  = tid >> 2;
    int e0 = (tid & 3) * 16;
    float acc[16];
#pragma unroll
    for (int e = 0; e < 16; ++e) acc[e] = 0.0f;
#pragma unroll 4
    for (int d = 0; d < 64; ++d) {
        float qv = Qs[m][d];
#pragma unroll
        for (int e = 0; e < 16; ++e) acc[e] = fmaf(qv, Am[d][e0 + e], acc[e]);
    }

    float* op = g_ao + ((size_t)b * SEQ + mt * 64 + m) * DIM + h * HD + e0;
#pragma unroll
    for (int e4 = 0; e4 < 4; ++e4) {
        float4 o4 = make_float4(acc[e4*4+0], acc[e4*4+1], acc[e4*4+2], acc[e4*4+3]);
        *(float4*)(op + e4 * 4) = o4;
    }
}

// ---------------- LayerNorm(proj + x) ----------------------------------------
__global__ __launch_bounds__(256) void ln_kernel(
    const float* __restrict__ x, const float* __restrict__ gamma,
    const float* __restrict__ beta, float* __restrict__ out)
{
    int row = blockIdx.x;
    int tid = threadIdx.x;
    const float* pr = g_proj + (size_t)row * DIM;
    const float* xr = x      + (size_t)row * DIM;

    float4 pv = *(const float4*)(pr + tid * 4);
    float4 xv = *(const float4*)(xr + tid * 4);
    float v[4] = { pv.x + xv.x, pv.y + xv.y, pv.z + xv.z, pv.w + xv.w };

    float s = v[0] + v[1] + v[2] + v[3];
    float s2 = v[0]*v[0] + v[1]*v[1] + v[2]*v[2] + v[3]*v[3];

#pragma unroll
    for (int o = 16; o > 0; o >>= 1) {
        s  += __shfl_xor_sync(0xFFFFFFFFu, s,  o);
        s2 += __shfl_xor_sync(0xFFFFFFFFu, s2, o);
    }
    __shared__ float rs[8], rs2[8];
    int wid = tid >> 5, lane = tid & 31;
    if (lane == 0) { rs[wid] = s; rs2[wid] = s2; }
    __syncthreads();
    if (wid == 0) {
        float a  = (lane < 8) ? rs[lane]  : 0.0f;
        float a2 = (lane < 8) ? rs2[lane] : 0.0f;
#pragma unroll
        for (int o = 4; o > 0; o >>= 1) {
            a  += __shfl_xor_sync(0xFFFFFFFFu, a,  o);
            a2 += __shfl_xor_sync(0xFFFFFFFFu, a2, o);
        }
        if (lane == 0) { rs[0] = a; rs2[0] = a2; }
    }
    __syncthreads();
    float mu  = rs[0]  * (1.0f / DIM);
    float var = rs2[0] * (1.0f / DIM) - mu * mu;
    float rstd = rsqrtf(var + LNEPS);

    const float* gp = gamma + tid * 4;
    const float* bp = beta  + tid * 4;
    float4 o4;
    o4.x = (v[0] - mu) * rstd * gp[0] + bp[0];
    o4.y = (v[1] - mu) * rstd * gp[1] + bp[1];
    o4.z = (v[2] - mu) * rstd * gp[2] + bp[2];
    o4.w = (v[3] - mu) * rstd * gp[3] + bp[3];
    *(float4*)(out + (size_t)row * DIM + tid * 4) = o4;
}

// ---------------- host launcher ----------------------------------------------
extern "C" void kernel_launch(void* const* d_in, const int* in_sizes, int n_in,
                              void* d_out, int out_size)
{
    (void)in_sizes; (void)n_in; (void)out_size;
    const float* x     = (const float*)d_in[0];
    const float* Wq    = (const float*)d_in[1];
    const float* Wk    = (const float*)d_in[2];
    const float* Wv    = (const float*)d_in[3];
    const float* Wo    = (const float*)d_in[4];
    const float* bo    = (const float*)d_in[5];
    const float* alpha = (const float*)d_in[6];
    const float* temp  = (const float*)d_in[7];
    const float* gamma = (const float*)d_in[8];
    const float* beta  = (const float*)d_in[9];
    float* out = (float*)d_out;

    float *qp, *kp, *vp, *aop, *projp;
    cudaGetSymbolAddress((void**)&qp,    g_q);
    cudaGetSymbolAddress((void**)&kp,    g_k);
    cudaGetSymbolAddress((void**)&vp,    g_v);
    cudaGetSymbolAddress((void**)&aop,   g_ao);
    cudaGetSymbolAddress((void**)&projp, g_proj);

    dim3 gg(DIM / 128, MTOT / 128);
    sgemm_nt<<<gg, 256>>>(x, Wq, nullptr, qp, MTOT, DIM, DIM);
    sgemm_nt<<<gg, 256>>>(x, Wk, nullptr, kp, MTOT, DIM, DIM);
    sgemm_nt<<<gg, 256>>>(x, Wv, nullptr, vp, MTOT, DIM, DIM);

    kkt_kernel<<<dim3(BH, NSPLIT), 256>>>();
    solve_kernel<<<BH, 256>>>(alpha, temp);
    qmap_kernel<<<dim3(SEQ / 64, BH), 256>>>();

    sgemm_nt<<<gg, 256>>>(aop, Wo, bo, projp, MTOT, DIM, DIM);
    ln_kernel<<<MTOT, 256>>>(x, gamma, beta, out);
}

// round 2
// speedup vs baseline: 1.6286x; 1.6286x over previous
#include <cuda_runtime.h>
#include <math.h>

#define BATCH 4
#define SEQ   4096
#define DIM   1024
#define NH    16
#define HD    64
#define BH    (BATCH*NH)          // 64
#define MTOT  (BATCH*SEQ)         // 16384
#define NSPLIT 8
#define LNEPS 1e-5f

// ---------------- scratch (static device globals; no allocation) -------------
__device__ float g_q   [MTOT*DIM];
__device__ float g_k   [MTOT*DIM];
__device__ float g_v   [MTOT*DIM];
__device__ float g_ao  [MTOT*DIM];
__device__ float g_proj[MTOT*DIM];
__device__ float g_part[NSPLIT*BH*2*HD*HD];
__device__ float g_amap[BH*HD*HD];

// ---------------- tf32 helpers ------------------------------------------------
__device__ __forceinline__ unsigned f2tf(float x) {
    unsigned r;
    asm("cvt.rna.tf32.f32 %0, %1;" : "=r"(r) : "f"(x));
    return r;
}

__device__ __forceinline__ void mma8(float c[4],
    unsigned a0, unsigned a1, unsigned a2, unsigned a3,
    unsigned b0, unsigned b1)
{
    asm volatile(
        "mma.sync.aligned.m16n8k8.row.col.f32.tf32.tf32.f32 "
        "{%0,%1,%2,%3}, {%4,%5,%6,%7}, {%8,%9}, {%0,%1,%2,%3};"
        : "+f"(c[0]), "+f"(c[1]), "+f"(c[2]), "+f"(c[3])
        : "r"(a0), "r"(a1), "r"(a2), "r"(a3), "r"(b0), "r"(b1));
}

#define CP16(dst_u32, src_ptr) \
    asm volatile("cp.async.cg.shared.global [%0], [%1], 16;\n" \
                 :: "r"(dst_u32), "l"(src_ptr))
#define CPCOMMIT() asm volatile("cp.async.commit_group;\n" ::: "memory")
#define CPWAIT0()  asm volatile("cp.async.wait_group 0;\n" ::: "memory")

// ---------------- GEMM (tf32 3-way split, fp32-accurate) ----------------------
// C[m,n] = sum_k A[m,k]*B[n,k] (+bias[n]); A: MxK rm, B: NxK rm, C: MxN rm.
// 128x128 block tile, BK=16, 256 threads = 8 warps (2x4), warp tile 64x32.
__global__ __launch_bounds__(256, 2) void gemm_tf32(
    const float* __restrict__ A, const float* __restrict__ B,
    const float* __restrict__ bias, float* __restrict__ C,
    int M, int N, int K)
{
    __shared__ float As[2][128][20];
    __shared__ float Bs[2][128][20];

    const int tid  = threadIdx.x;
    const int lane = tid & 31;
    const int warp = tid >> 5;
    const int wm = (warp >> 2) * 64;   // warp M offset in tile
    const int wn = (warp & 3) * 32;    // warp N offset in tile
    const int bm = blockIdx.y * 128;
    const int bn = blockIdx.x * 128;
    const int g4 = lane >> 2;          // groupID
    const int tg = lane & 3;           // thread-in-group

    float acc[4][4][4];
#pragma unroll
    for (int t = 0; t < 4; ++t)
#pragma unroll
        for (int u = 0; u < 4; ++u)
#pragma unroll
            for (int r = 0; r < 4; ++r) acc[t][u][r] = 0.0f;

    // chunk loader: 128 rows x 16 k, as float4 per thread x2 per array
    auto loadc = [&](int kc, int bf) {
        int f = tid;
#pragma unroll
        for (int it = 0; it < 2; ++it, f += 256) {
            int row = f >> 2;
            int k4  = (f & 3) * 4;
            const float* sa = A + (size_t)(bm + row) * K + kc * 16 + k4;
            const float* sb = B + (size_t)(bn + row) * K + kc * 16 + k4;
            unsigned da = (unsigned)__cvta_generic_to_shared(&As[bf][row][k4]);
            unsigned db = (unsigned)__cvta_generic_to_shared(&Bs[bf][row][k4]);
            CP16(da, sa);
            CP16(db, sb);
        }
    };

    loadc(0, 0);
    CPCOMMIT();

    const int NK = K / 16;
    for (int kc = 0; kc < NK; ++kc) {
        CPWAIT0();
        __syncthreads();
        if (kc + 1 < NK) { loadc(kc + 1, (kc + 1) & 1); CPCOMMIT(); }

        const int bf = kc & 1;
#pragma unroll
        for (int s = 0; s < 2; ++s) {
            const int kk = s * 8 + tg;
            unsigned ahi[4][4], alo[4][4];
#pragma unroll
            for (int t = 0; t < 4; ++t) {
                int r0 = wm + t * 16 + g4;
                float x0 = As[bf][r0][kk];
                float x1 = As[bf][r0 + 8][kk];
                float x2 = As[bf][r0][kk + 4];
                float x3 = As[bf][r0 + 8][kk + 4];
                ahi[t][0] = f2tf(x0); alo[t][0] = f2tf(x0 - __uint_as_float(ahi[t][0]));
                ahi[t][1] = f2tf(x1); alo[t][1] = f2tf(x1 - __uint_as_float(ahi[t][1]));
                ahi[t][2] = f2tf(x2); alo[t][2] = f2tf(x2 - __uint_as_float(ahi[t][2]));
                ahi[t][3] = f2tf(x3); alo[t][3] = f2tf(x3 - __uint_as_float(ahi[t][3]));
            }
#pragma unroll
            for (int u = 0; u < 4; ++u) {
                int c0 = wn + u * 8 + g4;
                float y0 = Bs[bf][c0][kk];
                float y1 = Bs[bf][c0][kk + 4];
                unsigned bh0 = f2tf(y0), bl0 = f2tf(y0 - __uint_as_float(bh0));
                unsigned bh1 = f2tf(y1), bl1 = f2tf(y1 - __uint_as_float(bh1));
#pragma unroll
                for (int t = 0; t < 4; ++t) {
                    mma8(acc[t][u], alo[t][0], alo[t][1], alo[t][2], alo[t][3], bh0, bh1);
                    mma8(acc[t][u], ahi[t][0], ahi[t][1], ahi[t][2], ahi[t][3], bl0, bl1);
                    mma8(acc[t][u], ahi[t][0], ahi[t][1], ahi[t][2], ahi[t][3], bh0, bh1);
                }
            }
        }
        __syncthreads();
    }

    // epilogue
#pragma unroll
    for (int t = 0; t < 4; ++t) {
        int r = bm + wm + t * 16 + g4;
#pragma unroll
        for (int u = 0; u < 4; ++u) {
            int c = bn + wn + u * 8 + tg * 2;
            float b0 = 0.0f, b1 = 0.0f;
            if (bias) { b0 = bias[c]; b1 = bias[c + 1]; }
            *(float2*)&C[(size_t)r * N + c] =
                make_float2(acc[t][u][0] + b0, acc[t][u][1] + b1);
            *(float2*)&C[(size_t)(r + 8) * N + c] =
                make_float2(acc[t][u][2] + b0, acc[t][u][3] + b1);
        }
    }
}

// ---------------- per-(b,h) Gram partials: kk = K^T K, kv = K^T V ------------
// grid: (BH, NSPLIT), block 256. Output tile 64(d) x 128([kk|kv] cols).
__global__ __launch_bounds__(256) void kkt_kernel()
{
    int bh = blockIdx.x;
    int split = blockIdx.y;
    int b = bh >> 4, h = bh & 15;
    const float* kb = g_k + (size_t)b * SEQ * DIM + h * HD;
    const float* vb = g_v + (size_t)b * SEQ * DIM + h * HD;

    __shared__ float KV[64][132];   // [n][0:64]=K, [64:128]=V, pad 4
    int tid = threadIdx.x;
    int d0 = (tid >> 4) * 4;        // 0..60
    int e0 = (tid & 15) * 8;        // 0..120

    float acc[4][8];
#pragma unroll
    for (int i = 0; i < 4; ++i)
#pragma unroll
        for (int j = 0; j < 8; ++j) acc[i][j] = 0.0f;

    int nbase = split * (SEQ / NSPLIT);
    for (int t0 = 0; t0 < SEQ / NSPLIT; t0 += 64) {
        __syncthreads();
#pragma unroll
        for (int it = 0; it < 8; ++it) {
            int f = tid + it * 256;
            int tensor = f >> 10;
            int rem = f & 1023;
            int row = rem >> 4;
            int c4 = (rem & 15) * 4;
            const float* src = (tensor ? vb : kb) + (size_t)(nbase + t0 + row) * DIM + c4;
            float4 v4 = *(const float4*)src;
            float* dst = &KV[row][tensor * 64 + c4];
            dst[0] = v4.x; dst[1] = v4.y; dst[2] = v4.z; dst[3] = v4.w;
        }
        __syncthreads();
#pragma unroll 8
        for (int n = 0; n < 64; ++n) {
            float4 a  = *(const float4*)&KV[n][d0];
            float4 p0 = *(const float4*)&KV[n][e0];
            float4 p1 = *(const float4*)&KV[n][e0 + 4];
            float av[4] = { a.x, a.y, a.z, a.w };
            float bv[8] = { p0.x, p0.y, p0.z, p0.w, p1.x, p1.y, p1.z, p1.w };
#pragma unroll
            for (int i = 0; i < 4; ++i)
#pragma unroll
                for (int j = 0; j < 8; ++j) acc[i][j] = fmaf(av[i], bv[j], acc[i][j]);
        }
    }

    float* pkk = g_part + (size_t)(split * BH + bh) * 2 * 4096;
    float* pkv = pkk + 4096;
    bool isv = (e0 >= 64);
    int ec = isv ? (e0 - 64) : e0;
    float* dst = isv ? pkv : pkk;
#pragma unroll
    for (int i = 0; i < 4; ++i) {
        *(float4*)&dst[(d0 + i) * 64 + ec] =
            make_float4(acc[i][0], acc[i][1], acc[i][2], acc[i][3]);
        *(float4*)&dst[(d0 + i) * 64 + ec + 4] =
            make_float4(acc[i][4], acc[i][5], acc[i][6], acc[i][7]);
    }
}

// ------- reduce partials, solve (kk+aI) X = ktv, column softmax -> g_amap ----
__global__ __launch_bounds__(256) void solve_kernel(
    const float* __restrict__ alpha_p, const float* __restrict__ temp_p)
{
    int bh = blockIdx.x;
    __shared__ float A[64][65];
    __shared__ float X[64][65];
    int tid = threadIdx.x;

    for (int i = tid; i < 4096; i += 256) {
        float skk = 0.0f, skv = 0.0f;
#pragma unroll
        for (int s = 0; s < NSPLIT; ++s) {
            const float* p = g_part + ((size_t)(s * BH + bh) * 2) * 4096;
            skk += p[i];
            skv += p[4096 + i];
        }
        A[i >> 6][i & 63] = skk;
        X[i >> 6][i & 63] = skv;
    }
    __syncthreads();
    if (tid < 64) A[tid][tid] += alpha_p[0];

    int r  = tid >> 2;
    int c0 = (tid & 3) * 16;
    for (int p = 0; p < 64; ++p) {
        __syncthreads();
        float pinv = 1.0f / A[p][p];
        __syncthreads();
        if (tid < 64)      A[p][tid]      *= pinv;
        else if (tid < 128) X[p][tid - 64] *= pinv;
        __syncthreads();
        float f = (r != p) ? A[r][p] : 0.0f;
        __syncthreads();
        if (r != p) {
#pragma unroll
            for (int c = 0; c < 16; ++c) {
                A[r][c0 + c] = fmaf(-f, A[p][c0 + c], A[r][c0 + c]);
                X[r][c0 + c] = fmaf(-f, X[p][c0 + c], X[r][c0 + c]);
            }
        }
    }
    __syncthreads();

    if (tid < 64) {
        float invt = 1.0f / temp_p[0];
        float mx = -1e30f;
        for (int d = 0; d < 64; ++d) mx = fmaxf(mx, X[d][tid] * invt);
        float s = 0.0f;
        for (int d = 0; d < 64; ++d) s += expf(X[d][tid] * invt - mx);
        float inv_s = 1.0f / s;
        for (int d = 0; d < 64; ++d)
            g_amap[(size_t)bh * 4096 + d * 64 + tid] =
                expf(X[d][tid] * invt - mx) * inv_s;
    }
}

// ---------------- out = Q @ attn_map per (b,h) -------------------------------
// grid: (SEQ/64, BH), block 256, per-thread 4x4 microtile
__global__ __launch_bounds__(256) void qmap_kernel()
{
    int mt = blockIdx.x;
    int bh = blockIdx.y;
    int b = bh >> 4, h = bh & 15;
    __shared__ float Qs[64][68];
    __shared__ float Am[64][68];
    int tid = threadIdx.x;

    for (int i = tid * 4; i < 4096; i += 1024) {
        float4 v = *(const float4*)&g_amap[(size_t)bh * 4096 + i];
        *(float4*)&Am[i >> 6][i & 63] = v;
    }
    const float* qb = g_q + ((size_t)b * SEQ + mt * 64) * DIM + h * HD;
#pragma unroll
    for (int it = 0; it < 4; ++it) {
        int f = tid + it * 256;
        int row = f >> 4, c4 = (f & 15) * 4;
        float4 v = *(const float4*)(qb + (size_t)row * DIM + c4);
        *(float4*)&Qs[row][c4] = v;
    }
    __syncthreads();

    int m0 = (tid >> 4) * 4;
    int e0 = (tid & 15) * 4;
    float acc[4][4];
#pragma unroll
    for (int i = 0; i < 4; ++i)
#pragma unroll
        for (int j = 0; j < 4; ++j) acc[i][j] = 0.0f;

#pragma unroll 8
    for (int d = 0; d < 64; ++d) {
        float a0 = Qs[m0 + 0][d];
        float a1 = Qs[m0 + 1][d];
        float a2 = Qs[m0 + 2][d];
        float a3 = Qs[m0 + 3][d];
        float4 bb = *(const float4*)&Am[d][e0];
        float bv[4] = { bb.x, bb.y, bb.z, bb.w };
#pragma unroll
        for (int j = 0; j < 4; ++j) {
            acc[0][j] = fmaf(a0, bv[j], acc[0][j]);
            acc[1][j] = fmaf(a1, bv[j], acc[1][j]);
            acc[2][j] = fmaf(a2, bv[j], acc[2][j]);
            acc[3][j] = fmaf(a3, bv[j], acc[3][j]);
        }
    }

    float* ob = g_ao + ((size_t)b * SEQ + mt * 64) * DIM + h * HD;
#pragma unroll
    for (int i = 0; i < 4; ++i)
        *(float4*)&ob[(size_t)(m0 + i) * DIM + e0] =
            make_float4(acc[i][0], acc[i][1], acc[i][2], acc[i][3]);
}

// ---------------- LayerNorm(proj + x) ----------------------------------------
__global__ __launch_bounds__(256) void ln_kernel(
    const float* __restrict__ x, const float* __restrict__ gamma,
    const float* __restrict__ beta, float* __restrict__ out)
{
    int row = blockIdx.x;
    int tid = threadIdx.x;
    const float* pr = g_proj + (size_t)row * DIM;
    const float* xr = x      + (size_t)row * DIM;

    float4 pv = *(const float4*)(pr + tid * 4);
    float4 xv = *(const float4*)(xr + tid * 4);
    float v[4] = { pv.x + xv.x, pv.y + xv.y, pv.z + xv.z, pv.w + xv.w };

    float s = v[0] + v[1] + v[2] + v[3];
    float s2 = v[0]*v[0] + v[1]*v[1] + v[2]*v[2] + v[3]*v[3];

#pragma unroll
    for (int o = 16; o > 0; o >>= 1) {
        s  += __shfl_xor_sync(0xFFFFFFFFu, s,  o);
        s2 += __shfl_xor_sync(0xFFFFFFFFu, s2, o);
    }
    __shared__ float rs[8], rs2[8];
    int wid = tid >> 5, lane = tid & 31;
    if (lane == 0) { rs[wid] = s; rs2[wid] = s2; }
    __syncthreads();
    if (wid == 0) {
        float a  = (lane < 8) ? rs[lane]  : 0.0f;
        float a2 = (lane < 8) ? rs2[lane] : 0.0f;
#pragma unroll
        for (int o = 4; o > 0; o >>= 1) {
            a  += __shfl_xor_sync(0xFFFFFFFFu, a,  o);
            a2 += __shfl_xor_sync(0xFFFFFFFFu, a2, o);
        }
        if (lane == 0) { rs[0] = a; rs2[0] = a2; }
    }
    __syncthreads();
    float mu  = rs[0]  * (1.0f / DIM);
    float var = rs2[0] * (1.0f / DIM) - mu * mu;
    float rstd = rsqrtf(var + LNEPS);

    const float* gp = gamma + tid * 4;
    const float* bp = beta  + tid * 4;
    float4 o4;
    o4.x = (v[0] - mu) * rstd * gp[0] + bp[0];
    o4.y = (v[1] - mu) * rstd * gp[1] + bp[1];
    o4.z = (v[2] - mu) * rstd * gp[2] + bp[2];
    o4.w = (v[3] - mu) * rstd * gp[3] + bp[3];
    *(float4*)(out + (size_t)row * DIM + tid * 4) = o4;
}

// ---------------- host launcher ----------------------------------------------
extern "C" void kernel_launch(void* const* d_in, const int* in_sizes, int n_in,
                              void* d_out, int out_size)
{
    (void)in_sizes; (void)n_in; (void)out_size;
    const float* x     = (const float*)d_in[0];
    const float* Wq    = (const float*)d_in[1];
    const float* Wk    = (const float*)d_in[2];
    const float* Wv    = (const float*)d_in[3];
    const float* Wo    = (const float*)d_in[4];
    const float* bo    = (const float*)d_in[5];
    const float* alpha = (const float*)d_in[6];
    const float* temp  = (const float*)d_in[7];
    const float* gamma = (const float*)d_in[8];
    const float* beta  = (const float*)d_in[9];
    float* out = (float*)d_out;

    float *qp, *kp, *vp, *aop, *projp;
    cudaGetSymbolAddress((void**)&qp,    g_q);
    cudaGetSymbolAddress((void**)&kp,    g_k);
    cudaGetSymbolAddress((void**)&vp,    g_v);
    cudaGetSymbolAddress((void**)&aop,   g_ao);
    cudaGetSymbolAddress((void**)&projp, g_proj);

    dim3 gg(DIM / 128, MTOT / 128);
    gemm_tf32<<<gg, 256>>>(x, Wq, nullptr, qp, MTOT, DIM, DIM);
    gemm_tf32<<<gg, 256>>>(x, Wk, nullptr, kp, MTOT, DIM, DIM);
    gemm_tf32<<<gg, 256>>>(x, Wv, nullptr, vp, MTOT, DIM, DIM);

    kkt_kernel<<<dim3(BH, NSPLIT), 256>>>();
    solve_kernel<<<BH, 256>>>(alpha, temp);
    qmap_kernel<<<dim3(SEQ / 64, BH), 256>>>();

    gemm_tf32<<<gg, 256>>>(aop, Wo, bo, projp, MTOT, DIM, DIM);
    ln_kernel<<<MTOT, 256>>>(x, gamma, beta, out);
}

// round 3
// speedup vs baseline: 2.9508x; 1.8119x over previous
#include <cuda_runtime.h>
#include <cuda_bf16.h>
#include <math.h>

#define BATCH 4
#define SEQ   4096
#define DIM   1024
#define NH    16
#define HD    64
#define BH    (BATCH*NH)          // 64
#define MTOT  (BATCH*SEQ)         // 16384
#define K3    (3*DIM)             // 3072
#define NSPLIT 8
#define LNEPS 1e-5f

// ---------------- scratch (static device globals; no allocation) -------------
__device__ float g_q   [MTOT*DIM];
__device__ float g_k   [MTOT*DIM];
__device__ float g_v   [MTOT*DIM];
__device__ float g_ao  [MTOT*DIM];
__device__ float g_proj[MTOT*DIM];
__device__ float g_part[NSPLIT*BH*2*HD*HD];
__device__ float g_amap[BH*HD*HD];
__device__ __align__(16) __nv_bfloat16 g_a3[(size_t)MTOT*K3];
__device__ __align__(16) __nv_bfloat16 g_w3[3][(size_t)DIM*K3];

// ---------------- async copy helpers ------------------------------------------
#define CP16(dst_u32, src_ptr) \
    asm volatile("cp.async.cg.shared.global [%0], [%1], 16;\n" \
                 :: "r"(dst_u32), "l"(src_ptr))
#define CPCOMMIT() asm volatile("cp.async.commit_group;\n" ::: "memory")
#define CPWAIT1()  asm volatile("cp.async.wait_group 1;\n" ::: "memory")

__device__ __forceinline__ void ldsm4(unsigned r[4], unsigned addr) {
    asm volatile("ldmatrix.sync.aligned.m8n8.x4.shared.b16 {%0,%1,%2,%3}, [%4];"
                 : "=r"(r[0]), "=r"(r[1]), "=r"(r[2]), "=r"(r[3]) : "r"(addr));
}

__device__ __forceinline__ void mma16816(float* c, const unsigned a[4],
                                         unsigned b0, unsigned b1) {
    asm volatile(
        "mma.sync.aligned.m16n8k16.row.col.f32.bf16.bf16.f32 "
        "{%0,%1,%2,%3}, {%4,%5,%6,%7}, {%8,%9}, {%0,%1,%2,%3};"
        : "+f"(c[0]), "+f"(c[1]), "+f"(c[2]), "+f"(c[3])
        : "r"(a[0]), "r"(a[1]), "r"(a[2]), "r"(a[3]), "r"(b0), "r"(b1));
}

// ---------------- f32 -> interleaved bf16 hi/lo (3-term split) ----------------
// mode 0 (A-side): out[3k..] = {hi, lo, hi};  mode 1 (B-side): {hi, hi, lo}
__global__ __launch_bounds__(256) void conv3_kernel(
    const float* __restrict__ src, __nv_bfloat16* __restrict__ dst, int mode)
{
    int t = blockIdx.x * blockDim.x + threadIdx.x;
    size_t base = (size_t)t * 8;
    float4 v0 = *(const float4*)(src + base);
    float4 v1 = *(const float4*)(src + base + 4);
    float xs[8] = { v0.x, v0.y, v0.z, v0.w, v1.x, v1.y, v1.z, v1.w };
    __nv_bfloat16 o[24];
#pragma unroll
    for (int i = 0; i < 8; ++i) {
        float x = xs[i];
        __nv_bfloat16 hi = __float2bfloat16(x);
        __nv_bfloat16 lo = __float2bfloat16(x - __bfloat162float(hi));
        if (mode == 0) { o[3*i] = hi; o[3*i+1] = lo; o[3*i+2] = hi; }
        else           { o[3*i] = hi; o[3*i+1] = hi; o[3*i+2] = lo; }
    }
    uint4* dp = (uint4*)(dst + base * 3);
    const uint4* op = (const uint4*)o;
    dp[0] = op[0]; dp[1] = op[1]; dp[2] = op[2];
}

// ---------------- bf16 GEMM (fp32-emulated), C[m,n]=sum_k A3[m,k]*B3[n,k] ----
// 128x128 tile, BK=64 bf16, 256 threads = 8 warps (2x4), warp tile 64x32.
// 3-stage cp.async pipeline, XOR-swizzled smem, ldmatrix fragments.
__global__ __launch_bounds__(256) void gemm_bf16(
    const __nv_bfloat16* __restrict__ A3, const __nv_bfloat16* __restrict__ B3,
    const float* __restrict__ bias, float* __restrict__ C, int M, int N)
{
    extern __shared__ __nv_bfloat16 sm[];
    // byte layout: A bufs [0,3)*16384 ; B bufs 49152 + [0,3)*16384
    const unsigned smem_base = (unsigned)__cvta_generic_to_shared(sm);
    const int tid  = threadIdx.x;
    const int lane = tid & 31;
    const int warp = tid >> 5;
    const int wm = (warp >> 2) * 64;
    const int wn = (warp & 3) * 32;
    const int bm = blockIdx.y * 128;
    const int bn = blockIdx.x * 128;
    const int g4 = lane >> 2;
    const int tg = lane & 3;

    float acc[4][4][4];
#pragma unroll
    for (int t = 0; t < 4; ++t)
#pragma unroll
        for (int u = 0; u < 4; ++u)
#pragma unroll
            for (int r = 0; r < 4; ++r) acc[t][u][r] = 0.0f;

    auto load_chunk = [&](int kc, int bf) {
#pragma unroll
        for (int it = 0; it < 4; ++it) {
            int idx = tid + it * 256;
            int row = idx >> 3;
            int c8  = idx & 7;
            const __nv_bfloat16* sa = A3 + (size_t)(bm + row) * K3 + kc * 64 + c8 * 8;
            const __nv_bfloat16* sb = B3 + (size_t)(bn + row) * K3 + kc * 64 + c8 * 8;
            unsigned sw = (unsigned)((c8 ^ (row & 7)) * 16);
            unsigned da = smem_base + bf * 16384 + row * 128 + sw;
            unsigned db = smem_base + 49152 + bf * 16384 + row * 128 + sw;
            CP16(da, sa);
            CP16(db, sb);
        }
    };

    // ldmatrix thread-address components
    const int khalf = lane >> 4;                 // 0/1 -> k 0-7 / 8-15
    int rowA[4], rowB[2];
#pragma unroll
    for (int t = 0; t < 4; ++t) rowA[t] = wm + t * 16 + (lane & 15);
#pragma unroll
    for (int p = 0; p < 2; ++p) rowB[p] = wn + p * 16 + (lane & 15);

    load_chunk(0, 0); CPCOMMIT();
    load_chunk(1, 1); CPCOMMIT();

    const int NC = K3 / 64;   // 48
    for (int kc = 0; kc < NC; ++kc) {
        CPWAIT1();
        __syncthreads();
        if (kc + 2 < NC) { load_chunk(kc + 2, (kc + 2) % 3); CPCOMMIT(); }

        const int bf = kc % 3;
        const unsigned abase = smem_base + bf * 16384;
        const unsigned bbase = smem_base + 49152 + bf * 16384;

#pragma unroll
        for (int s = 0; s < 4; ++s) {
            const int ch = s * 2 + khalf;        // 16B-chunk id within row
            unsigned a[4][4], b[2][4];
#pragma unroll
            for (int t = 0; t < 4; ++t) {
                unsigned addr = abase + rowA[t] * 128 +
                                (unsigned)((ch ^ (rowA[t] & 7)) * 16);
                ldsm4(a[t], addr);
            }
#pragma unroll
            for (int p = 0; p < 2; ++p) {
                unsigned addr = bbase + rowB[p] * 128 +
                                (unsigned)((ch ^ (rowB[p] & 7)) * 16);
                ldsm4(b[p], addr);
            }
#pragma unroll
            for (int t = 0; t < 4; ++t)
#pragma unroll
                for (int u = 0; u < 4; ++u) {
                    int p = u >> 1, h = u & 1;
                    mma16816(acc[t][u], a[t], b[p][h], b[p][2 + h]);
                }
        }
    }

    // epilogue (same acc layout as tf32 m16n8: c0,c1 @ row g4; c2,c3 @ row g4+8)
#pragma unroll
    for (int t = 0; t < 4; ++t) {
        int r = bm + wm + t * 16 + g4;
#pragma unroll
        for (int u = 0; u < 4; ++u) {
            int c = bn + wn + u * 8 + tg * 2;
            float b0 = 0.0f, b1 = 0.0f;
            if (bias) { b0 = bias[c]; b1 = bias[c + 1]; }
            *(float2*)&C[(size_t)r * N + c] =
                make_float2(acc[t][u][0] + b0, acc[t][u][1] + b1);
            *(float2*)&C[(size_t)(r + 8) * N + c] =
                make_float2(acc[t][u][2] + b0, acc[t][u][3] + b1);
        }
    }
}

// ---------------- per-(b,h) Gram partials: kk = K^T K, kv = K^T V ------------
__global__ __launch_bounds__(256) void kkt_kernel()
{
    int bh = blockIdx.x;
    int split = blockIdx.y;
    int b = bh >> 4, h = bh & 15;
    const float* kb = g_k + (size_t)b * SEQ * DIM + h * HD;
    const float* vb = g_v + (size_t)b * SEQ * DIM + h * HD;

    __shared__ float KV[64][132];
    int tid = threadIdx.x;
    int d0 = (tid >> 4) * 4;
    int e0 = (tid & 15) * 8;

    float acc[4][8];
#pragma unroll
    for (int i = 0; i < 4; ++i)
#pragma unroll
        for (int j = 0; j < 8; ++j) acc[i][j] = 0.0f;

    int nbase = split * (SEQ / NSPLIT);
    for (int t0 = 0; t0 < SEQ / NSPLIT; t0 += 64) {
        __syncthreads();
#pragma unroll
        for (int it = 0; it < 8; ++it) {
            int f = tid + it * 256;
            int tensor = f >> 10;
            int rem = f & 1023;
            int row = rem >> 4;
            int c4 = (rem & 15) * 4;
            const float* src = (tensor ? vb : kb) + (size_t)(nbase + t0 + row) * DIM + c4;
            float4 v4 = *(const float4*)src;
            float* dst = &KV[row][tensor * 64 + c4];
            dst[0] = v4.x; dst[1] = v4.y; dst[2] = v4.z; dst[3] = v4.w;
        }
        __syncthreads();
#pragma unroll 8
        for (int n = 0; n < 64; ++n) {
            float4 a  = *(const float4*)&KV[n][d0];
            float4 p0 = *(const float4*)&KV[n][e0];
            float4 p1 = *(const float4*)&KV[n][e0 + 4];
            float av[4] = { a.x, a.y, a.z, a.w };
            float bv[8] = { p0.x, p0.y, p0.z, p0.w, p1.x, p1.y, p1.z, p1.w };
#pragma unroll
            for (int i = 0; i < 4; ++i)
#pragma unroll
                for (int j = 0; j < 8; ++j) acc[i][j] = fmaf(av[i], bv[j], acc[i][j]);
        }
    }

    float* pkk = g_part + (size_t)(split * BH + bh) * 2 * 4096;
    float* pkv = pkk + 4096;
    bool isv = (e0 >= 64);
    int ec = isv ? (e0 - 64) : e0;
    float* dst = isv ? pkv : pkk;
#pragma unroll
    for (int i = 0; i < 4; ++i) {
        *(float4*)&dst[(d0 + i) * 64 + ec] =
            make_float4(acc[i][0], acc[i][1], acc[i][2], acc[i][3]);
        *(float4*)&dst[(d0 + i) * 64 + ec + 4] =
            make_float4(acc[i][4], acc[i][5], acc[i][6], acc[i][7]);
    }
}

// ------- reduce partials, solve (kk+aI) X = ktv, column softmax -> g_amap ----
__global__ __launch_bounds__(256) void solve_kernel(
    const float* __restrict__ alpha_p, const float* __restrict__ temp_p)
{
    int bh = blockIdx.x;
    __shared__ float A[64][65];
    __shared__ float X[64][65];
    int tid = threadIdx.x;

    for (int i = tid; i < 4096; i += 256) {
        float skk = 0.0f, skv = 0.0f;
#pragma unroll
        for (int s = 0; s < NSPLIT; ++s) {
            const float* p = g_part + ((size_t)(s * BH + bh) * 2) * 4096;
            skk += p[i];
            skv += p[4096 + i];
        }
        A[i >> 6][i & 63] = skk;
        X[i >> 6][i & 63] = skv;
    }
    __syncthreads();
    if (tid < 64) A[tid][tid] += alpha_p[0];

    int r  = tid >> 2;
    int c0 = (tid & 3) * 16;
    for (int p = 0; p < 64; ++p) {
        __syncthreads();
        float pinv = 1.0f / A[p][p];
        __syncthreads();
        if (tid < 64)      A[p][tid]      *= pinv;
        else if (tid < 128) X[p][tid - 64] *= pinv;
        __syncthreads();
        float f = (r != p) ? A[r][p] : 0.0f;
        __syncthreads();
        if (r != p) {
#pragma unroll
            for (int c = 0; c < 16; ++c) {
                A[r][c0 + c] = fmaf(-f, A[p][c0 + c], A[r][c0 + c]);
                X[r][c0 + c] = fmaf(-f, X[p][c0 + c], X[r][c0 + c]);
            }
        }
    }
    __syncthreads();

    if (tid < 64) {
        float invt = 1.0f / temp_p[0];
        float mx = -1e30f;
        for (int d = 0; d < 64; ++d) mx = fmaxf(mx, X[d][tid] * invt);
        float s = 0.0f;
        for (int d = 0; d < 64; ++d) s += expf(X[d][tid] * invt - mx);
        float inv_s = 1.0f / s;
        for (int d = 0; d < 64; ++d)
            g_amap[(size_t)bh * 4096 + d * 64 + tid] =
                expf(X[d][tid] * invt - mx) * inv_s;
    }
}

// ---------------- out = Q @ attn_map per (b,h) -------------------------------
__global__ __launch_bounds__(256) void qmap_kernel()
{
    int mt = blockIdx.x;
    int bh = blockIdx.y;
    int b = bh >> 4, h = bh & 15;
    __shared__ float Qs[64][68];
    __shared__ float Am[64][68];
    int tid = threadIdx.x;

    for (int i = tid * 4; i < 4096; i += 1024) {
        float4 v = *(const float4*)&g_amap[(size_t)bh * 4096 + i];
        *(float4*)&Am[i >> 6][i & 63] = v;
    }
    const float* qb = g_q + ((size_t)b * SEQ + mt * 64) * DIM + h * HD;
#pragma unroll
    for (int it = 0; it < 4; ++it) {
        int f = tid + it * 256;
        int row = f >> 4, c4 = (f & 15) * 4;
        float4 v = *(const float4*)(qb + (size_t)row * DIM + c4);
        *(float4*)&Qs[row][c4] = v;
    }
    __syncthreads();

    int m0 = (tid >> 4) * 4;
    int e0 = (tid & 15) * 4;
    float acc[4][4];
#pragma unroll
    for (int i = 0; i < 4; ++i)
#pragma unroll
        for (int j = 0; j < 4; ++j) acc[i][j] = 0.0f;

#pragma unroll 8
    for (int d = 0; d < 64; ++d) {
        float a0 = Qs[m0 + 0][d];
        float a1 = Qs[m0 + 1][d];
        float a2 = Qs[m0 + 2][d];
        float a3 = Qs[m0 + 3][d];
        float4 bb = *(const float4*)&Am[d][e0];
        float bv[4] = { bb.x, bb.y, bb.z, bb.w };
#pragma unroll
        for (int j = 0; j < 4; ++j) {
            acc[0][j] = fmaf(a0, bv[j], acc[0][j]);
            acc[1][j] = fmaf(a1, bv[j], acc[1][j]);
            acc[2][j] = fmaf(a2, bv[j], acc[2][j]);
            acc[3][j] = fmaf(a3, bv[j], acc[3][j]);
        }
    }

    float* ob = g_ao + ((size_t)b * SEQ + mt * 64) * DIM + h * HD;
#pragma unroll
    for (int i = 0; i < 4; ++i)
        *(float4*)&ob[(size_t)(m0 + i) * DIM + e0] =
            make_float4(acc[i][0], acc[i][1], acc[i][2], acc[i][3]);
}

// ---------------- LayerNorm(proj + x) ----------------------------------------
__global__ __launch_bounds__(256) void ln_kernel(
    const float* __restrict__ x, const float* __restrict__ gamma,
    const float* __restrict__ beta, float* __restrict__ out)
{
    int row = blockIdx.x;
    int tid = threadIdx.x;
    const float* pr = g_proj + (size_t)row * DIM;
    const float* xr = x      + (size_t)row * DIM;

    float4 pv = *(const float4*)(pr + tid * 4);
    float4 xv = *(const float4*)(xr + tid * 4);
    float v[4] = { pv.x + xv.x, pv.y + xv.y, pv.z + xv.z, pv.w + xv.w };

    float s = v[0] + v[1] + v[2] + v[3];
    float s2 = v[0]*v[0] + v[1]*v[1] + v[2]*v[2] + v[3]*v[3];

#pragma unroll
    for (int o = 16; o > 0; o >>= 1) {
        s  += __shfl_xor_sync(0xFFFFFFFFu, s,  o);
        s2 += __shfl_xor_sync(0xFFFFFFFFu, s2, o);
    }
    __shared__ float rs[8], rs2[8];
    int wid = tid >> 5, lane = tid & 31;
    if (lane == 0) { rs[wid] = s; rs2[wid] = s2; }
    __syncthreads();
    if (wid == 0) {
        float a  = (lane < 8) ? rs[lane]  : 0.0f;
        float a2 = (lane < 8) ? rs2[lane] : 0.0f;
#pragma unroll
        for (int o = 4; o > 0; o >>= 1) {
            a  += __shfl_xor_sync(0xFFFFFFFFu, a,  o);
            a2 += __shfl_xor_sync(0xFFFFFFFFu, a2, o);
        }
        if (lane == 0) { rs[0] = a; rs2[0] = a2; }
    }
    __syncthreads();
    float mu  = rs[0]  * (1.0f / DIM);
    float var = rs2[0] * (1.0f / DIM) - mu * mu;
    float rstd = rsqrtf(var + LNEPS);

    const float* gp = gamma + tid * 4;
    const float* bp = beta  + tid * 4;
    float4 o4;
    o4.x = (v[0] - mu) * rstd * gp[0] + bp[0];
    o4.y = (v[1] - mu) * rstd * gp[1] + bp[1];
    o4.z = (v[2] - mu) * rstd * gp[2] + bp[2];
    o4.w = (v[3] - mu) * rstd * gp[3] + bp[3];
    *(float4*)(out + (size_t)row * DIM + tid * 4) = o4;
}

// ---------------- host launcher ----------------------------------------------
extern "C" void kernel_launch(void* const* d_in, const int* in_sizes, int n_in,
                              void* d_out, int out_size)
{
    (void)in_sizes; (void)n_in; (void)out_size;
    const float* x     = (const float*)d_in[0];
    const float* Wq    = (const float*)d_in[1];
    const float* Wk    = (const float*)d_in[2];
    const float* Wv    = (const float*)d_in[3];
    const float* Wo    = (const float*)d_in[4];
    const float* bo    = (const float*)d_in[5];
    const float* alpha = (const float*)d_in[6];
    const float* temp  = (const float*)d_in[7];
    const float* gamma = (const float*)d_in[8];
    const float* beta  = (const float*)d_in[9];
    float* out = (float*)d_out;

    float *qp, *kp, *vp, *aop, *projp;
    __nv_bfloat16 *a3p, *w3p;
    cudaGetSymbolAddress((void**)&qp,    g_q);
    cudaGetSymbolAddress((void**)&kp,    g_k);
    cudaGetSymbolAddress((void**)&vp,    g_v);
    cudaGetSymbolAddress((void**)&aop,   g_ao);
    cudaGetSymbolAddress((void**)&projp, g_proj);
    cudaGetSymbolAddress((void**)&a3p,   g_a3);
    cudaGetSymbolAddress((void**)&w3p,   g_w3);

    const int SMEM_GEMM = 98304;  // 3-stage * (16KB A + 16KB B)
    cudaFuncSetAttribute(gemm_bf16,
                         cudaFuncAttributeMaxDynamicSharedMemorySize, SMEM_GEMM);

    // convert inputs to interleaved bf16 hi/lo
    conv3_kernel<<<MTOT*DIM/2048, 256>>>(x,  a3p, 0);
    conv3_kernel<<<DIM*DIM/2048, 256>>>(Wq, w3p + 0*(size_t)DIM*K3, 1);
    conv3_kernel<<<DIM*DIM/2048, 256>>>(Wk, w3p + 1*(size_t)DIM*K3, 1);
    conv3_kernel<<<DIM*DIM/2048, 256>>>(Wv, w3p + 2*(size_t)DIM*K3, 1);

    dim3 gg(DIM / 128, MTOT / 128);
    gemm_bf16<<<gg, 256, SMEM_GEMM>>>(a3p, w3p + 0*(size_t)DIM*K3, nullptr, qp, MTOT, DIM);
    gemm_bf16<<<gg, 256, SMEM_GEMM>>>(a3p, w3p + 1*(size_t)DIM*K3, nullptr, kp, MTOT, DIM);
    gemm_bf16<<<gg, 256, SMEM_GEMM>>>(a3p, w3p + 2*(size_t)DIM*K3, nullptr, vp, MTOT, DIM);

    kkt_kernel<<<dim3(BH, NSPLIT), 256>>>();
    solve_kernel<<<BH, 256>>>(alpha, temp);
    qmap_kernel<<<dim3(SEQ / 64, BH), 256>>>();

    conv3_kernel<<<MTOT*DIM/2048, 256>>>(aop, a3p, 0);
    conv3_kernel<<<DIM*DIM/2048, 256>>>(Wo, w3p + 0*(size_t)DIM*K3, 1);
    gemm_bf16<<<gg, 256, SMEM_GEMM>>>(a3p, w3p + 0*(size_t)DIM*K3, bo, projp, MTOT, DIM);

    ln_kernel<<<MTOT, 256>>>(x, gamma, beta, out);
}

// round 6
// speedup vs baseline: 4.4010x; 1.4915x over previous
#include <cuda_runtime.h>
#include <cuda_fp16.h>
#include <cstdint>
#include <math.h>

#define BATCH 4
#define SEQ   4096
#define DIM   1024
#define NH    16
#define HD    64
#define BH    (BATCH*NH)          // 64
#define MTOT  (BATCH*SEQ)         // 16384
#define K2    (2*DIM)             // 2048
#define NSPLIT 8
#define LNEPS 1e-5f

// ---------------- scratch (static device globals; no allocation) -------------
__device__ float g_q   [MTOT*DIM];
__device__ float g_k   [MTOT*DIM];
__device__ float g_v   [MTOT*DIM];
__device__ float g_ao  [MTOT*DIM];
__device__ float g_proj[MTOT*DIM];
__device__ float g_part[NSPLIT*BH*2*HD*HD];
__device__ float g_amap[BH*HD*HD];
__device__ __align__(16) __half g_a2[(size_t)MTOT*K2];
__device__ __align__(16) __half g_w2[3][(size_t)DIM*K2];

// ---------------- async copy / mma helpers ------------------------------------
#define CP16(dst_u32, src_ptr) \
    asm volatile("cp.async.cg.shared.global [%0], [%1], 16;\n" \
                 :: "r"(dst_u32), "l"(src_ptr))
#define CPCOMMIT() asm volatile("cp.async.commit_group;\n" ::: "memory")
#define CPWAIT1()  asm volatile("cp.async.wait_group 1;\n" ::: "memory")

__device__ __forceinline__ void ldsm4(unsigned r[4], unsigned addr) {
    asm volatile("ldmatrix.sync.aligned.m8n8.x4.shared.b16 {%0,%1,%2,%3}, [%4];"
                 : "=r"(r[0]), "=r"(r[1]), "=r"(r[2]), "=r"(r[3]) : "r"(addr));
}

__device__ __forceinline__ void mma16816(float* c, const unsigned a[4],
                                         unsigned b0, unsigned b1) {
    asm volatile(
        "mma.sync.aligned.m16n8k16.row.col.f32.f16.f16.f32 "
        "{%0,%1,%2,%3}, {%4,%5,%6,%7}, {%8,%9}, {%0,%1,%2,%3};"
        : "+f"(c[0]), "+f"(c[1]), "+f"(c[2]), "+f"(c[3])
        : "r"(a[0]), "r"(a[1]), "r"(a[2]), "r"(a[3]), "r"(b0), "r"(b1));
}

// ---------------- f32 -> interleaved fp16 (2-term split) ----------------------
// mode 0 (A-side): out[2k..] = {hi, lo};  mode 1 (B-side): {hi, hi}
__global__ __launch_bounds__(256) void conv2_kernel(
    const float* __restrict__ src, __half* __restrict__ dst, int mode)
{
    int t = blockIdx.x * blockDim.x + threadIdx.x;
    size_t base = (size_t)t * 8;
    float4 v0 = *(const float4*)(src + base);
    float4 v1 = *(const float4*)(src + base + 4);
    float xs[8] = { v0.x, v0.y, v0.z, v0.w, v1.x, v1.y, v1.z, v1.w };
    __half o[16];
#pragma unroll
    for (int i = 0; i < 8; ++i) {
        float x = xs[i];
        __half hi = __float2half_rn(x);
        if (mode == 0) {
            __half lo = __float2half_rn(x - __half2float(hi));
            o[2*i] = hi; o[2*i+1] = lo;
        } else {
            o[2*i] = hi; o[2*i+1] = hi;
        }
    }
    uint4* dp = (uint4*)(dst + base * 2);
    const uint4* op = (const uint4*)o;
    dp[0] = op[0]; dp[1] = op[1];
}

// ---------------- fp16 GEMM (fp32-emulated), C[m,n]=sum_k A2[m,k]*B2[n,k] -----
// 128x128 tile, BK=64 fp16, 256 threads = 8 warps (2x4), warp tile 64x32.
// 3-stage cp.async pipeline, XOR-swizzled smem, ldmatrix fragments.
__global__ __launch_bounds__(256) void gemm_f16(
    const __half* __restrict__ A2, const __half* __restrict__ B2,
    const float* __restrict__ bias, float* __restrict__ C, int M, int N)
{
    extern __shared__ __half sm[];
    // byte layout: A bufs [0,3)*16384 ; B bufs 49152 + [0,3)*16384
    const unsigned smem_base = (unsigned)__cvta_generic_to_shared(sm);
    const int tid  = threadIdx.x;
    const int lane = tid & 31;
    const int warp = tid >> 5;
    const int wm = (warp >> 2) * 64;
    const int wn = (warp & 3) * 32;
    const int bm = blockIdx.y * 128;
    const int bn = blockIdx.x * 128;
    const int g4 = lane >> 2;
    const int tg = lane & 3;

    float acc[4][4][4];
#pragma unroll
    for (int t = 0; t < 4; ++t)
#pragma unroll
        for (int u = 0; u < 4; ++u)
#pragma unroll
            for (int r = 0; r < 4; ++r) acc[t][u][r] = 0.0f;

    auto load_chunk = [&](int kc, int bf) {
#pragma unroll
        for (int it = 0; it < 4; ++it) {
            int idx = tid + it * 256;
            int row = idx >> 3;
            int c8  = idx & 7;
            const __half* sa = A2 + (size_t)(bm + row) * K2 + kc * 64 + c8 * 8;
            const __half* sb = B2 + (size_t)(bn + row) * K2 + kc * 64 + c8 * 8;
            unsigned sw = (unsigned)((c8 ^ (row & 7)) * 16);
            unsigned da = smem_base + bf * 16384 + row * 128 + sw;
            unsigned db = smem_base + 49152 + bf * 16384 + row * 128 + sw;
            CP16(da, sa);
            CP16(db, sb);
        }
    };

    const int khalf = lane >> 4;                 // 0/1 -> k 0-7 / 8-15
    int rowA[4], rowB[2];
#pragma unroll
    for (int t = 0; t < 4; ++t) rowA[t] = wm + t * 16 + (lane & 15);
#pragma unroll
    for (int p = 0; p < 2; ++p) rowB[p] = wn + p * 16 + (lane & 15);

    load_chunk(0, 0); CPCOMMIT();
    load_chunk(1, 1); CPCOMMIT();

    const int NC = K2 / 64;   // 32
    for (int kc = 0; kc < NC; ++kc) {
        CPWAIT1();
        __syncthreads();
        if (kc + 2 < NC) { load_chunk(kc + 2, (kc + 2) % 3); CPCOMMIT(); }

        const int bf = kc % 3;
        const unsigned abase = smem_base + bf * 16384;
        const unsigned bbase = smem_base + 49152 + bf * 16384;

#pragma unroll
        for (int s = 0; s < 4; ++s) {
            const int ch = s * 2 + khalf;        // 16B-chunk id within row
            unsigned a[4][4], b[2][4];
#pragma unroll
            for (int t = 0; t < 4; ++t) {
                unsigned addr = abase + rowA[t] * 128 +
                                (unsigned)((ch ^ (rowA[t] & 7)) * 16);
                ldsm4(a[t], addr);
            }
#pragma unroll
            for (int p = 0; p < 2; ++p) {
                unsigned addr = bbase + rowB[p] * 128 +
                                (unsigned)((ch ^ (rowB[p] & 7)) * 16);
                ldsm4(b[p], addr);
            }
#pragma unroll
            for (int t = 0; t < 4; ++t)
#pragma unroll
                for (int u = 0; u < 4; ++u) {
                    int p = u >> 1, h = u & 1;
                    mma16816(acc[t][u], a[t], b[p][h], b[p][2 + h]);
                }
        }
    }

#pragma unroll
    for (int t = 0; t < 4; ++t) {
        int r = bm + wm + t * 16 + g4;
#pragma unroll
        for (int u = 0; u < 4; ++u) {
            int c = bn + wn + u * 8 + tg * 2;
            float b0 = 0.0f, b1 = 0.0f;
            if (bias) { b0 = bias[c]; b1 = bias[c + 1]; }
            *(float2*)&C[(size_t)r * N + c] =
                make_float2(acc[t][u][0] + b0, acc[t][u][1] + b1);
            *(float2*)&C[(size_t)(r + 8) * N + c] =
                make_float2(acc[t][u][2] + b0, acc[t][u][3] + b1);
        }
    }
}

// ---------------- per-(b,h) Gram partials via fp16 mma ------------------------
// C[d][j] = sum_n K[n][d] * T[j][n], j<64: T=K (KK), j>=64: T=V (KV).
// Smem tile T[128][72]: rows 0-63 = K^T (d-major), 64-127 = V^T (e-major),
// cols = 64 n values. 8 warps: 2(m) x 4(n), warp tile 32x32.
__global__ __launch_bounds__(256) void kkt_kernel()
{
    int bh = blockIdx.x;
    int split = blockIdx.y;
    int b = bh >> 4, h = bh & 15;
    const float* kb = g_k + (size_t)b * SEQ * DIM + h * HD;
    const float* vb = g_v + (size_t)b * SEQ * DIM + h * HD;

    __shared__ __half T[128][72];
    const unsigned tb = (unsigned)__cvta_generic_to_shared(&T[0][0]);
    const int tid = threadIdx.x;
    const int lane = tid & 31;
    const int warp = tid >> 5;
    const int wm = (warp >> 2) * 32;   // A rows (d): 0 or 32
    const int wn = (warp & 3) * 32;    // B rows (j): 0,32,64,96
    const int g4 = lane >> 2;
    const int tg = lane & 3;

    float acc[2][4][4];
#pragma unroll
    for (int mt = 0; mt < 2; ++mt)
#pragma unroll
        for (int u = 0; u < 4; ++u)
#pragma unroll
            for (int r = 0; r < 4; ++r) acc[mt][u][r] = 0.0f;

    const int khalf = lane >> 4;
    int rowA[2], rowB[2];
#pragma unroll
    for (int mt = 0; mt < 2; ++mt) rowA[mt] = wm + mt * 16 + (lane & 15);
#pragma unroll
    for (int p = 0; p < 2; ++p) rowB[p] = wn + p * 16 + (lane & 15);

    int nbase0 = split * (SEQ / NSPLIT);
    for (int t0 = 0; t0 < SEQ / NSPLIT; t0 += 64) {
        __syncthreads();
        // load 64 n-rows of K and V, store transposed as fp16
#pragma unroll
        for (int it = 0; it < 8; ++it) {
            int idx = tid + it * 256;
            int tensor = idx >> 10;
            int rem = idx & 1023;
            int n = rem & 63;
            int c4 = (rem >> 6) * 4;
            const float* src = (tensor ? vb : kb) +
                               (size_t)(nbase0 + t0 + n) * DIM + c4;
            float4 v4 = *(const float4*)src;
            T[tensor * 64 + c4 + 0][n] = __float2half_rn(v4.x);
            T[tensor * 64 + c4 + 1][n] = __float2half_rn(v4.y);
            T[tensor * 64 + c4 + 2][n] = __float2half_rn(v4.z);
            T[tensor * 64 + c4 + 3][n] = __float2half_rn(v4.w);
        }
        __syncthreads();

#pragma unroll
        for (int ks = 0; ks < 4; ++ks) {
            unsigned a[2][4], bfr[2][4];
            unsigned colb = (unsigned)(ks * 32 + khalf * 16);   // bytes within row
#pragma unroll
            for (int mt = 0; mt < 2; ++mt)
                ldsm4(a[mt], tb + rowA[mt] * 144 + colb);
#pragma unroll
            for (int p = 0; p < 2; ++p)
                ldsm4(bfr[p], tb + rowB[p] * 144 + colb);
#pragma unroll
            for (int mt = 0; mt < 2; ++mt)
#pragma unroll
                for (int u = 0; u < 4; ++u) {
                    int p = u >> 1, hh = u & 1;
                    mma16816(acc[mt][u], a[mt], bfr[p][hh], bfr[p][2 + hh]);
                }
        }
    }

    float* pkk = g_part + (size_t)(split * BH + bh) * 2 * 4096;
    float* pkv = pkk + 4096;
#pragma unroll
    for (int mt = 0; mt < 2; ++mt) {
        int d = wm + mt * 16 + g4;
#pragma unroll
        for (int u = 0; u < 4; ++u) {
            int j = wn + u * 8 + tg * 2;
            float* dst = (j < 64) ? (pkk + d * 64 + j) : (pkv + d * 64 + (j - 64));
            *(float2*)dst = make_float2(acc[mt][u][0], acc[mt][u][1]);
            float* dst2 = (j < 64) ? (pkk + (d + 8) * 64 + j)
                                   : (pkv + (d + 8) * 64 + (j - 64));
            *(float2*)dst2 = make_float2(acc[mt][u][2], acc[mt][u][3]);
        }
    }
}

// ------- reduce partials, solve (kk+aI) X = ktv, column softmax -> g_amap ----
__global__ __launch_bounds__(256) void solve_kernel(
    const float* __restrict__ alpha_p, const float* __restrict__ temp_p)
{
    int bh = blockIdx.x;
    __shared__ float A[64][65];
    __shared__ float X[64][65];
    int tid = threadIdx.x;

    for (int i = tid; i < 4096; i += 256) {
        float skk = 0.0f, skv = 0.0f;
#pragma unroll
        for (int s = 0; s < NSPLIT; ++s) {
            const float* p = g_part + ((size_t)(s * BH + bh) * 2) * 4096;
            skk += p[i];
            skv += p[4096 + i];
        }
        A[i >> 6][i & 63] = skk;
        X[i >> 6][i & 63] = skv;
    }
    __syncthreads();
    if (tid < 64) A[tid][tid] += alpha_p[0];

    int r  = tid >> 2;
    int c0 = (tid & 3) * 16;
    for (int p = 0; p < 64; ++p) {
        __syncthreads();
        float pinv = 1.0f / A[p][p];
        __syncthreads();
        if (tid < 64)      A[p][tid]      *= pinv;
        else if (tid < 128) X[p][tid - 64] *= pinv;
        __syncthreads();
        float f = (r != p) ? A[r][p] : 0.0f;
        __syncthreads();
        if (r != p) {
#pragma unroll
            for (int c = 0; c < 16; ++c) {
                A[r][c0 + c] = fmaf(-f, A[p][c0 + c], A[r][c0 + c]);
                X[r][c0 + c] = fmaf(-f, X[p][c0 + c], X[r][c0 + c]);
            }
        }
    }
    __syncthreads();

    if (tid < 64) {
        float invt = 1.0f / temp_p[0];
        float mx = -1e30f;
        for (int d = 0; d < 64; ++d) mx = fmaxf(mx, X[d][tid] * invt);
        float s = 0.0f;
        for (int d = 0; d < 64; ++d) s += expf(X[d][tid] * invt - mx);
        float inv_s = 1.0f / s;
        for (int d = 0; d < 64; ++d)
            g_amap[(size_t)bh * 4096 + d * 64 + tid] =
                expf(X[d][tid] * invt - mx) * inv_s;
    }
}

// ---------------- out = Q @ attn_map per (b,h) -------------------------------
__global__ __launch_bounds__(256) void qmap_kernel()
{
    int mt = blockIdx.x;
    int bh = blockIdx.y;
    int b = bh >> 4, h = bh & 15;
    __shared__ float Qs[64][68];
    __shared__ float Am[64][68];
    int tid = threadIdx.x;

    for (int i = tid * 4; i < 4096; i += 1024) {
        float4 v = *(const float4*)&g_amap[(size_t)bh * 4096 + i];
        *(float4*)&Am[i >> 6][i & 63] = v;
    }
    const float* qb = g_q + ((size_t)b * SEQ + mt * 64) * DIM + h * HD;
#pragma unroll
    for (int it = 0; it < 4; ++it) {
        int f = tid + it * 256;
        int row = f >> 4, c4 = (f & 15) * 4;
        float4 v = *(const float4*)(qb + (size_t)row * DIM + c4);
        *(float4*)&Qs[row][c4] = v;
    }
    __syncthreads();

    int m0 = (tid >> 4) * 4;
    int e0 = (tid & 15) * 4;
    float acc[4][4];
#pragma unroll
    for (int i = 0; i < 4; ++i)
#pragma unroll
        for (int j = 0; j < 4; ++j) acc[i][j] = 0.0f;

#pragma unroll 8
    for (int d = 0; d < 64; ++d) {
        float a0 = Qs[m0 + 0][d];
        float a1 = Qs[m0 + 1][d];
        float a2 = Qs[m0 + 2][d];
        float a3 = Qs[m0 + 3][d];
        float4 bb = *(const float4*)&Am[d][e0];
        float bv[4] = { bb.x, bb.y, bb.z, bb.w };
#pragma unroll
        for (int j = 0; j < 4; ++j) {
            acc[0][j] = fmaf(a0, bv[j], acc[0][j]);
            acc[1][j] = fmaf(a1, bv[j], acc[1][j]);
            acc[2][j] = fmaf(a2, bv[j], acc[2][j]);
            acc[3][j] = fmaf(a3, bv[j], acc[3][j]);
        }
    }

    float* ob = g_ao + ((size_t)b * SEQ + mt * 64) * DIM + h * HD;
#pragma unroll
    for (int i = 0; i < 4; ++i)
        *(float4*)&ob[(size_t)(m0 + i) * DIM + e0] =
            make_float4(acc[i][0], acc[i][1], acc[i][2], acc[i][3]);
}

// ---------------- LayerNorm(proj + x) ----------------------------------------
__global__ __launch_bounds__(256) void ln_kernel(
    const float* __restrict__ x, const float* __restrict__ gamma,
    const float* __restrict__ beta, float* __restrict__ out)
{
    int row = blockIdx.x;
    int tid = threadIdx.x;
    const float* pr = g_proj + (size_t)row * DIM;
    const float* xr = x      + (size_t)row * DIM;

    float4 pv = *(const float4*)(pr + tid * 4);
    float4 xv = *(const float4*)(xr + tid * 4);
    float v[4] = { pv.x + xv.x, pv.y + xv.y, pv.z + xv.z, pv.w + xv.w };

    float s = v[0] + v[1] + v[2] + v[3];
    float s2 = v[0]*v[0] + v[1]*v[1] + v[2]*v[2] + v[3]*v[3];

#pragma unroll
    for (int o = 16; o > 0; o >>= 1) {
        s  += __shfl_xor_sync(0xFFFFFFFFu, s,  o);
        s2 += __shfl_xor_sync(0xFFFFFFFFu, s2, o);
    }
    __shared__ float rs[8], rs2[8];
    int wid = tid >> 5, lane = tid & 31;
    if (lane == 0) { rs[wid] = s; rs2[wid] = s2; }
    __syncthreads();
    if (wid == 0) {
        float a  = (lane < 8) ? rs[lane]  : 0.0f;
        float a2 = (lane < 8) ? rs2[lane] : 0.0f;
#pragma unroll
        for (int o = 4; o > 0; o >>= 1) {
            a  += __shfl_xor_sync(0xFFFFFFFFu, a,  o);
            a2 += __shfl_xor_sync(0xFFFFFFFFu, a2, o);
        }
        if (lane == 0) { rs[0] = a; rs2[0] = a2; }
    }
    __syncthreads();
    float mu  = rs[0]  * (1.0f / DIM);
    float var = rs2[0] * (1.0f / DIM) - mu * mu;
    float rstd = rsqrtf(var + LNEPS);

    const float* gp = gamma + tid * 4;
    const float* bp = beta  + tid * 4;
    float4 o4;
    o4.x = (v[0] - mu) * rstd * gp[0] + bp[0];
    o4.y = (v[1] - mu) * rstd * gp[1] + bp[1];
    o4.z = (v[2] - mu) * rstd * gp[2] + bp[2];
    o4.w = (v[3] - mu) * rstd * gp[3] + bp[3];
    *(float4*)(out + (size_t)row * DIM + tid * 4) = o4;
}

// ---------------- host launcher ----------------------------------------------
extern "C" void kernel_launch(void* const* d_in, const int* in_sizes, int n_in,
                              void* d_out, int out_size)
{
    (void)in_sizes; (void)n_in; (void)out_size;
    const float* x     = (const float*)d_in[0];
    const float* Wq    = (const float*)d_in[1];
    const float* Wk    = (const float*)d_in[2];
    const float* Wv    = (const float*)d_in[3];
    const float* Wo    = (const float*)d_in[4];
    const float* bo    = (const float*)d_in[5];
    const float* alpha = (const float*)d_in[6];
    const float* temp  = (const float*)d_in[7];
    const float* gamma = (const float*)d_in[8];
    const float* beta  = (const float*)d_in[9];
    float* out = (float*)d_out;

    float *qp, *kp, *vp, *aop, *projp;
    __half *a2p, *w2p;
    cudaGetSymbolAddress((void**)&qp,    g_q);
    cudaGetSymbolAddress((void**)&kp,    g_k);
    cudaGetSymbolAddress((void**)&vp,    g_v);
    cudaGetSymbolAddress((void**)&aop,   g_ao);
    cudaGetSymbolAddress((void**)&projp, g_proj);
    cudaGetSymbolAddress((void**)&a2p,   g_a2);
    cudaGetSymbolAddress((void**)&w2p,   g_w2);

    const int SMEM_GEMM = 98304;  // 3-stage * (16KB A + 16KB B)
    cudaFuncSetAttribute(gemm_f16,
                         cudaFuncAttributeMaxDynamicSharedMemorySize, SMEM_GEMM);

    // convert inputs to interleaved fp16 hi/lo
    conv2_kernel<<<MTOT*DIM/2048, 256>>>(x,  a2p, 0);
    conv2_kernel<<<DIM*DIM/2048, 256>>>(Wq, w2p + 0*(size_t)DIM*K2, 1);
    conv2_kernel<<<DIM*DIM/2048, 256>>>(Wk, w2p + 1*(size_t)DIM*K2, 1);
    conv2_kernel<<<DIM*DIM/2048, 256>>>(Wv, w2p + 2*(size_t)DIM*K2, 1);

    dim3 gg(DIM / 128, MTOT / 128);
    gemm_f16<<<gg, 256, SMEM_GEMM>>>(a2p, w2p + 0*(size_t)DIM*K2, nullptr, qp, MTOT, DIM);
    gemm_f16<<<gg, 256, SMEM_GEMM>>>(a2p, w2p + 1*(size_t)DIM*K2, nullptr, kp, MTOT, DIM);
    gemm_f16<<<gg, 256, SMEM_GEMM>>>(a2p, w2p + 2*(size_t)DIM*K2, nullptr, vp, MTOT, DIM);

    kkt_kernel<<<dim3(BH, NSPLIT), 256>>>();
    solve_kernel<<<BH, 256>>>(alpha, temp);
    qmap_kernel<<<dim3(SEQ / 64, BH), 256>>>();

    conv2_kernel<<<MTOT*DIM/2048, 256>>>(aop, a2p, 0);
    conv2_kernel<<<DIM*DIM/2048, 256>>>(Wo, w2p + 0*(size_t)DIM*K2, 1);
    gemm_f16<<<gg, 256, SMEM_GEMM>>>(a2p, w2p + 0*(size_t)DIM*K2, bo, projp, MTOT, DIM);

    ln_kernel<<<MTOT, 256>>>(x, gamma, beta, out);
}

// round 7
// speedup vs baseline: 6.8651x; 1.5599x over previous
#include <cuda_runtime.h>
#include <cuda_fp16.h>
#include <cstdint>
#include <math.h>

#define BATCH 4
#define SEQ   4096
#define DIM   1024
#define NH    16
#define HD    64
#define BH    (BATCH*NH)          // 64
#define MTOT  (BATCH*SEQ)         // 16384
#define NSPLIT 8
#define LNEPS 1e-5f

// ---------------- scratch (static device globals; no allocation) -------------
__device__ __align__(16) __half g_xh [(size_t)MTOT*DIM];
__device__ __align__(16) __half g_wh [4][(size_t)DIM*DIM];
__device__ __align__(16) __half g_qh [(size_t)MTOT*DIM];
__device__ __align__(16) __half g_kh [(size_t)MTOT*DIM];
__device__ __align__(16) __half g_vh [(size_t)MTOT*DIM];
__device__ __align__(16) __half g_aoh[(size_t)MTOT*DIM];
__device__ float g_proj[MTOT*DIM];
__device__ float g_part[NSPLIT*BH*2*HD*HD];
__device__ float g_amap[BH*HD*HD];

// ---------------- async copy / mma helpers ------------------------------------
#define CP16(dst_u32, src_ptr) \
    asm volatile("cp.async.cg.shared.global [%0], [%1], 16;\n" \
                 :: "r"(dst_u32), "l"(src_ptr))
#define CPCOMMIT() asm volatile("cp.async.commit_group;\n" ::: "memory")
#define CPWAIT1()  asm volatile("cp.async.wait_group 1;\n" ::: "memory")

__device__ __forceinline__ void ldsm4(unsigned r[4], unsigned addr) {
    asm volatile("ldmatrix.sync.aligned.m8n8.x4.shared.b16 {%0,%1,%2,%3}, [%4];"
                 : "=r"(r[0]), "=r"(r[1]), "=r"(r[2]), "=r"(r[3]) : "r"(addr));
}

__device__ __forceinline__ void mma16816(float* c, const unsigned a[4],
                                         unsigned b0, unsigned b1) {
    asm volatile(
        "mma.sync.aligned.m16n8k16.row.col.f32.f16.f16.f32 "
        "{%0,%1,%2,%3}, {%4,%5,%6,%7}, {%8,%9}, {%0,%1,%2,%3};"
        : "+f"(c[0]), "+f"(c[1]), "+f"(c[2]), "+f"(c[3])
        : "r"(a[0]), "r"(a[1]), "r"(a[2]), "r"(a[3]), "r"(b0), "r"(b1));
}

// ---------------- f32 -> fp16 (plain) -----------------------------------------
__global__ __launch_bounds__(256) void convh_kernel(
    const float* __restrict__ src, __half* __restrict__ dst)
{
    size_t base = (size_t)(blockIdx.x * blockDim.x + threadIdx.x) * 8;
    float4 v0 = *(const float4*)(src + base);
    float4 v1 = *(const float4*)(src + base + 4);
    __half o[8];
    o[0] = __float2half_rn(v0.x); o[1] = __float2half_rn(v0.y);
    o[2] = __float2half_rn(v0.z); o[3] = __float2half_rn(v0.w);
    o[4] = __float2half_rn(v1.x); o[5] = __float2half_rn(v1.y);
    o[6] = __float2half_rn(v1.z); o[7] = __float2half_rn(v1.w);
    *(uint4*)(dst + base) = *(const uint4*)o;
}

// ---------------- fp16 GEMM: C[m,n]=sum_k A[m,k]*B[n,k] ----------------------
// K = DIM = 1024. 128x128 tile, BK=64, 256 thr = 8 warps (2x4), warp 64x32.
// 3-stage cp.async, XOR-swizzled smem, ldmatrix. Output: fp16 (Ch) or f32+bias.
__global__ __launch_bounds__(256) void gemm_f16(
    const __half* __restrict__ A2, const __half* __restrict__ B2,
    const float* __restrict__ bias, float* __restrict__ Cf,
    __half* __restrict__ Ch, int M, int N)
{
    extern __shared__ __half sm[];
    const unsigned smem_base = (unsigned)__cvta_generic_to_shared(sm);
    const int tid  = threadIdx.x;
    const int lane = tid & 31;
    const int warp = tid >> 5;
    const int wm = (warp >> 2) * 64;
    const int wn = (warp & 3) * 32;
    const int bm = blockIdx.y * 128;
    const int bn = blockIdx.x * 128;
    const int g4 = lane >> 2;
    const int tg = lane & 3;

    float acc[4][4][4];
#pragma unroll
    for (int t = 0; t < 4; ++t)
#pragma unroll
        for (int u = 0; u < 4; ++u)
#pragma unroll
            for (int r = 0; r < 4; ++r) acc[t][u][r] = 0.0f;

    auto load_chunk = [&](int kc, int bf) {
#pragma unroll
        for (int it = 0; it < 4; ++it) {
            int idx = tid + it * 256;
            int row = idx >> 3;
            int c8  = idx & 7;
            const __half* sa = A2 + (size_t)(bm + row) * DIM + kc * 64 + c8 * 8;
            const __half* sb = B2 + (size_t)(bn + row) * DIM + kc * 64 + c8 * 8;
            unsigned sw = (unsigned)((c8 ^ (row & 7)) * 16);
            unsigned da = smem_base + bf * 16384 + row * 128 + sw;
            unsigned db = smem_base + 49152 + bf * 16384 + row * 128 + sw;
            CP16(da, sa);
            CP16(db, sb);
        }
    };

    const int khalf = lane >> 4;
    int rowA[4], rowB[2];
#pragma unroll
    for (int t = 0; t < 4; ++t) rowA[t] = wm + t * 16 + (lane & 15);
#pragma unroll
    for (int p = 0; p < 2; ++p) rowB[p] = wn + p * 16 + (lane & 15);

    load_chunk(0, 0); CPCOMMIT();
    load_chunk(1, 1); CPCOMMIT();

    const int NC = DIM / 64;   // 16
    for (int kc = 0; kc < NC; ++kc) {
        CPWAIT1();
        __syncthreads();
        if (kc + 2 < NC) { load_chunk(kc + 2, (kc + 2) % 3); CPCOMMIT(); }

        const int bf = kc % 3;
        const unsigned abase = smem_base + bf * 16384;
        const unsigned bbase = smem_base + 49152 + bf * 16384;

#pragma unroll
        for (int s = 0; s < 4; ++s) {
            const int ch = s * 2 + khalf;
            unsigned a[4][4], b[2][4];
#pragma unroll
            for (int t = 0; t < 4; ++t) {
                unsigned addr = abase + rowA[t] * 128 +
                                (unsigned)((ch ^ (rowA[t] & 7)) * 16);
                ldsm4(a[t], addr);
            }
#pragma unroll
            for (int p = 0; p < 2; ++p) {
                unsigned addr = bbase + rowB[p] * 128 +
                                (unsigned)((ch ^ (rowB[p] & 7)) * 16);
                ldsm4(b[p], addr);
            }
#pragma unroll
            for (int t = 0; t < 4; ++t)
#pragma unroll
                for (int u = 0; u < 4; ++u) {
                    int p = u >> 1, h = u & 1;
                    mma16816(acc[t][u], a[t], b[p][h], b[p][2 + h]);
                }
        }
    }

#pragma unroll
    for (int t = 0; t < 4; ++t) {
        int r = bm + wm + t * 16 + g4;
#pragma unroll
        for (int u = 0; u < 4; ++u) {
            int c = bn + wn + u * 8 + tg * 2;
            if (Ch) {
                *(__half2*)&Ch[(size_t)r * N + c] =
                    __floats2half2_rn(acc[t][u][0], acc[t][u][1]);
                *(__half2*)&Ch[(size_t)(r + 8) * N + c] =
                    __floats2half2_rn(acc[t][u][2], acc[t][u][3]);
            } else {
                float b0 = 0.0f, b1 = 0.0f;
                if (bias) { b0 = bias[c]; b1 = bias[c + 1]; }
                *(float2*)&Cf[(size_t)r * N + c] =
                    make_float2(acc[t][u][0] + b0, acc[t][u][1] + b1);
                *(float2*)&Cf[(size_t)(r + 8) * N + c] =
                    make_float2(acc[t][u][2] + b0, acc[t][u][3] + b1);
            }
        }
    }
}

// ---------------- per-(b,h) Gram partials via fp16 mma ------------------------
// C[d][j] = sum_n K[n][d] * T[j][n], j<64: KK, j>=64: KV.
__global__ __launch_bounds__(256) void kkt_kernel()
{
    int bh = blockIdx.x;
    int split = blockIdx.y;
    int b = bh >> 4, h = bh & 15;
    const __half* kb = g_kh + (size_t)b * SEQ * DIM + h * HD;
    const __half* vb = g_vh + (size_t)b * SEQ * DIM + h * HD;

    __shared__ __half T[128][72];
    const unsigned tb = (unsigned)__cvta_generic_to_shared(&T[0][0]);
    const int tid = threadIdx.x;
    const int lane = tid & 31;
    const int warp = tid >> 5;
    const int wm = (warp >> 2) * 32;
    const int wn = (warp & 3) * 32;
    const int g4 = lane >> 2;
    const int tg = lane & 3;

    float acc[2][4][4];
#pragma unroll
    for (int mt = 0; mt < 2; ++mt)
#pragma unroll
        for (int u = 0; u < 4; ++u)
#pragma unroll
            for (int r = 0; r < 4; ++r) acc[mt][u][r] = 0.0f;

    const int khalf = lane >> 4;
    int rowA[2], rowB[2];
#pragma unroll
    for (int mt = 0; mt < 2; ++mt) rowA[mt] = wm + mt * 16 + (lane & 15);
#pragma unroll
    for (int p = 0; p < 2; ++p) rowB[p] = wn + p * 16 + (lane & 15);

    int nbase0 = split * (SEQ / NSPLIT);
    for (int t0 = 0; t0 < SEQ / NSPLIT; t0 += 64) {
        __syncthreads();
#pragma unroll
        for (int it = 0; it < 8; ++it) {
            int idx = tid + it * 256;
            int tensor = idx >> 10;
            int rem = idx & 1023;
            int n = rem & 63;
            int c4 = (rem >> 6) * 4;
            const __half* src = (tensor ? vb : kb) +
                                (size_t)(nbase0 + t0 + n) * DIM + c4;
            uint2 u2 = *(const uint2*)src;
            __half2 p0 = *reinterpret_cast<__half2*>(&u2.x);
            __half2 p1 = *reinterpret_cast<__half2*>(&u2.y);
            T[tensor * 64 + c4 + 0][n] = __low2half(p0);
            T[tensor * 64 + c4 + 1][n] = __high2half(p0);
            T[tensor * 64 + c4 + 2][n] = __low2half(p1);
            T[tensor * 64 + c4 + 3][n] = __high2half(p1);
        }
        __syncthreads();

#pragma unroll
        for (int ks = 0; ks < 4; ++ks) {
            unsigned a[2][4], bfr[2][4];
            unsigned colb = (unsigned)(ks * 32 + khalf * 16);
#pragma unroll
            for (int mt = 0; mt < 2; ++mt)
                ldsm4(a[mt], tb + rowA[mt] * 144 + colb);
#pragma unroll
            for (int p = 0; p < 2; ++p)
                ldsm4(bfr[p], tb + rowB[p] * 144 + colb);
#pragma unroll
            for (int mt = 0; mt < 2; ++mt)
#pragma unroll
                for (int u = 0; u < 4; ++u) {
                    int p = u >> 1, hh = u & 1;
                    mma16816(acc[mt][u], a[mt], bfr[p][hh], bfr[p][2 + hh]);
                }
        }
    }

    float* pkk = g_part + (size_t)(split * BH + bh) * 2 * 4096;
    float* pkv = pkk + 4096;
#pragma unroll
    for (int mt = 0; mt < 2; ++mt) {
        int d = wm + mt * 16 + g4;
#pragma unroll
        for (int u = 0; u < 4; ++u) {
            int j = wn + u * 8 + tg * 2;
            float* dst = (j < 64) ? (pkk + d * 64 + j) : (pkv + d * 64 + (j - 64));
            *(float2*)dst = make_float2(acc[mt][u][0], acc[mt][u][1]);
            float* dst2 = (j < 64) ? (pkk + (d + 8) * 64 + j)
                                   : (pkv + (d + 8) * 64 + (j - 64));
            *(float2*)dst2 = make_float2(acc[mt][u][2], acc[mt][u][3]);
        }
    }
}

// ------- reduce partials, solve (kk+aI) X = ktv, column softmax -> g_amap ----
__global__ __launch_bounds__(256) void solve_kernel(
    const float* __restrict__ alpha_p, const float* __restrict__ temp_p)
{
    int bh = blockIdx.x;
    __shared__ float A[64][65];
    __shared__ float X[64][65];
    int tid = threadIdx.x;

    for (int i = tid; i < 4096; i += 256) {
        float skk = 0.0f, skv = 0.0f;
#pragma unroll
        for (int s = 0; s < NSPLIT; ++s) {
            const float* p = g_part + ((size_t)(s * BH + bh) * 2) * 4096;
            skk += p[i];
            skv += p[4096 + i];
        }
        A[i >> 6][i & 63] = skk;
        X[i >> 6][i & 63] = skv;
    }
    __syncthreads();
    if (tid < 64) A[tid][tid] += alpha_p[0];

    int r  = tid >> 2;
    int c0 = (tid & 3) * 16;
    for (int p = 0; p < 64; ++p) {
        __syncthreads();
        float pinv = 1.0f / A[p][p];
        __syncthreads();
        if (tid < 64)      A[p][tid]      *= pinv;
        else if (tid < 128) X[p][tid - 64] *= pinv;
        __syncthreads();
        float f = (r != p) ? A[r][p] : 0.0f;
        __syncthreads();
        if (r != p) {
#pragma unroll
            for (int c = 0; c < 16; ++c) {
                A[r][c0 + c] = fmaf(-f, A[p][c0 + c], A[r][c0 + c]);
                X[r][c0 + c] = fmaf(-f, X[p][c0 + c], X[r][c0 + c]);
            }
        }
    }
    __syncthreads();

    if (tid < 64) {
        float invt = 1.0f / temp_p[0];
        float mx = -1e30f;
        for (int d = 0; d < 64; ++d) mx = fmaxf(mx, X[d][tid] * invt);
        float s = 0.0f;
        for (int d = 0; d < 64; ++d) s += expf(X[d][tid] * invt - mx);
        float inv_s = 1.0f / s;
        for (int d = 0; d < 64; ++d)
            g_amap[(size_t)bh * 4096 + d * 64 + tid] =
                expf(X[d][tid] * invt - mx) * inv_s;
    }
}

// ---------------- ao = Q @ attn_map per (b,h), fp16 in / fp16 out -------------
__global__ __launch_bounds__(256) void qmap_kernel()
{
    int mt = blockIdx.x;
    int bh = blockIdx.y;
    int b = bh >> 4, h = bh & 15;
    __shared__ float Qs[64][68];
    __shared__ float Am[64][68];
    int tid = threadIdx.x;

    for (int i = tid * 4; i < 4096; i += 1024) {
        float4 v = *(const float4*)&g_amap[(size_t)bh * 4096 + i];
        *(float4*)&Am[i >> 6][i & 63] = v;
    }
    const __half* qb = g_qh + ((size_t)b * SEQ + mt * 64) * DIM + h * HD;
#pragma unroll
    for (int it = 0; it < 4; ++it) {
        int f = tid + it * 256;
        int row = f >> 4, c4 = (f & 15) * 4;
        uint2 u2 = *(const uint2*)(qb + (size_t)row * DIM + c4);
        __half2 p0 = *reinterpret_cast<__half2*>(&u2.x);
        __half2 p1 = *reinterpret_cast<__half2*>(&u2.y);
        Qs[row][c4 + 0] = __low2float(p0);
        Qs[row][c4 + 1] = __high2float(p0);
        Qs[row][c4 + 2] = __low2float(p1);
        Qs[row][c4 + 3] = __high2float(p1);
    }
    __syncthreads();

    int m0 = (tid >> 4) * 4;
    int e0 = (tid & 15) * 4;
    float acc[4][4];
#pragma unroll
    for (int i = 0; i < 4; ++i)
#pragma unroll
        for (int j = 0; j < 4; ++j) acc[i][j] = 0.0f;

#pragma unroll 8
    for (int d = 0; d < 64; ++d) {
        float a0 = Qs[m0 + 0][d];
        float a1 = Qs[m0 + 1][d];
        float a2 = Qs[m0 + 2][d];
        float a3 = Qs[m0 + 3][d];
        float4 bb = *(const float4*)&Am[d][e0];
        float bv[4] = { bb.x, bb.y, bb.z, bb.w };
#pragma unroll
        for (int j = 0; j < 4; ++j) {
            acc[0][j] = fmaf(a0, bv[j], acc[0][j]);
            acc[1][j] = fmaf(a1, bv[j], acc[1][j]);
            acc[2][j] = fmaf(a2, bv[j], acc[2][j]);
            acc[3][j] = fmaf(a3, bv[j], acc[3][j]);
        }
    }

    __half* ob = g_aoh + ((size_t)b * SEQ + mt * 64) * DIM + h * HD;
#pragma unroll
    for (int i = 0; i < 4; ++i) {
        __half2 h01 = __floats2half2_rn(acc[i][0], acc[i][1]);
        __half2 h23 = __floats2half2_rn(acc[i][2], acc[i][3]);
        __half hv[4];
        *(__half2*)&hv[0] = h01;
        *(__half2*)&hv[2] = h23;
        *(uint2*)&ob[(size_t)(m0 + i) * DIM + e0] = *(const uint2*)hv;
    }
}

// ---------------- LayerNorm(proj + x) ----------------------------------------
__global__ __launch_bounds__(256) void ln_kernel(
    const float* __restrict__ x, const float* __restrict__ gamma,
    const float* __restrict__ beta, float* __restrict__ out)
{
    int row = blockIdx.x;
    int tid = threadIdx.x;
    const float* pr = g_proj + (size_t)row * DIM;
    const float* xr = x      + (size_t)row * DIM;

    float4 pv = *(const float4*)(pr + tid * 4);
    float4 xv = *(const float4*)(xr + tid * 4);
    float v[4] = { pv.x + xv.x, pv.y + xv.y, pv.z + xv.z, pv.w + xv.w };

    float s = v[0] + v[1] + v[2] + v[3];
    float s2 = v[0]*v[0] + v[1]*v[1] + v[2]*v[2] + v[3]*v[3];

#pragma unroll
    for (int o = 16; o > 0; o >>= 1) {
        s  += __shfl_xor_sync(0xFFFFFFFFu, s,  o);
        s2 += __shfl_xor_sync(0xFFFFFFFFu, s2, o);
    }
    __shared__ float rs[8], rs2[8];
    int wid = tid >> 5, lane = tid & 31;
    if (lane == 0) { rs[wid] = s; rs2[wid] = s2; }
    __syncthreads();
    if (wid == 0) {
        float a  = (lane < 8) ? rs[lane]  : 0.0f;
        float a2 = (lane < 8) ? rs2[lane] : 0.0f;
#pragma unroll
        for (int o = 4; o > 0; o >>= 1) {
            a  += __shfl_xor_sync(0xFFFFFFFFu, a,  o);
            a2 += __shfl_xor_sync(0xFFFFFFFFu, a2, o);
        }
        if (lane == 0) { rs[0] = a; rs2[0] = a2; }
    }
    __syncthreads();
    float mu  = rs[0]  * (1.0f / DIM);
    float var = rs2[0] * (1.0f / DIM) - mu * mu;
    float rstd = rsqrtf(var + LNEPS);

    const float* gp = gamma + tid * 4;
    const float* bp = beta  + tid * 4;
    float4 o4;
    o4.x = (v[0] - mu) * rstd * gp[0] + bp[0];
    o4.y = (v[1] - mu) * rstd * gp[1] + bp[1];
    o4.z = (v[2] - mu) * rstd * gp[2] + bp[2];
    o4.w = (v[3] - mu) * rstd * gp[3] + bp[3];
    *(float4*)(out + (size_t)row * DIM + tid * 4) = o4;
}

// ---------------- host launcher ----------------------------------------------
extern "C" void kernel_launch(void* const* d_in, const int* in_sizes, int n_in,
                              void* d_out, int out_size)
{
    (void)in_sizes; (void)n_in; (void)out_size;
    const float* x     = (const float*)d_in[0];
    const float* Wq    = (const float*)d_in[1];
    const float* Wk    = (const float*)d_in[2];
    const float* Wv    = (const float*)d_in[3];
    const float* Wo    = (const float*)d_in[4];
    const float* bo    = (const float*)d_in[5];
    const float* alpha = (const float*)d_in[6];
    const float* temp  = (const float*)d_in[7];
    const float* gamma = (const float*)d_in[8];
    const float* beta  = (const float*)d_in[9];
    float* out = (float*)d_out;

    __half *xh, *wh, *qh, *kh, *vh, *aoh;
    float *projp;
    cudaGetSymbolAddress((void**)&xh,    g_xh);
    cudaGetSymbolAddress((void**)&wh,    g_wh);
    cudaGetSymbolAddress((void**)&qh,    g_qh);
    cudaGetSymbolAddress((void**)&kh,    g_kh);
    cudaGetSymbolAddress((void**)&vh,    g_vh);
    cudaGetSymbolAddress((void**)&aoh,   g_aoh);
    cudaGetSymbolAddress((void**)&projp, g_proj);

    const int SMEM_GEMM = 98304;  // 3-stage * (16KB A + 16KB B)
    cudaFuncSetAttribute(gemm_f16,
                         cudaFuncAttributeMaxDynamicSharedMemorySize, SMEM_GEMM);

    const size_t WSZ = (size_t)DIM * DIM;
    convh_kernel<<<MTOT*DIM/2048, 256>>>(x,  xh);
    convh_kernel<<<DIM*DIM/2048, 256>>>(Wq, wh + 0*WSZ);
    convh_kernel<<<DIM*DIM/2048, 256>>>(Wk, wh + 1*WSZ);
    convh_kernel<<<DIM*DIM/2048, 256>>>(Wv, wh + 2*WSZ);
    convh_kernel<<<DIM*DIM/2048, 256>>>(Wo, wh + 3*WSZ);

    dim3 gg(DIM / 128, MTOT / 128);
    gemm_f16<<<gg, 256, SMEM_GEMM>>>(xh, wh + 0*WSZ, nullptr, nullptr, qh, MTOT, DIM);
    gemm_f16<<<gg, 256, SMEM_GEMM>>>(xh, wh + 1*WSZ, nullptr, nullptr, kh, MTOT, DIM);
    gemm_f16<<<gg, 256, SMEM_GEMM>>>(xh, wh + 2*WSZ, nullptr, nullptr, vh, MTOT, DIM);

    kkt_kernel<<<dim3(BH, NSPLIT), 256>>>();
    solve_kernel<<<BH, 256>>>(alpha, temp);
    qmap_kernel<<<dim3(SEQ / 64, BH), 256>>>();

    gemm_f16<<<gg, 256, SMEM_GEMM>>>(aoh, wh + 3*WSZ, bo, projp, nullptr, MTOT, DIM);

    ln_kernel<<<MTOT, 256>>>(x, gamma, beta, out);
}

// round 8
// speedup vs baseline: 8.2027x; 1.1948x over previous
#include <cuda_runtime.h>
#include <cuda_fp16.h>
#include <cstdint>
#include <math.h>

#define BATCH 4
#define SEQ   4096
#define DIM   1024
#define NH    16
#define HD    64
#define BH    (BATCH*NH)          // 64
#define MTOT  (BATCH*SEQ)         // 16384
#define NSPLIT 8
#define LNEPS 1e-5f

// ---------------- scratch (static device globals; no allocation) -------------
__device__ __align__(16) __half g_xh [(size_t)MTOT*DIM];
__device__ __align__(16) __half g_wh [4][(size_t)DIM*DIM];
__device__ __align__(16) __half g_kh [(size_t)MTOT*DIM];
__device__ __align__(16) __half g_vh [(size_t)MTOT*DIM];
__device__ __align__(16) __half g_wp [(size_t)BATCH*DIM*DIM];  // folded W' per batch
__device__ __align__(16) __half g_w2 [(size_t)BATCH*DIM*DIM];  // folded W2^T per batch
__device__ float g_proj[MTOT*DIM];
__device__ float g_part[NSPLIT*BH*2*HD*HD];
__device__ float g_amap[BH*HD*HD];

// ---------------- async copy / mma helpers ------------------------------------
#define CP16(dst_u32, src_ptr) \
    asm volatile("cp.async.cg.shared.global [%0], [%1], 16;\n" \
                 :: "r"(dst_u32), "l"(src_ptr))
#define CPCOMMIT() asm volatile("cp.async.commit_group;\n" ::: "memory")
#define CPWAIT1()  asm volatile("cp.async.wait_group 1;\n" ::: "memory")

__device__ __forceinline__ void ldsm4(unsigned r[4], unsigned addr) {
    asm volatile("ldmatrix.sync.aligned.m8n8.x4.shared.b16 {%0,%1,%2,%3}, [%4];"
                 : "=r"(r[0]), "=r"(r[1]), "=r"(r[2]), "=r"(r[3]) : "r"(addr));
}

__device__ __forceinline__ void mma16816(float* c, const unsigned a[4],
                                         unsigned b0, unsigned b1) {
    asm volatile(
        "mma.sync.aligned.m16n8k16.row.col.f32.f16.f16.f32 "
        "{%0,%1,%2,%3}, {%4,%5,%6,%7}, {%8,%9}, {%0,%1,%2,%3};"
        : "+f"(c[0]), "+f"(c[1]), "+f"(c[2]), "+f"(c[3])
        : "r"(a[0]), "r"(a[1]), "r"(a[2]), "r"(a[3]), "r"(b0), "r"(b1));
}

// ---------------- f32 -> fp16 (plain) -----------------------------------------
__global__ __launch_bounds__(256) void convh_kernel(
    const float* __restrict__ src, __half* __restrict__ dst)
{
    size_t base = (size_t)(blockIdx.x * blockDim.x + threadIdx.x) * 8;
    float4 v0 = *(const float4*)(src + base);
    float4 v1 = *(const float4*)(src + base + 4);
    __half o[8];
    o[0] = __float2half_rn(v0.x); o[1] = __float2half_rn(v0.y);
    o[2] = __float2half_rn(v0.z); o[3] = __float2half_rn(v0.w);
    o[4] = __float2half_rn(v1.x); o[5] = __float2half_rn(v1.y);
    o[6] = __float2half_rn(v1.z); o[7] = __float2half_rn(v1.w);
    *(uint4*)(dst + base) = *(const uint4*)o;
}

// ---------------- fp16 GEMM: C[m,n]=sum_k A[m,k]*B[n,k], K=DIM ---------------
// 128x128 tile, BK=64, 256 thr = 8 warps (2x4), warp 64x32, 3-stage cp.async.
// Batched via blockIdx.z with element strides. Output fp16 (Ch) or f32+bias.
__global__ __launch_bounds__(256) void gemm_f16(
    const __half* __restrict__ A0, const __half* __restrict__ B0,
    const float* __restrict__ bias, float* __restrict__ Cf0,
    __half* __restrict__ Ch0, int N,
    size_t strA, size_t strB, size_t strC)
{
    extern __shared__ __half sm[];
    const unsigned smem_base = (unsigned)__cvta_generic_to_shared(sm);
    const int tid  = threadIdx.x;
    const int lane = tid & 31;
    const int warp = tid >> 5;
    const int wm = (warp >> 2) * 64;
    const int wn = (warp & 3) * 32;
    const int bm = blockIdx.y * 128;
    const int bn = blockIdx.x * 128;
    const int z  = blockIdx.z;
    const int g4 = lane >> 2;
    const int tg = lane & 3;

    const __half* A2 = A0 + (size_t)z * strA;
    const __half* B2 = B0 + (size_t)z * strB;

    float acc[4][4][4];
#pragma unroll
    for (int t = 0; t < 4; ++t)
#pragma unroll
        for (int u = 0; u < 4; ++u)
#pragma unroll
            for (int r = 0; r < 4; ++r) acc[t][u][r] = 0.0f;

    auto load_chunk = [&](int kc, int bf) {
#pragma unroll
        for (int it = 0; it < 4; ++it) {
            int idx = tid + it * 256;
            int row = idx >> 3;
            int c8  = idx & 7;
            const __half* sa = A2 + (size_t)(bm + row) * DIM + kc * 64 + c8 * 8;
            const __half* sb = B2 + (size_t)(bn + row) * DIM + kc * 64 + c8 * 8;
            unsigned sw = (unsigned)((c8 ^ (row & 7)) * 16);
            unsigned da = smem_base + bf * 16384 + row * 128 + sw;
            unsigned db = smem_base + 49152 + bf * 16384 + row * 128 + sw;
            CP16(da, sa);
            CP16(db, sb);
        }
    };

    const int khalf = lane >> 4;
    int rowA[4], rowB[2];
#pragma unroll
    for (int t = 0; t < 4; ++t) rowA[t] = wm + t * 16 + (lane & 15);
#pragma unroll
    for (int p = 0; p < 2; ++p) rowB[p] = wn + p * 16 + (lane & 15);

    load_chunk(0, 0); CPCOMMIT();
    load_chunk(1, 1); CPCOMMIT();

    const int NC = DIM / 64;   // 16
    for (int kc = 0; kc < NC; ++kc) {
        CPWAIT1();
        __syncthreads();
        if (kc + 2 < NC) { load_chunk(kc + 2, (kc + 2) % 3); CPCOMMIT(); }

        const int bf = kc % 3;
        const unsigned abase = smem_base + bf * 16384;
        const unsigned bbase = smem_base + 49152 + bf * 16384;

#pragma unroll
        for (int s = 0; s < 4; ++s) {
            const int ch = s * 2 + khalf;
            unsigned a[4][4], b[2][4];
#pragma unroll
            for (int t = 0; t < 4; ++t) {
                unsigned addr = abase + rowA[t] * 128 +
                                (unsigned)((ch ^ (rowA[t] & 7)) * 16);
                ldsm4(a[t], addr);
            }
#pragma unroll
            for (int p = 0; p < 2; ++p) {
                unsigned addr = bbase + rowB[p] * 128 +
                                (unsigned)((ch ^ (rowB[p] & 7)) * 16);
                ldsm4(b[p], addr);
            }
#pragma unroll
            for (int t = 0; t < 4; ++t)
#pragma unroll
                for (int u = 0; u < 4; ++u) {
                    int p = u >> 1, h = u & 1;
                    mma16816(acc[t][u], a[t], b[p][h], b[p][2 + h]);
                }
        }
    }

#pragma unroll
    for (int t = 0; t < 4; ++t) {
        int r = bm + wm + t * 16 + g4;
#pragma unroll
        for (int u = 0; u < 4; ++u) {
            int c = bn + wn + u * 8 + tg * 2;
            if (Ch0) {
                __half* Ch = Ch0 + (size_t)z * strC;
                *(__half2*)&Ch[(size_t)r * N + c] =
                    __floats2half2_rn(acc[t][u][0], acc[t][u][1]);
                *(__half2*)&Ch[(size_t)(r + 8) * N + c] =
                    __floats2half2_rn(acc[t][u][2], acc[t][u][3]);
            } else {
                float* Cf = Cf0 + (size_t)z * strC;
                float b0 = 0.0f, b1 = 0.0f;
                if (bias) { b0 = bias[c]; b1 = bias[c + 1]; }
                *(float2*)&Cf[(size_t)r * N + c] =
                    make_float2(acc[t][u][0] + b0, acc[t][u][1] + b1);
                *(float2*)&Cf[(size_t)(r + 8) * N + c] =
                    make_float2(acc[t][u][2] + b0, acc[t][u][3] + b1);
            }
        }
    }
}

// ---------------- per-(b,h) Gram partials via fp16 mma ------------------------
__global__ __launch_bounds__(256) void kkt_kernel()
{
    int bh = blockIdx.x;
    int split = blockIdx.y;
    int b = bh >> 4, h = bh & 15;
    const __half* kb = g_kh + (size_t)b * SEQ * DIM + h * HD;
    const __half* vb = g_vh + (size_t)b * SEQ * DIM + h * HD;

    __shared__ __half T[128][72];
    const unsigned tb = (unsigned)__cvta_generic_to_shared(&T[0][0]);
    const int tid = threadIdx.x;
    const int lane = tid & 31;
    const int warp = tid >> 5;
    const int wm = (warp >> 2) * 32;
    const int wn = (warp & 3) * 32;
    const int g4 = lane >> 2;
    const int tg = lane & 3;

    float acc[2][4][4];
#pragma unroll
    for (int mt = 0; mt < 2; ++mt)
#pragma unroll
        for (int u = 0; u < 4; ++u)
#pragma unroll
            for (int r = 0; r < 4; ++r) acc[mt][u][r] = 0.0f;

    const int khalf = lane >> 4;
    int rowA[2], rowB[2];
#pragma unroll
    for (int mt = 0; mt < 2; ++mt) rowA[mt] = wm + mt * 16 + (lane & 15);
#pragma unroll
    for (int p = 0; p < 2; ++p) rowB[p] = wn + p * 16 + (lane & 15);

    int nbase0 = split * (SEQ / NSPLIT);
    for (int t0 = 0; t0 < SEQ / NSPLIT; t0 += 64) {
        __syncthreads();
#pragma unroll
        for (int it = 0; it < 8; ++it) {
            int idx = tid + it * 256;
            int tensor = idx >> 10;
            int rem = idx & 1023;
            int n = rem & 63;
            int c4 = (rem >> 6) * 4;
            const __half* src = (tensor ? vb : kb) +
                                (size_t)(nbase0 + t0 + n) * DIM + c4;
            uint2 u2 = *(const uint2*)src;
            __half2 p0 = *reinterpret_cast<__half2*>(&u2.x);
            __half2 p1 = *reinterpret_cast<__half2*>(&u2.y);
            T[tensor * 64 + c4 + 0][n] = __low2half(p0);
            T[tensor * 64 + c4 + 1][n] = __high2half(p0);
            T[tensor * 64 + c4 + 2][n] = __low2half(p1);
            T[tensor * 64 + c4 + 3][n] = __high2half(p1);
        }
        __syncthreads();

#pragma unroll
        for (int ks = 0; ks < 4; ++ks) {
            unsigned a[2][4], bfr[2][4];
            unsigned colb = (unsigned)(ks * 32 + khalf * 16);
#pragma unroll
            for (int mt = 0; mt < 2; ++mt)
                ldsm4(a[mt], tb + rowA[mt] * 144 + colb);
#pragma unroll
            for (int p = 0; p < 2; ++p)
                ldsm4(bfr[p], tb + rowB[p] * 144 + colb);
#pragma unroll
            for (int mt = 0; mt < 2; ++mt)
#pragma unroll
                for (int u = 0; u < 4; ++u) {
                    int p = u >> 1, hh = u & 1;
                    mma16816(acc[mt][u], a[mt], bfr[p][hh], bfr[p][2 + hh]);
                }
        }
    }

    float* pkk = g_part + (size_t)(split * BH + bh) * 2 * 4096;
    float* pkv = pkk + 4096;
#pragma unroll
    for (int mt = 0; mt < 2; ++mt) {
        int d = wm + mt * 16 + g4;
#pragma unroll
        for (int u = 0; u < 4; ++u) {
            int j = wn + u * 8 + tg * 2;
            float* dst = (j < 64) ? (pkk + d * 64 + j) : (pkv + d * 64 + (j - 64));
            *(float2*)dst = make_float2(acc[mt][u][0], acc[mt][u][1]);
            float* dst2 = (j < 64) ? (pkk + (d + 8) * 64 + j)
                                   : (pkv + (d + 8) * 64 + (j - 64));
            *(float2*)dst2 = make_float2(acc[mt][u][2], acc[mt][u][3]);
        }
    }
}

// ------- reduce partials, solve (kk+aI) X = ktv, column softmax -> g_amap ----
__global__ __launch_bounds__(256) void solve_kernel(
    const float* __restrict__ alpha_p, const float* __restrict__ temp_p)
{
    int bh = blockIdx.x;
    __shared__ float A[64][65];
    __shared__ float X[64][65];
    int tid = threadIdx.x;

    for (int i = tid; i < 4096; i += 256) {
        float skk = 0.0f, skv = 0.0f;
#pragma unroll
        for (int s = 0; s < NSPLIT; ++s) {
            const float* p = g_part + ((size_t)(s * BH + bh) * 2) * 4096;
            skk += p[i];
            skv += p[4096 + i];
        }
        A[i >> 6][i & 63] = skk;
        X[i >> 6][i & 63] = skv;
    }
    __syncthreads();
    if (tid < 64) A[tid][tid] += alpha_p[0];

    int r  = tid >> 2;
    int c0 = (tid & 3) * 16;
    for (int p = 0; p < 64; ++p) {
        __syncthreads();
        float pinv = 1.0f / A[p][p];
        __syncthreads();
        if (tid < 64)      A[p][tid]      *= pinv;
        else if (tid < 128) X[p][tid - 64] *= pinv;
        __syncthreads();
        float f = (r != p) ? A[r][p] : 0.0f;
        __syncthreads();
        if (r != p) {
#pragma unroll
            for (int c = 0; c < 16; ++c) {
                A[r][c0 + c] = fmaf(-f, A[p][c0 + c], A[r][c0 + c]);
                X[r][c0 + c] = fmaf(-f, X[p][c0 + c], X[r][c0 + c]);
            }
        }
    }
    __syncthreads();

    if (tid < 64) {
        float invt = 1.0f / temp_p[0];
        float mx = -1e30f;
        for (int d = 0; d < 64; ++d) mx = fmaxf(mx, X[d][tid] * invt);
        float s = 0.0f;
        for (int d = 0; d < 64; ++d) s += expf(X[d][tid] * invt - mx);
        float inv_s = 1.0f / s;
        for (int d = 0; d < 64; ++d)
            g_amap[(size_t)bh * 4096 + d * 64 + tid] =
                expf(X[d][tid] * invt - mx) * inv_s;
    }
}

// ---------- fold1: W'_b[din, h*64+j] = sum_e Wq[h*64+e, din] * amap[e, j] -----
// grid: (BH, DIM/256), block 256 = 32(d-groups) x 8(j-groups), 8x8 microtile.
__global__ __launch_bounds__(256) void fold1_kernel()
{
    int bh = blockIdx.x;
    int chunk = blockIdx.y;           // 256 din per chunk
    int b = bh >> 4, h = bh & 15;

    __shared__ __half WqS[64][256];   // [e][din_local]
    __shared__ float  AmS[64][64];    // [e][j]
    int tid = threadIdx.x;

    const __half* wq = g_wh[0] + (size_t)(h * 64) * DIM + chunk * 256;
#pragma unroll
    for (int it = 0; it < 8; ++it) {
        int idx = tid + it * 256;     // 2048 uint4 total
        int e = idx >> 5;             // 32 uint4 per row
        int c8 = (idx & 31) * 8;
        *(uint4*)&WqS[e][c8] = *(const uint4*)(wq + (size_t)e * DIM + c8);
    }
#pragma unroll
    for (int it = 0; it < 4; ++it) {
        int idx = tid + it * 256;     // 1024 float4
        int e = idx >> 4;
        int j4 = (idx & 15) * 4;
        *(float4*)&AmS[e][j4] =
            *(const float4*)&g_amap[(size_t)bh * 4096 + e * 64 + j4];
    }
    __syncthreads();

    int ty = tid >> 3;                // 0..31 -> d0 = ty*8
    int tx = tid & 7;                 // 0..7  -> j0 = tx*8
    float acc[8][8];
#pragma unroll
    for (int i = 0; i < 8; ++i)
#pragma unroll
        for (int j = 0; j < 8; ++j) acc[i][j] = 0.0f;

#pragma unroll 4
    for (int e = 0; e < 64; ++e) {
        __half ah[8];
        *(uint4*)ah = *(const uint4*)&WqS[e][ty * 8];
        float bv[8];
        float4 b0 = *(const float4*)&AmS[e][tx * 8];
        float4 b1 = *(const float4*)&AmS[e][tx * 8 + 4];
        bv[0]=b0.x; bv[1]=b0.y; bv[2]=b0.z; bv[3]=b0.w;
        bv[4]=b1.x; bv[5]=b1.y; bv[6]=b1.z; bv[7]=b1.w;
#pragma unroll
        for (int i = 0; i < 8; ++i) {
            float av = __half2float(ah[i]);
#pragma unroll
            for (int j = 0; j < 8; ++j) acc[i][j] = fmaf(av, bv[j], acc[i][j]);
        }
    }

    __half* wp = g_wp + (size_t)b * DIM * DIM;
#pragma unroll
    for (int i = 0; i < 8; ++i) {
        int din = chunk * 256 + ty * 8 + i;
        __half o[8];
#pragma unroll
        for (int j = 0; j < 8; ++j) o[j] = __float2half_rn(acc[i][j]);
        *(uint4*)&wp[(size_t)din * DIM + h * 64 + tx * 8] = *(const uint4*)o;
    }
}

// ---------------- LayerNorm(proj + x) ----------------------------------------
__global__ __launch_bounds__(256) void ln_kernel(
    const float* __restrict__ x, const float* __restrict__ gamma,
    const float* __restrict__ beta, float* __restrict__ out)
{
    int row = blockIdx.x;
    int tid = threadIdx.x;
    const float* pr = g_proj + (size_t)row * DIM;
    const float* xr = x      + (size_t)row * DIM;

    float4 pv = *(const float4*)(pr + tid * 4);
    float4 xv = *(const float4*)(xr + tid * 4);
    float v[4] = { pv.x + xv.x, pv.y + xv.y, pv.z + xv.z, pv.w + xv.w };

    float s = v[0] + v[1] + v[2] + v[3];
    float s2 = v[0]*v[0] + v[1]*v[1] + v[2]*v[2] + v[3]*v[3];

#pragma unroll
    for (int o = 16; o > 0; o >>= 1) {
        s  += __shfl_xor_sync(0xFFFFFFFFu, s,  o);
        s2 += __shfl_xor_sync(0xFFFFFFFFu, s2, o);
    }
    __shared__ float rs[8], rs2[8];
    int wid = tid >> 5, lane = tid & 31;
    if (lane == 0) { rs[wid] = s; rs2[wid] = s2; }
    __syncthreads();
    if (wid == 0) {
        float a  = (lane < 8) ? rs[lane]  : 0.0f;
        float a2 = (lane < 8) ? rs2[lane] : 0.0f;
#pragma unroll
        for (int o = 4; o > 0; o >>= 1) {
            a  += __shfl_xor_sync(0xFFFFFFFFu, a,  o);
            a2 += __shfl_xor_sync(0xFFFFFFFFu, a2, o);
        }
        if (lane == 0) { rs[0] = a; rs2[0] = a2; }
    }
    __syncthreads();
    float mu  = rs[0]  * (1.0f / DIM);
    float var = rs2[0] * (1.0f / DIM) - mu * mu;
    float rstd = rsqrtf(var + LNEPS);

    const float* gp = gamma + tid * 4;
    const float* bp = beta  + tid * 4;
    float4 o4;
    o4.x = (v[0] - mu) * rstd * gp[0] + bp[0];
    o4.y = (v[1] - mu) * rstd * gp[1] + bp[1];
    o4.z = (v[2] - mu) * rstd * gp[2] + bp[2];
    o4.w = (v[3] - mu) * rstd * gp[3] + bp[3];
    *(float4*)(out + (size_t)row * DIM + tid * 4) = o4;
}

// ---------------- host launcher ----------------------------------------------
extern "C" void kernel_launch(void* const* d_in, const int* in_sizes, int n_in,
                              void* d_out, int out_size)
{
    (void)in_sizes; (void)n_in; (void)out_size;
    const float* x     = (const float*)d_in[0];
    const float* Wq    = (const float*)d_in[1];
    const float* Wk    = (const float*)d_in[2];
    const float* Wv    = (const float*)d_in[3];
    const float* Wo    = (const float*)d_in[4];
    const float* bo    = (const float*)d_in[5];
    const float* alpha = (const float*)d_in[6];
    const float* temp  = (const float*)d_in[7];
    const float* gamma = (const float*)d_in[8];
    const float* beta  = (const float*)d_in[9];
    float* out = (float*)d_out;

    __half *xh, *wh, *kh, *vh, *wpp, *w2p;
    float *projp;
    cudaGetSymbolAddress((void**)&xh,    g_xh);
    cudaGetSymbolAddress((void**)&wh,    g_wh);
    cudaGetSymbolAddress((void**)&kh,    g_kh);
    cudaGetSymbolAddress((void**)&vh,    g_vh);
    cudaGetSymbolAddress((void**)&wpp,   g_wp);
    cudaGetSymbolAddress((void**)&w2p,   g_w2);
    cudaGetSymbolAddress((void**)&projp, g_proj);

    const int SMEM_GEMM = 98304;
    cudaFuncSetAttribute(gemm_f16,
                         cudaFuncAttributeMaxDynamicSharedMemorySize, SMEM_GEMM);

    const size_t WSZ = (size_t)DIM * DIM;
    convh_kernel<<<MTOT*DIM/2048, 256>>>(x,  xh);
    convh_kernel<<<DIM*DIM/2048, 256>>>(Wq, wh + 0*WSZ);
    convh_kernel<<<DIM*DIM/2048, 256>>>(Wk, wh + 1*WSZ);
    convh_kernel<<<DIM*DIM/2048, 256>>>(Wv, wh + 2*WSZ);
    convh_kernel<<<DIM*DIM/2048, 256>>>(Wo, wh + 3*WSZ);

    // K, V projections
    gemm_f16<<<dim3(DIM/128, MTOT/128, 1), 256, SMEM_GEMM>>>(
        xh, wh + 1*WSZ, nullptr, nullptr, kh, DIM, 0, 0, 0);
    gemm_f16<<<dim3(DIM/128, MTOT/128, 1), 256, SMEM_GEMM>>>(
        xh, wh + 2*WSZ, nullptr, nullptr, vh, DIM, 0, 0, 0);

    // attention map
    kkt_kernel<<<dim3(BH, NSPLIT), 256>>>();
    solve_kernel<<<BH, 256>>>(alpha, temp);

    // fold amap into weights:  W'_b = fold(Wq, amap),  W2^T_b = Wo @ W'_b (k=j)
    fold1_kernel<<<dim3(BH, DIM/256), 256>>>();
    gemm_f16<<<dim3(DIM/128, DIM/128, BATCH), 256, SMEM_GEMM>>>(
        wh + 3*WSZ, wpp, nullptr, nullptr, w2p, DIM, 0, WSZ, WSZ);

    // proj[b] = x[b] @ W2_b + bo
    gemm_f16<<<dim3(DIM/128, SEQ/128, BATCH), 256, SMEM_GEMM>>>(
        xh, w2p, bo, projp, nullptr, DIM, (size_t)SEQ*DIM, WSZ, (size_t)SEQ*DIM);

    ln_kernel<<<MTOT, 256>>>(x, gamma, beta, out);
}

// round 9
// speedup vs baseline: 9.8509x; 1.2009x over previous
#include <cuda_runtime.h>
#include <cuda_fp16.h>
#include <cstdint>
#include <math.h>

#define BATCH 4
#define SEQ   4096
#define DIM   1024
#define NH    16
#define HD    64
#define BH    (BATCH*NH)          // 64
#define MTOT  (BATCH*SEQ)         // 16384
#define LNEPS 1e-5f

// ---------------- scratch (static device globals; no allocation) -------------
__device__ __align__(16) __half g_xh [(size_t)MTOT*DIM];
__device__ __align__(16) __half g_xt [(size_t)BATCH*DIM*SEQ];   // X^T per batch
__device__ __align__(16) __half g_wh [4][(size_t)DIM*DIM];
__device__ __align__(16) __half g_gm [(size_t)BATCH*DIM*DIM];   // G = X^T X
__device__ __align__(16) __half g_hk [(size_t)BATCH*DIM*DIM];   // Hk = Wk G
__device__ __align__(16) __half g_wp [(size_t)BATCH*DIM*DIM];   // folded W'
__device__ __align__(16) __half g_w2 [(size_t)BATCH*DIM*DIM];   // folded W2^T
__device__ float g_proj[MTOT*DIM];
__device__ float g_part[BH*2*HD*HD];
__device__ float g_amap[BH*HD*HD];

// ---------------- async copy / mma helpers ------------------------------------
#define CP16(dst_u32, src_ptr) \
    asm volatile("cp.async.cg.shared.global [%0], [%1], 16;\n" \
                 :: "r"(dst_u32), "l"(src_ptr))
#define CPCOMMIT() asm volatile("cp.async.commit_group;\n" ::: "memory")
#define CPWAIT1()  asm volatile("cp.async.wait_group 1;\n" ::: "memory")

__device__ __forceinline__ void ldsm4(unsigned r[4], unsigned addr) {
    asm volatile("ldmatrix.sync.aligned.m8n8.x4.shared.b16 {%0,%1,%2,%3}, [%4];"
                 : "=r"(r[0]), "=r"(r[1]), "=r"(r[2]), "=r"(r[3]) : "r"(addr));
}

__device__ __forceinline__ void mma16816(float* c, const unsigned a[4],
                                         unsigned b0, unsigned b1) {
    asm volatile(
        "mma.sync.aligned.m16n8k16.row.col.f32.f16.f16.f32 "
        "{%0,%1,%2,%3}, {%4,%5,%6,%7}, {%8,%9}, {%0,%1,%2,%3};"
        : "+f"(c[0]), "+f"(c[1]), "+f"(c[2]), "+f"(c[3])
        : "r"(a[0]), "r"(a[1]), "r"(a[2]), "r"(a[3]), "r"(b0), "r"(b1));
}

// ---------------- f32 -> fp16 (plain) -----------------------------------------
__global__ __launch_bounds__(256) void convh_kernel(
    const float* __restrict__ src, __half* __restrict__ dst)
{
    size_t base = (size_t)(blockIdx.x * blockDim.x + threadIdx.x) * 8;
    float4 v0 = *(const float4*)(src + base);
    float4 v1 = *(const float4*)(src + base + 4);
    __half o[8];
    o[0] = __float2half_rn(v0.x); o[1] = __float2half_rn(v0.y);
    o[2] = __float2half_rn(v0.z); o[3] = __float2half_rn(v0.w);
    o[4] = __float2half_rn(v1.x); o[5] = __float2half_rn(v1.y);
    o[6] = __float2half_rn(v1.z); o[7] = __float2half_rn(v1.w);
    *(uint4*)(dst + base) = *(const uint4*)o;
}

// ---------------- xh -> xT (per-batch 64x64 tiled transpose, fp16) ------------
// grid: (DIM/64, SEQ/64, BATCH)
__global__ __launch_bounds__(256) void transpose_kernel()
{
    int ib = blockIdx.x, nb = blockIdx.y, b = blockIdx.z;
    __shared__ __half Ts[64][64];
    int tid = threadIdx.x;
    const __half* src = g_xh + ((size_t)(b * SEQ + nb * 64)) * DIM + ib * 64;
#pragma unroll
    for (int it = 0; it < 2; ++it) {
        int idx = tid + it * 256;
        int r  = idx >> 3;                    // n-local 0..63
        int cc = idx & 7;                     // i-chunk 0..7
        int ccs = cc ^ ((r >> 3) & 7);        // XOR swizzle
        *(uint4*)&Ts[r][ccs * 8] = *(const uint4*)(src + (size_t)r * DIM + cc * 8);
    }
    __syncthreads();
    __half* dst = g_xt + ((size_t)b * DIM + ib * 64) * SEQ + nb * 64;
#pragma unroll
    for (int it = 0; it < 2; ++it) {
        int idx = tid + it * 256;
        int ng = idx & 7;                     // n-chunk
        int i  = idx >> 3;                    // i-local 0..63
        __half o[8];
#pragma unroll
        for (int k = 0; k < 8; ++k) {
            int n = ng * 8 + k;
            int cc = (i >> 3) ^ ((n >> 3) & 7);
            o[k] = Ts[n][cc * 8 + (i & 7)];
        }
        *(uint4*)(dst + (size_t)i * SEQ + ng * 8) = *(const uint4*)o;
    }
}

// ---------------- fp16 GEMM: C[m,n]=sum_k A[m,k]*B[n,k] ----------------------
// 128x128 tile, BK=64, 256 thr = 8 warps (2x4), warp 64x32, 3-stage cp.async.
// nck = K/64 chunks; lda/ldb = row strides; batched via blockIdx.z.
__global__ __launch_bounds__(256) void gemm_f16(
    const __half* __restrict__ A0, const __half* __restrict__ B0,
    const float* __restrict__ bias, float* __restrict__ Cf0,
    __half* __restrict__ Ch0, int N, int nck, int lda, int ldb,
    size_t strA, size_t strB, size_t strC)
{
    extern __shared__ __half sm[];
    const unsigned smem_base = (unsigned)__cvta_generic_to_shared(sm);
    const int tid  = threadIdx.x;
    const int lane = tid & 31;
    const int warp = tid >> 5;
    const int wm = (warp >> 2) * 64;
    const int wn = (warp & 3) * 32;
    const int bm = blockIdx.y * 128;
    const int bn = blockIdx.x * 128;
    const int z  = blockIdx.z;
    const int g4 = lane >> 2;
    const int tg = lane & 3;

    const __half* A2 = A0 + (size_t)z * strA;
    const __half* B2 = B0 + (size_t)z * strB;

    float acc[4][4][4];
#pragma unroll
    for (int t = 0; t < 4; ++t)
#pragma unroll
        for (int u = 0; u < 4; ++u)
#pragma unroll
            for (int r = 0; r < 4; ++r) acc[t][u][r] = 0.0f;

    auto load_chunk = [&](int kc, int bf) {
#pragma unroll
        for (int it = 0; it < 4; ++it) {
            int idx = tid + it * 256;
            int row = idx >> 3;
            int c8  = idx & 7;
            const __half* sa = A2 + (size_t)(bm + row) * lda + kc * 64 + c8 * 8;
            const __half* sb = B2 + (size_t)(bn + row) * ldb + kc * 64 + c8 * 8;
            unsigned sw = (unsigned)((c8 ^ (row & 7)) * 16);
            unsigned da = smem_base + bf * 16384 + row * 128 + sw;
            unsigned db = smem_base + 49152 + bf * 16384 + row * 128 + sw;
            CP16(da, sa);
            CP16(db, sb);
        }
    };

    const int khalf = lane >> 4;
    int rowA[4], rowB[2];
#pragma unroll
    for (int t = 0; t < 4; ++t) rowA[t] = wm + t * 16 + (lane & 15);
#pragma unroll
    for (int p = 0; p < 2; ++p) rowB[p] = wn + p * 16 + (lane & 15);

    load_chunk(0, 0); CPCOMMIT();
    load_chunk(1, 1); CPCOMMIT();

    for (int kc = 0; kc < nck; ++kc) {
        CPWAIT1();
        __syncthreads();
        if (kc + 2 < nck) { load_chunk(kc + 2, (kc + 2) % 3); CPCOMMIT(); }

        const int bf = kc % 3;
        const unsigned abase = smem_base + bf * 16384;
        const unsigned bbase = smem_base + 49152 + bf * 16384;

#pragma unroll
        for (int s = 0; s < 4; ++s) {
            const int ch = s * 2 + khalf;
            unsigned a[4][4], b[2][4];
#pragma unroll
            for (int t = 0; t < 4; ++t) {
                unsigned addr = abase + rowA[t] * 128 +
                                (unsigned)((ch ^ (rowA[t] & 7)) * 16);
                ldsm4(a[t], addr);
            }
#pragma unroll
            for (int p = 0; p < 2; ++p) {
                unsigned addr = bbase + rowB[p] * 128 +
                                (unsigned)((ch ^ (rowB[p] & 7)) * 16);
                ldsm4(b[p], addr);
            }
#pragma unroll
            for (int t = 0; t < 4; ++t)
#pragma unroll
                for (int u = 0; u < 4; ++u) {
                    int p = u >> 1, h = u & 1;
                    mma16816(acc[t][u], a[t], b[p][h], b[p][2 + h]);
                }
        }
    }

#pragma unroll
    for (int t = 0; t < 4; ++t) {
        int r = bm + wm + t * 16 + g4;
#pragma unroll
        for (int u = 0; u < 4; ++u) {
            int c = bn + wn + u * 8 + tg * 2;
            if (Ch0) {
                __half* Ch = Ch0 + (size_t)z * strC;
                *(__half2*)&Ch[(size_t)r * N + c] =
                    __floats2half2_rn(acc[t][u][0], acc[t][u][1]);
                *(__half2*)&Ch[(size_t)(r + 8) * N + c] =
                    __floats2half2_rn(acc[t][u][2], acc[t][u][3]);
            } else {
                float* Cf = Cf0 + (size_t)z * strC;
                float b0 = 0.0f, b1 = 0.0f;
                if (bias) { b0 = bias[c]; b1 = bias[c + 1]; }
                *(float2*)&Cf[(size_t)r * N + c] =
                    make_float2(acc[t][u][0] + b0, acc[t][u][1] + b1);
                *(float2*)&Cf[(size_t)(r + 8) * N + c] =
                    make_float2(acc[t][u][2] + b0, acc[t][u][3] + b1);
            }
        }
    }
}

// -------- kkt2: kk/kv from Hk_h · [Wk_h | Wv_h]^T (per-head diag blocks) ------
// C[d][j] = sum_i Hk[h*64+d][i] * T[j][i];  j<64: T=Wk_h (kk), j>=64: Wv_h (kv)
__global__ __launch_bounds__(256) void kkt2_kernel()
{
    int bh = blockIdx.x;
    int b = bh >> 4, h = bh & 15;
    const __half* hk = g_hk    + (size_t)b * DIM * DIM + (size_t)(h * HD) * DIM;
    const __half* wk = g_wh[1] + (size_t)(h * HD) * DIM;
    const __half* wv = g_wh[2] + (size_t)(h * HD) * DIM;

    __shared__ __half Hs[64][72];
    __shared__ __half Ts[128][72];
    const unsigned hb = (unsigned)__cvta_generic_to_shared(&Hs[0][0]);
    const unsigned tb = (unsigned)__cvta_generic_to_shared(&Ts[0][0]);
    const int tid = threadIdx.x;
    const int lane = tid & 31;
    const int warp = tid >> 5;
    const int wm = (warp >> 2) * 32;
    const int wn = (warp & 3) * 32;
    const int g4 = lane >> 2;
    const int tg = lane & 3;

    float acc[2][4][4];
#pragma unroll
    for (int mt = 0; mt < 2; ++mt)
#pragma unroll
        for (int u = 0; u < 4; ++u)
#pragma unroll
            for (int r = 0; r < 4; ++r) acc[mt][u][r] = 0.0f;

    const int khalf = lane >> 4;
    int rowA[2], rowB[2];
#pragma unroll
    for (int mt = 0; mt < 2; ++mt) rowA[mt] = wm + mt * 16 + (lane & 15);
#pragma unroll
    for (int p = 0; p < 2; ++p) rowB[p] = wn + p * 16 + (lane & 15);

    for (int i0 = 0; i0 < DIM; i0 += 64) {
        __syncthreads();
#pragma unroll
        for (int it = 0; it < 2; ++it) {          // Hs: 64x64 = 512 uint4
            int idx = tid + it * 256;
            int r = idx >> 3, c8 = (idx & 7) * 8;
            *(uint4*)&Hs[r][c8] = *(const uint4*)(hk + (size_t)r * DIM + i0 + c8);
        }
#pragma unroll
        for (int it = 0; it < 4; ++it) {          // Ts: 128x64 = 1024 uint4
            int idx = tid + it * 256;
            int r = idx >> 3, c8 = (idx & 7) * 8;
            const __half* src = (r < 64 ? wk + (size_t)r * DIM
                                        : wv + (size_t)(r - 64) * DIM) + i0 + c8;
            *(uint4*)&Ts[r][c8] = *(const uint4*)src;
        }
        __syncthreads();

#pragma unroll
        for (int ks = 0; ks < 4; ++ks) {
            unsigned a[2][4], bfr[2][4];
            unsigned colb = (unsigned)(ks * 32 + khalf * 16);
#pragma unroll
            for (int mt = 0; mt < 2; ++mt)
                ldsm4(a[mt], hb + rowA[mt] * 144 + colb);
#pragma unroll
            for (int p = 0; p < 2; ++p)
                ldsm4(bfr[p], tb + rowB[p] * 144 + colb);
#pragma unroll
            for (int mt = 0; mt < 2; ++mt)
#pragma unroll
                for (int u = 0; u < 4; ++u) {
                    int p = u >> 1, hh = u & 1;
                    mma16816(acc[mt][u], a[mt], bfr[p][hh], bfr[p][2 + hh]);
                }
        }
    }

    float* pkk = g_part + (size_t)bh * 2 * 4096;
    float* pkv = pkk + 4096;
#pragma unroll
    for (int mt = 0; mt < 2; ++mt) {
        int d = wm + mt * 16 + g4;
#pragma unroll
        for (int u = 0; u < 4; ++u) {
            int j = wn + u * 8 + tg * 2;
            float* dst = (j < 64) ? (pkk + d * 64 + j) : (pkv + d * 64 + (j - 64));
            *(float2*)dst = make_float2(acc[mt][u][0], acc[mt][u][1]);
            float* dst2 = (j < 64) ? (pkk + (d + 8) * 64 + j)
                                   : (pkv + (d + 8) * 64 + (j - 64));
            *(float2*)dst2 = make_float2(acc[mt][u][2], acc[mt][u][3]);
        }
    }
}

// ------- solve (kk+aI) X = ktv, column softmax -> g_amap ----------------------
__global__ __launch_bounds__(256) void solve_kernel(
    const float* __restrict__ alpha_p, const float* __restrict__ temp_p)
{
    int bh = blockIdx.x;
    __shared__ float A[64][65];
    __shared__ float X[64][65];
    int tid = threadIdx.x;

    const float* p = g_part + (size_t)bh * 2 * 4096;
    for (int i = tid; i < 4096; i += 256) {
        A[i >> 6][i & 63] = p[i];
        X[i >> 6][i & 63] = p[4096 + i];
    }
    __syncthreads();
    if (tid < 64) A[tid][tid] += alpha_p[0];

    int r  = tid >> 2;
    int c0 = (tid & 3) * 16;
    for (int pp = 0; pp < 64; ++pp) {
        __syncthreads();
        float pinv = 1.0f / A[pp][pp];
        __syncthreads();
        if (tid < 64)      A[pp][tid]      *= pinv;
        else if (tid < 128) X[pp][tid - 64] *= pinv;
        __syncthreads();
        float f = (r != pp) ? A[r][pp] : 0.0f;
        __syncthreads();
        if (r != pp) {
#pragma unroll
            for (int c = 0; c < 16; ++c) {
                A[r][c0 + c] = fmaf(-f, A[pp][c0 + c], A[r][c0 + c]);
                X[r][c0 + c] = fmaf(-f, X[pp][c0 + c], X[r][c0 + c]);
            }
        }
    }
    __syncthreads();

    if (tid < 64) {
        float invt = 1.0f / temp_p[0];
        float mx = -1e30f;
        for (int d = 0; d < 64; ++d) mx = fmaxf(mx, X[d][tid] * invt);
        float s = 0.0f;
        for (int d = 0; d < 64; ++d) s += expf(X[d][tid] * invt - mx);
        float inv_s = 1.0f / s;
        for (int d = 0; d < 64; ++d)
            g_amap[(size_t)bh * 4096 + d * 64 + tid] =
                expf(X[d][tid] * invt - mx) * inv_s;
    }
}

// ---------- fold1: W'_b[din, h*64+j] = sum_e Wq[h*64+e, din] * amap[e, j] -----
__global__ __launch_bounds__(256) void fold1_kernel()
{
    int bh = blockIdx.x;
    int chunk = blockIdx.y;
    int b = bh >> 4, h = bh & 15;

    __shared__ __half WqS[64][256];
    __shared__ float  AmS[64][64];
    int tid = threadIdx.x;

    const __half* wq = g_wh[0] + (size_t)(h * 64) * DIM + chunk * 256;
#pragma unroll
    for (int it = 0; it < 8; ++it) {
        int idx = tid + it * 256;
        int e = idx >> 5;
        int c8 = (idx & 31) * 8;
        *(uint4*)&WqS[e][c8] = *(const uint4*)(wq + (size_t)e * DIM + c8);
    }
#pragma unroll
    for (int it = 0; it < 4; ++it) {
        int idx = tid + it * 256;
        int e = idx >> 4;
        int j4 = (idx & 15) * 4;
        *(float4*)&AmS[e][j4] =
            *(const float4*)&g_amap[(size_t)bh * 4096 + e * 64 + j4];
    }
    __syncthreads();

    int ty = tid >> 3;
    int tx = tid & 7;
    float acc[8][8];
#pragma unroll
    for (int i = 0; i < 8; ++i)
#pragma unroll
        for (int j = 0; j < 8; ++j) acc[i][j] = 0.0f;

#pragma unroll 4
    for (int e = 0; e < 64; ++e) {
        __half ah[8];
        *(uint4*)ah = *(const uint4*)&WqS[e][ty * 8];
        float bv[8];
        float4 b0 = *(const float4*)&AmS[e][tx * 8];
        float4 b1 = *(const float4*)&AmS[e][tx * 8 + 4];
        bv[0]=b0.x; bv[1]=b0.y; bv[2]=b0.z; bv[3]=b0.w;
        bv[4]=b1.x; bv[5]=b1.y; bv[6]=b1.z; bv[7]=b1.w;
#pragma unroll
        for (int i = 0; i < 8; ++i) {
            float av = __half2float(ah[i]);
#pragma unroll
            for (int j = 0; j < 8; ++j) acc[i][j] = fmaf(av, bv[j], acc[i][j]);
        }
    }

    __half* wp = g_wp + (size_t)b * DIM * DIM;
#pragma unroll
    for (int i = 0; i < 8; ++i) {
        int din = chunk * 256 + ty * 8 + i;
        __half o[8];
#pragma unroll
        for (int j = 0; j < 8; ++j) o[j] = __float2half_rn(acc[i][j]);
        *(uint4*)&wp[(size_t)din * DIM + h * 64 + tx * 8] = *(const uint4*)o;
    }
}

// ---------------- LayerNorm(proj + x) ----------------------------------------
__global__ __launch_bounds__(256) void ln_kernel(
    const float* __restrict__ x, const float* __restrict__ gamma,
    const float* __restrict__ beta, float* __restrict__ out)
{
    int row = blockIdx.x;
    int tid = threadIdx.x;
    const float* pr = g_proj + (size_t)row * DIM;
    const float* xr = x      + (size_t)row * DIM;

    float4 pv = *(const float4*)(pr + tid * 4);
    float4 xv = *(const float4*)(xr + tid * 4);
    float v[4] = { pv.x + xv.x, pv.y + xv.y, pv.z + xv.z, pv.w + xv.w };

    float s = v[0] + v[1] + v[2] + v[3];
    float s2 = v[0]*v[0] + v[1]*v[1] + v[2]*v[2] + v[3]*v[3];

#pragma unroll
    for (int o = 16; o > 0; o >>= 1) {
        s  += __shfl_xor_sync(0xFFFFFFFFu, s,  o);
        s2 += __shfl_xor_sync(0xFFFFFFFFu, s2, o);
    }
    __shared__ float rs[8], rs2[8];
    int wid = tid >> 5, lane = tid & 31;
    if (lane == 0) { rs[wid] = s; rs2[wid] = s2; }
    __syncthreads();
    if (wid == 0) {
        float a  = (lane < 8) ? rs[lane]  : 0.0f;
        float a2 = (lane < 8) ? rs2[lane] : 0.0f;
#pragma unroll
        for (int o = 4; o > 0; o >>= 1) {
            a  += __shfl_xor_sync(0xFFFFFFFFu, a,  o);
            a2 += __shfl_xor_sync(0xFFFFFFFFu, a2, o);
        }
        if (lane == 0) { rs[0] = a; rs2[0] = a2; }
    }
    __syncthreads();
    float mu  = rs[0]  * (1.0f / DIM);
    float var = rs2[0] * (1.0f / DIM) - mu * mu;
    float rstd = rsqrtf(var + LNEPS);

    const float* gp = gamma + tid * 4;
    const float* bp = beta  + tid * 4;
    float4 o4;
    o4.x = (v[0] - mu) * rstd * gp[0] + bp[0];
    o4.y = (v[1] - mu) * rstd * gp[1] + bp[1];
    o4.z = (v[2] - mu) * rstd * gp[2] + bp[2];
    o4.w = (v[3] - mu) * rstd * gp[3] + bp[3];
    *(float4*)(out + (size_t)row * DIM + tid * 4) = o4;
}

// ---------------- host launcher ----------------------------------------------
extern "C" void kernel_launch(void* const* d_in, const int* in_sizes, int n_in,
                              void* d_out, int out_size)
{
    (void)in_sizes; (void)n_in; (void)out_size;
    const float* x     = (const float*)d_in[0];
    const float* Wq    = (const float*)d_in[1];
    const float* Wk    = (const float*)d_in[2];
    const float* Wv    = (const float*)d_in[3];
    const float* Wo    = (const float*)d_in[4];
    const float* bo    = (const float*)d_in[5];
    const float* alpha = (const float*)d_in[6];
    const float* temp  = (const float*)d_in[7];
    const float* gamma = (const float*)d_in[8];
    const float* beta  = (const float*)d_in[9];
    float* out = (float*)d_out;

    __half *xh, *xt, *wh, *gm, *hk, *wpp, *w2p;
    float *projp;
    cudaGetSymbolAddress((void**)&xh,    g_xh);
    cudaGetSymbolAddress((void**)&xt,    g_xt);
    cudaGetSymbolAddress((void**)&wh,    g_wh);
    cudaGetSymbolAddress((void**)&gm,    g_gm);
    cudaGetSymbolAddress((void**)&hk,    g_hk);
    cudaGetSymbolAddress((void**)&wpp,   g_wp);
    cudaGetSymbolAddress((void**)&w2p,   g_w2);
    cudaGetSymbolAddress((void**)&projp, g_proj);

    const int SMEM_GEMM = 98304;
    cudaFuncSetAttribute(gemm_f16,
                         cudaFuncAttributeMaxDynamicSharedMemorySize, SMEM_GEMM);

    const size_t WSZ = (size_t)DIM * DIM;
    convh_kernel<<<MTOT*DIM/2048, 256>>>(x,  xh);
    convh_kernel<<<DIM*DIM/2048, 256>>>(Wq, wh + 0*WSZ);
    convh_kernel<<<DIM*DIM/2048, 256>>>(Wk, wh + 1*WSZ);
    convh_kernel<<<DIM*DIM/2048, 256>>>(Wv, wh + 2*WSZ);
    convh_kernel<<<DIM*DIM/2048, 256>>>(Wo, wh + 3*WSZ);

    // X^T per batch, then G_b = X_b^T X_b  (NT on xT rows)
    transpose_kernel<<<dim3(DIM/64, SEQ/64, BATCH), 256>>>();
    gemm_f16<<<dim3(DIM/128, DIM/128, BATCH), 256, SMEM_GEMM>>>(
        xt, xt, nullptr, nullptr, gm, DIM, SEQ/64, SEQ, SEQ,
        (size_t)DIM*SEQ, (size_t)DIM*SEQ, WSZ);

    // Hk_b = Wk @ G_b  (G symmetric -> NT works)
    gemm_f16<<<dim3(DIM/128, DIM/128, BATCH), 256, SMEM_GEMM>>>(
        wh + 1*WSZ, gm, nullptr, nullptr, hk, DIM, DIM/64, DIM, DIM,
        0, WSZ, WSZ);

    // per-head Gram blocks + solve + softmax
    kkt2_kernel<<<BH, 256>>>();
    solve_kernel<<<BH, 256>>>(alpha, temp);

    // fold amap into weights:  W'_b = fold(Wq, amap),  W2^T_b = Wo @ W'_b
    fold1_kernel<<<dim3(BH, DIM/256), 256>>>();
    gemm_f16<<<dim3(DIM/128, DIM/128, BATCH), 256, SMEM_GEMM>>>(
        wh + 3*WSZ, wpp, nullptr, nullptr, w2p, DIM, DIM/64, DIM, DIM,
        0, WSZ, WSZ);

    // proj[b] = x[b] @ W2_b + bo
    gemm_f16<<<dim3(DIM/128, SEQ/128, BATCH), 256, SMEM_GEMM>>>(
        xh, w2p, bo, projp, nullptr, DIM, DIM/64, DIM, DIM,
        (size_t)SEQ*DIM, WSZ, (size_t)SEQ*DIM);

    ln_kernel<<<MTOT, 256>>>(x, gamma, beta, out);
}

// round 10
// speedup vs baseline: 9.9816x; 1.0133x over previous
#include <cuda_runtime.h>
#include <cuda_fp16.h>
#include <cstdint>
#include <math.h>

#define BATCH 4
#define SEQ   4096
#define DIM   1024
#define NH    16
#define HD    64
#define BH    (BATCH*NH)          // 64
#define MTOT  (BATCH*SEQ)         // 16384
#define LNEPS 1e-5f

// ---------------- scratch (static device globals; no allocation) -------------
__device__ __align__(16) __half g_xh [(size_t)MTOT*DIM];
__device__ __align__(16) __half g_xt [(size_t)BATCH*DIM*SEQ];   // X^T per batch
__device__ __align__(16) __half g_wh [4][(size_t)DIM*DIM];
__device__ __align__(16) __half g_gm [(size_t)BATCH*DIM*DIM];   // G = X^T X
__device__ __align__(16) __half g_hk [(size_t)BATCH*DIM*DIM];   // Hk = Wk G
__device__ __align__(16) __half g_wp [(size_t)BATCH*DIM*DIM];   // folded W'
__device__ __align__(16) __half g_w2 [(size_t)BATCH*DIM*DIM];   // folded W2^T
__device__ __align__(16) __half g_projh[(size_t)MTOT*DIM];
__device__ float g_part[BH*2*HD*HD];
__device__ float g_amap[BH*HD*HD];

// ---------------- async copy / mma helpers ------------------------------------
#define CP16(dst_u32, src_ptr) \
    asm volatile("cp.async.cg.shared.global [%0], [%1], 16;\n" \
                 :: "r"(dst_u32), "l"(src_ptr))
#define CPCOMMIT() asm volatile("cp.async.commit_group;\n" ::: "memory")
#define CPWAIT1()  asm volatile("cp.async.wait_group 1;\n" ::: "memory")
#define CPWAIT0()  asm volatile("cp.async.wait_group 0;\n" ::: "memory")

__device__ __forceinline__ void ldsm4(unsigned r[4], unsigned addr) {
    asm volatile("ldmatrix.sync.aligned.m8n8.x4.shared.b16 {%0,%1,%2,%3}, [%4];"
                 : "=r"(r[0]), "=r"(r[1]), "=r"(r[2]), "=r"(r[3]) : "r"(addr));
}

__device__ __forceinline__ void mma16816(float* c, const unsigned a[4],
                                         unsigned b0, unsigned b1) {
    asm volatile(
        "mma.sync.aligned.m16n8k16.row.col.f32.f16.f16.f32 "
        "{%0,%1,%2,%3}, {%4,%5,%6,%7}, {%8,%9}, {%0,%1,%2,%3};"
        : "+f"(c[0]), "+f"(c[1]), "+f"(c[2]), "+f"(c[3])
        : "r"(a[0]), "r"(a[1]), "r"(a[2]), "r"(a[3]), "r"(b0), "r"(b1));
}

// ---------------- f32 -> fp16 (plain, for weights) ----------------------------
__global__ __launch_bounds__(256) void convh_kernel(
    const float* __restrict__ src, __half* __restrict__ dst)
{
    size_t base = (size_t)(blockIdx.x * blockDim.x + threadIdx.x) * 8;
    float4 v0 = *(const float4*)(src + base);
    float4 v1 = *(const float4*)(src + base + 4);
    __half o[8];
    o[0] = __float2half_rn(v0.x); o[1] = __float2half_rn(v0.y);
    o[2] = __float2half_rn(v0.z); o[3] = __float2half_rn(v0.w);
    o[4] = __float2half_rn(v1.x); o[5] = __float2half_rn(v1.y);
    o[6] = __float2half_rn(v1.z); o[7] = __float2half_rn(v1.w);
    *(uint4*)(dst + base) = *(const uint4*)o;
}

// ---------- fused x(f32) -> xh(fp16 row-major) + xt(fp16 transposed) ----------
// grid: (DIM/64, SEQ/64, BATCH), block 256. 64(n) x 64(i) tile.
__global__ __launch_bounds__(256) void convx_kernel(const float* __restrict__ x)
{
    int ib = blockIdx.x, nb = blockIdx.y, b = blockIdx.z;
    __shared__ __half Ts[64][64];
    int tid = threadIdx.x;
    const float* src = x + ((size_t)(b * SEQ + nb * 64)) * DIM + ib * 64;
    __half* xh = g_xh + ((size_t)(b * SEQ + nb * 64)) * DIM + ib * 64;
#pragma unroll
    for (int it = 0; it < 2; ++it) {
        int idx = tid + it * 256;
        int r  = idx >> 3;                    // n-local 0..63
        int cc = idx & 7;                     // i-chunk 0..7 (8 fp16)
        float4 v0 = *(const float4*)(src + (size_t)r * DIM + cc * 8);
        float4 v1 = *(const float4*)(src + (size_t)r * DIM + cc * 8 + 4);
        __half o[8];
        o[0] = __float2half_rn(v0.x); o[1] = __float2half_rn(v0.y);
        o[2] = __float2half_rn(v0.z); o[3] = __float2half_rn(v0.w);
        o[4] = __float2half_rn(v1.x); o[5] = __float2half_rn(v1.y);
        o[6] = __float2half_rn(v1.z); o[7] = __float2half_rn(v1.w);
        *(uint4*)(xh + (size_t)r * DIM + cc * 8) = *(const uint4*)o;
        int ccs = cc ^ ((r >> 3) & 7);        // XOR swizzle
        *(uint4*)&Ts[r][ccs * 8] = *(const uint4*)o;
    }
    __syncthreads();
    __half* dst = g_xt + ((size_t)b * DIM + ib * 64) * SEQ + nb * 64;
#pragma unroll
    for (int it = 0; it < 2; ++it) {
        int idx = tid + it * 256;
        int ng = idx & 7;                     // n-chunk
        int i  = idx >> 3;                    // i-local 0..63
        __half o[8];
#pragma unroll
        for (int k = 0; k < 8; ++k) {
            int n = ng * 8 + k;
            int cc = (i >> 3) ^ ((n >> 3) & 7);
            o[k] = Ts[n][cc * 8 + (i & 7)];
        }
        *(uint4*)(dst + (size_t)i * SEQ + ng * 8) = *(const uint4*)o;
    }
}

// ---------------- fp16 GEMM: C[m,n]=sum_k A[m,k]*B[n,k] ----------------------
// 128x128 tile, BK=64, 256 thr = 8 warps (2x4), warp 64x32, 3-stage cp.async.
// sym=1: C symmetric — only blocks bn<=bm computed; mirror tile stored via smem.
__global__ __launch_bounds__(256) void gemm_f16(
    const __half* __restrict__ A0, const __half* __restrict__ B0,
    const float* __restrict__ bias, __half* __restrict__ Ch0, int N,
    int nck, int lda, int ldb, size_t strA, size_t strB, size_t strC, int sym)
{
    extern __shared__ __half sm[];
    const unsigned smem_base = (unsigned)__cvta_generic_to_shared(sm);
    const int tid  = threadIdx.x;
    const int lane = tid & 31;
    const int warp = tid >> 5;
    const int wm = (warp >> 2) * 64;
    const int wn = (warp & 3) * 32;
    const int bm = blockIdx.y * 128;
    const int bn = blockIdx.x * 128;
    const int z  = blockIdx.z;
    const int g4 = lane >> 2;
    const int tg = lane & 3;

    if (sym && bn > bm) return;

    const __half* A2 = A0 + (size_t)z * strA;
    const __half* B2 = B0 + (size_t)z * strB;
    __half* Ch = Ch0 + (size_t)z * strC;

    float acc[4][4][4];
#pragma unroll
    for (int t = 0; t < 4; ++t)
#pragma unroll
        for (int u = 0; u < 4; ++u)
#pragma unroll
            for (int r = 0; r < 4; ++r) acc[t][u][r] = 0.0f;

    auto load_chunk = [&](int kc, int bf) {
#pragma unroll
        for (int it = 0; it < 4; ++it) {
            int idx = tid + it * 256;
            int row = idx >> 3;
            int c8  = idx & 7;
            const __half* sa = A2 + (size_t)(bm + row) * lda + kc * 64 + c8 * 8;
            const __half* sb = B2 + (size_t)(bn + row) * ldb + kc * 64 + c8 * 8;
            unsigned sw = (unsigned)((c8 ^ (row & 7)) * 16);
            unsigned da = smem_base + bf * 16384 + row * 128 + sw;
            unsigned db = smem_base + 49152 + bf * 16384 + row * 128 + sw;
            CP16(da, sa);
            CP16(db, sb);
        }
    };

    const int khalf = lane >> 4;
    int rowA[4], rowB[2];
#pragma unroll
    for (int t = 0; t < 4; ++t) rowA[t] = wm + t * 16 + (lane & 15);
#pragma unroll
    for (int p = 0; p < 2; ++p) rowB[p] = wn + p * 16 + (lane & 15);

    load_chunk(0, 0); CPCOMMIT();
    load_chunk(1, 1); CPCOMMIT();

    for (int kc = 0; kc < nck; ++kc) {
        CPWAIT1();
        __syncthreads();
        if (kc + 2 < nck) { load_chunk(kc + 2, (kc + 2) % 3); CPCOMMIT(); }

        const int bf = kc % 3;
        const unsigned abase = smem_base + bf * 16384;
        const unsigned bbase = smem_base + 49152 + bf * 16384;

#pragma unroll
        for (int s = 0; s < 4; ++s) {
            const int ch = s * 2 + khalf;
            unsigned a[4][4], b[2][4];
#pragma unroll
            for (int t = 0; t < 4; ++t) {
                unsigned addr = abase + rowA[t] * 128 +
                                (unsigned)((ch ^ (rowA[t] & 7)) * 16);
                ldsm4(a[t], addr);
            }
#pragma unroll
            for (int p = 0; p < 2; ++p) {
                unsigned addr = bbase + rowB[p] * 128 +
                                (unsigned)((ch ^ (rowB[p] & 7)) * 16);
                ldsm4(b[p], addr);
            }
#pragma unroll
            for (int t = 0; t < 4; ++t)
#pragma unroll
                for (int u = 0; u < 4; ++u) {
                    int p = u >> 1, h = u & 1;
                    mma16816(acc[t][u], a[t], b[p][h], b[p][2 + h]);
                }
        }
    }

    // normal store (fp16, optional bias)
#pragma unroll
    for (int t = 0; t < 4; ++t) {
        int r = bm + wm + t * 16 + g4;
#pragma unroll
        for (int u = 0; u < 4; ++u) {
            int c = bn + wn + u * 8 + tg * 2;
            float b0 = 0.0f, b1 = 0.0f;
            if (bias) { b0 = bias[c]; b1 = bias[c + 1]; }
            *(__half2*)&Ch[(size_t)r * N + c] =
                __floats2half2_rn(acc[t][u][0] + b0, acc[t][u][1] + b1);
            *(__half2*)&Ch[(size_t)(r + 8) * N + c] =
                __floats2half2_rn(acc[t][u][2] + b0, acc[t][u][3] + b1);
        }
    }

    // mirror store for symmetric output (bn < bm): C[bn+j][bm+i] = T[i][j]
    if (sym && bn < bm) {
        CPWAIT0();
        __syncthreads();
        __half (*S)[130] = reinterpret_cast<__half (*)[130]>(sm);
#pragma unroll
        for (int t = 0; t < 4; ++t) {
            int r0 = wm + t * 16 + g4;
#pragma unroll
            for (int u = 0; u < 4; ++u) {
                int c0 = wn + u * 8 + tg * 2;
                S[r0][c0]     = __float2half_rn(acc[t][u][0]);
                S[r0][c0 + 1] = __float2half_rn(acc[t][u][1]);
                S[r0 + 8][c0]     = __float2half_rn(acc[t][u][2]);
                S[r0 + 8][c0 + 1] = __float2half_rn(acc[t][u][3]);
            }
        }
        __syncthreads();
#pragma unroll
        for (int it = 0; it < 8; ++it) {
            int idx = tid + it * 256;      // 2048 uint4 = 128 rows x 16 chunks
            int j  = idx >> 4;             // mirror row (orig col)
            int i0 = (idx & 15) * 8;       // mirror col base (orig row)
            __half o[8];
#pragma unroll
            for (int k = 0; k < 8; ++k) o[k] = S[i0 + k][j];
            *(uint4*)&Ch[(size_t)(bn + j) * N + bm + i0] = *(const uint4*)o;
        }
    }
}

// -------- kkt2: kk/kv from Hk_h · [Wk_h | Wv_h]^T (per-head diag blocks) ------
__global__ __launch_bounds__(256) void kkt2_kernel()
{
    int bh = blockIdx.x;
    int b = bh >> 4, h = bh & 15;
    const __half* hk = g_hk    + (size_t)b * DIM * DIM + (size_t)(h * HD) * DIM;
    const __half* wk = g_wh[1] + (size_t)(h * HD) * DIM;
    const __half* wv = g_wh[2] + (size_t)(h * HD) * DIM;

    __shared__ __half Hs[64][72];
    __shared__ __half Ts[128][72];
    const unsigned hb = (unsigned)__cvta_generic_to_shared(&Hs[0][0]);
    const unsigned tb = (unsigned)__cvta_generic_to_shared(&Ts[0][0]);
    const int tid = threadIdx.x;
    const int lane = tid & 31;
    const int warp = tid >> 5;
    const int wm = (warp >> 2) * 32;
    const int wn = (warp & 3) * 32;
    const int g4 = lane >> 2;
    const int tg = lane & 3;

    float acc[2][4][4];
#pragma unroll
    for (int mt = 0; mt < 2; ++mt)
#pragma unroll
        for (int u = 0; u < 4; ++u)
#pragma unroll
            for (int r = 0; r < 4; ++r) acc[mt][u][r] = 0.0f;

    const int khalf = lane >> 4;
    int rowA[2], rowB[2];
#pragma unroll
    for (int mt = 0; mt < 2; ++mt) rowA[mt] = wm + mt * 16 + (lane & 15);
#pragma unroll
    for (int p = 0; p < 2; ++p) rowB[p] = wn + p * 16 + (lane & 15);

    for (int i0 = 0; i0 < DIM; i0 += 64) {
        __syncthreads();
#pragma unroll
        for (int it = 0; it < 2; ++it) {
            int idx = tid + it * 256;
            int r = idx >> 3, c8 = (idx & 7) * 8;
            *(uint4*)&Hs[r][c8] = *(const uint4*)(hk + (size_t)r * DIM + i0 + c8);
        }
#pragma unroll
        for (int it = 0; it < 4; ++it) {
            int idx = tid + it * 256;
            int r = idx >> 3, c8 = (idx & 7) * 8;
            const __half* src = (r < 64 ? wk + (size_t)r * DIM
                                        : wv + (size_t)(r - 64) * DIM) + i0 + c8;
            *(uint4*)&Ts[r][c8] = *(const uint4*)src;
        }
        __syncthreads();

#pragma unroll
        for (int ks = 0; ks < 4; ++ks) {
            unsigned a[2][4], bfr[2][4];
            unsigned colb = (unsigned)(ks * 32 + khalf * 16);
#pragma unroll
            for (int mt = 0; mt < 2; ++mt)
                ldsm4(a[mt], hb + rowA[mt] * 144 + colb);
#pragma unroll
            for (int p = 0; p < 2; ++p)
                ldsm4(bfr[p], tb + rowB[p] * 144 + colb);
#pragma unroll
            for (int mt = 0; mt < 2; ++mt)
#pragma unroll
                for (int u = 0; u < 4; ++u) {
                    int p = u >> 1, hh = u & 1;
                    mma16816(acc[mt][u], a[mt], bfr[p][hh], bfr[p][2 + hh]);
                }
        }
    }

    float* pkk = g_part + (size_t)bh * 2 * 4096;
    float* pkv = pkk + 4096;
#pragma unroll
    for (int mt = 0; mt < 2; ++mt) {
        int d = wm + mt * 16 + g4;
#pragma unroll
        for (int u = 0; u < 4; ++u) {
            int j = wn + u * 8 + tg * 2;
            float* dst = (j < 64) ? (pkk + d * 64 + j) : (pkv + d * 64 + (j - 64));
            *(float2*)dst = make_float2(acc[mt][u][0], acc[mt][u][1]);
            float* dst2 = (j < 64) ? (pkk + (d + 8) * 64 + j)
                                   : (pkv + (d + 8) * 64 + (j - 64));
            *(float2*)dst2 = make_float2(acc[mt][u][2], acc[mt][u][3]);
        }
    }
}

// ------- solve (kk+aI) X = ktv, column softmax -> g_amap ----------------------
__global__ __launch_bounds__(256) void solve_kernel(
    const float* __restrict__ alpha_p, const float* __restrict__ temp_p)
{
    int bh = blockIdx.x;
    __shared__ float A[64][65];
    __shared__ float X[64][65];
    int tid = threadIdx.x;

    const float* p = g_part + (size_t)bh * 2 * 4096;
    for (int i = tid; i < 4096; i += 256) {
        A[i >> 6][i & 63] = p[i];
        X[i >> 6][i & 63] = p[4096 + i];
    }
    __syncthreads();
    if (tid < 64) A[tid][tid] += alpha_p[0];

    int r  = tid >> 2;
    int c0 = (tid & 3) * 16;
    for (int pp = 0; pp < 64; ++pp) {
        __syncthreads();
        float pinv = 1.0f / A[pp][pp];
        __syncthreads();
        if (tid < 64)      A[pp][tid]      *= pinv;
        else if (tid < 128) X[pp][tid - 64] *= pinv;
        __syncthreads();
        float f = (r != pp) ? A[r][pp] : 0.0f;
        __syncthreads();
        if (r != pp) {
#pragma unroll
            for (int c = 0; c < 16; ++c) {
                A[r][c0 + c] = fmaf(-f, A[pp][c0 + c], A[r][c0 + c]);
                X[r][c0 + c] = fmaf(-f, X[pp][c0 + c], X[r][c0 + c]);
            }
        }
    }
    __syncthreads();

    if (tid < 64) {
        float invt = 1.0f / temp_p[0];
        float mx = -1e30f;
        for (int d = 0; d < 64; ++d) mx = fmaxf(mx, X[d][tid] * invt);
        float s = 0.0f;
        for (int d = 0; d < 64; ++d) s += expf(X[d][tid] * invt - mx);
        float inv_s = 1.0f / s;
        for (int d = 0; d < 64; ++d)
            g_amap[(size_t)bh * 4096 + d * 64 + tid] =
                expf(X[d][tid] * invt - mx) * inv_s;
    }
}

// ---------- fold1: W'_b[din, h*64+j] = sum_e Wq[h*64+e, din] * amap[e, j] -----
__global__ __launch_bounds__(256) void fold1_kernel()
{
    int bh = blockIdx.x;
    int chunk = blockIdx.y;
    int b = bh >> 4, h = bh & 15;

    __shared__ __half WqS[64][256];
    __shared__ float  AmS[64][64];
    int tid = threadIdx.x;

    const __half* wq = g_wh[0] + (size_t)(h * 64) * DIM + chunk * 256;
#pragma unroll
    for (int it = 0; it < 8; ++it) {
        int idx = tid + it * 256;
        int e = idx >> 5;
        int c8 = (idx & 31) * 8;
        *(uint4*)&WqS[e][c8] = *(const uint4*)(wq + (size_t)e * DIM + c8);
    }
#pragma unroll
    for (int it = 0; it < 4; ++it) {
        int idx = tid + it * 256;
        int e = idx >> 4;
        int j4 = (idx & 15) * 4;
        *(float4*)&AmS[e][j4] =
            *(const float4*)&g_amap[(size_t)bh * 4096 + e * 64 + j4];
    }
    __syncthreads();

    int ty = tid >> 3;
    int tx = tid & 7;
    float acc[8][8];
#pragma unroll
    for (int i = 0; i < 8; ++i)
#pragma unroll
        for (int j = 0; j < 8; ++j) acc[i][j] = 0.0f;

#pragma unroll 4
    for (int e = 0; e < 64; ++e) {
        __half ah[8];
        *(uint4*)ah = *(const uint4*)&WqS[e][ty * 8];
        float bv[8];
        float4 b0 = *(const float4*)&AmS[e][tx * 8];
        float4 b1 = *(const float4*)&AmS[e][tx * 8 + 4];
        bv[0]=b0.x; bv[1]=b0.y; bv[2]=b0.z; bv[3]=b0.w;
        bv[4]=b1.x; bv[5]=b1.y; bv[6]=b1.z; bv[7]=b1.w;
#pragma unroll
        for (int i = 0; i < 8; ++i) {
            float av = __half2float(ah[i]);
#pragma unroll
            for (int j = 0; j < 8; ++j) acc[i][j] = fmaf(av, bv[j], acc[i][j]);
        }
    }

    __half* wp = g_wp + (size_t)b * DIM * DIM;
#pragma unroll
    for (int i = 0; i < 8; ++i) {
        int din = chunk * 256 + ty * 8 + i;
        __half o[8];
#pragma unroll
        for (int j = 0; j < 8; ++j) o[j] = __float2half_rn(acc[i][j]);
        *(uint4*)&wp[(size_t)din * DIM + h * 64 + tx * 8] = *(const uint4*)o;
    }
}

// ---------------- LayerNorm(proj(fp16) + x(f32)) ------------------------------
__global__ __launch_bounds__(256) void ln_kernel(
    const float* __restrict__ x, const float* __restrict__ gamma,
    const float* __restrict__ beta, float* __restrict__ out)
{
    int row = blockIdx.x;
    int tid = threadIdx.x;
    const __half* pr = g_projh + (size_t)row * DIM;
    const float*  xr = x       + (size_t)row * DIM;

    uint2 pu = *(const uint2*)(pr + tid * 4);
    __half2 p0 = *reinterpret_cast<__half2*>(&pu.x);
    __half2 p1 = *reinterpret_cast<__half2*>(&pu.y);
    float4 xv = *(const float4*)(xr + tid * 4);
    float v[4] = { __low2float(p0) + xv.x, __high2float(p0) + xv.y,
                   __low2float(p1) + xv.z, __high2float(p1) + xv.w };

    float s = v[0] + v[1] + v[2] + v[3];
    float s2 = v[0]*v[0] + v[1]*v[1] + v[2]*v[2] + v[3]*v[3];

#pragma unroll
    for (int o = 16; o > 0; o >>= 1) {
        s  += __shfl_xor_sync(0xFFFFFFFFu, s,  o);
        s2 += __shfl_xor_sync(0xFFFFFFFFu, s2, o);
    }
    __shared__ float rs[8], rs2[8];
    int wid = tid >> 5, lane = tid & 31;
    if (lane == 0) { rs[wid] = s; rs2[wid] = s2; }
    __syncthreads();
    if (wid == 0) {
        float a  = (lane < 8) ? rs[lane]  : 0.0f;
        float a2 = (lane < 8) ? rs2[lane] : 0.0f;
#pragma unroll
        for (int o = 4; o > 0; o >>= 1) {
            a  += __shfl_xor_sync(0xFFFFFFFFu, a,  o);
            a2 += __shfl_xor_sync(0xFFFFFFFFu, a2, o);
        }
        if (lane == 0) { rs[0] = a; rs2[0] = a2; }
    }
    __syncthreads();
    float mu  = rs[0]  * (1.0f / DIM);
    float var = rs2[0] * (1.0f / DIM) - mu * mu;
    float rstd = rsqrtf(var + LNEPS);

    const float* gp = gamma + tid * 4;
    const float* bp = beta  + tid * 4;
    float4 o4;
    o4.x = (v[0] - mu) * rstd * gp[0] + bp[0];
    o4.y = (v[1] - mu) * rstd * gp[1] + bp[1];
    o4.z = (v[2] - mu) * rstd * gp[2] + bp[2];
    o4.w = (v[3] - mu) * rstd * gp[3] + bp[3];
    *(float4*)(out + (size_t)row * DIM + tid * 4) = o4;
}

// ---------------- host launcher ----------------------------------------------
extern "C" void kernel_launch(void* const* d_in, const int* in_sizes, int n_in,
                              void* d_out, int out_size)
{
    (void)in_sizes; (void)n_in; (void)out_size;
    const float* x     = (const float*)d_in[0];
    const float* Wq    = (const float*)d_in[1];
    const float* Wk    = (const float*)d_in[2];
    const float* Wv    = (const float*)d_in[3];
    const float* Wo    = (const float*)d_in[4];
    const float* bo    = (const float*)d_in[5];
    const float* alpha = (const float*)d_in[6];
    const float* temp  = (const float*)d_in[7];
    const float* gamma = (const float*)d_in[8];
    const float* beta  = (const float*)d_in[9];
    float* out = (float*)d_out;

    __half *xh, *xt, *wh, *gm, *hk, *wpp, *w2p, *projh;
    cudaGetSymbolAddress((void**)&xh,    g_xh);
    cudaGetSymbolAddress((void**)&xt,    g_xt);
    cudaGetSymbolAddress((void**)&wh,    g_wh);
    cudaGetSymbolAddress((void**)&gm,    g_gm);
    cudaGetSymbolAddress((void**)&hk,    g_hk);
    cudaGetSymbolAddress((void**)&wpp,   g_wp);
    cudaGetSymbolAddress((void**)&w2p,   g_w2);
    cudaGetSymbolAddress((void**)&projh, g_projh);

    const int SMEM_GEMM = 98304;
    cudaFuncSetAttribute(gemm_f16,
                         cudaFuncAttributeMaxDynamicSharedMemorySize, SMEM_GEMM);

    const size_t WSZ = (size_t)DIM * DIM;
    convh_kernel<<<DIM*DIM/2048, 256>>>(Wq, wh + 0*WSZ);
    convh_kernel<<<DIM*DIM/2048, 256>>>(Wk, wh + 1*WSZ);
    convh_kernel<<<DIM*DIM/2048, 256>>>(Wv, wh + 2*WSZ);
    convh_kernel<<<DIM*DIM/2048, 256>>>(Wo, wh + 3*WSZ);

    // fused x conversion + transpose
    convx_kernel<<<dim3(DIM/64, SEQ/64, BATCH), 256>>>(x);

    // G_b = X_b^T X_b (symmetric: lower-triangle blocks + mirror)
    gemm_f16<<<dim3(DIM/128, DIM/128, BATCH), 256, SMEM_GEMM>>>(
        xt, xt, nullptr, gm, DIM, SEQ/64, SEQ, SEQ,
        (size_t)DIM*SEQ, (size_t)DIM*SEQ, WSZ, 1);

    // Hk_b = Wk @ G_b  (G symmetric -> NT works)
    gemm_f16<<<dim3(DIM/128, DIM/128, BATCH), 256, SMEM_GEMM>>>(
        wh + 1*WSZ, gm, nullptr, hk, DIM, DIM/64, DIM, DIM, 0, WSZ, WSZ, 0);

    // per-head Gram blocks + solve + softmax
    kkt2_kernel<<<BH, 256>>>();
    solve_kernel<<<BH, 256>>>(alpha, temp);

    // fold amap into weights
    fold1_kernel<<<dim3(BH, DIM/256), 256>>>();
    gemm_f16<<<dim3(DIM/128, DIM/128, BATCH), 256, SMEM_GEMM>>>(
        wh + 3*WSZ, wpp, nullptr, w2p, DIM, DIM/64, DIM, DIM, 0, WSZ, WSZ, 0);

    // proj[b] = x[b] @ W2_b + bo  (fp16 out)
    gemm_f16<<<dim3(DIM/128, SEQ/128, BATCH), 256, SMEM_GEMM>>>(
        xh, w2p, bo, projh, DIM, DIM/64, DIM, DIM,
        (size_t)SEQ*DIM, WSZ, (size_t)SEQ*DIM, 0);

    ln_kernel<<<MTOT, 256>>>(x, gamma, beta, out);
}

// round 11
// speedup vs baseline: 11.3597x; 1.1381x over previous
#include <cuda_runtime.h>
#include <cuda_fp16.h>
#include <cstdint>
#include <math.h>

#define BATCH 4
#define SEQ   4096
#define DIM   1024
#define NH    16
#define HD    64
#define BH    (BATCH*NH)          // 64
#define MTOT  (BATCH*SEQ)         // 16384
#define LNEPS 1e-5f
#define KS4   4                   // kkt2 i-splits

// ---------------- scratch (static device globals; no allocation) -------------
__device__ __align__(16) __half g_xh [(size_t)MTOT*DIM];
__device__ __align__(16) __half g_xt [(size_t)BATCH*DIM*SEQ];   // X^T per batch
__device__ __align__(16) __half g_wh [4][(size_t)DIM*DIM];
__device__ __align__(16) float  g_gp [(size_t)BATCH*2*DIM*DIM]; // G split-K partials
__device__ __align__(16) __half g_gm [(size_t)BATCH*DIM*DIM];   // G = X^T X
__device__ __align__(16) __half g_hk [(size_t)BATCH*DIM*DIM];   // Hk = Wk G
__device__ __align__(16) __half g_wp [(size_t)BATCH*DIM*DIM];   // folded W'
__device__ __align__(16) __half g_w2 [(size_t)BATCH*DIM*DIM];   // folded W2^T
__device__ __align__(16) __half g_projh[(size_t)MTOT*DIM];
__device__ float g_part[KS4*BH*2*HD*HD];
__device__ float g_amap[BH*HD*HD];

// ---------------- async copy / mma helpers ------------------------------------
#define CP16(dst_u32, src_ptr) \
    asm volatile("cp.async.cg.shared.global [%0], [%1], 16;\n" \
                 :: "r"(dst_u32), "l"(src_ptr))
#define CPCOMMIT() asm volatile("cp.async.commit_group;\n" ::: "memory")
#define CPWAIT1()  asm volatile("cp.async.wait_group 1;\n" ::: "memory")

__device__ __forceinline__ void ldsm4(unsigned r[4], unsigned addr) {
    asm volatile("ldmatrix.sync.aligned.m8n8.x4.shared.b16 {%0,%1,%2,%3}, [%4];"
                 : "=r"(r[0]), "=r"(r[1]), "=r"(r[2]), "=r"(r[3]) : "r"(addr));
}

__device__ __forceinline__ void mma16816(float* c, const unsigned a[4],
                                         unsigned b0, unsigned b1) {
    asm volatile(
        "mma.sync.aligned.m16n8k16.row.col.f32.f16.f16.f32 "
        "{%0,%1,%2,%3}, {%4,%5,%6,%7}, {%8,%9}, {%0,%1,%2,%3};"
        : "+f"(c[0]), "+f"(c[1]), "+f"(c[2]), "+f"(c[3])
        : "r"(a[0]), "r"(a[1]), "r"(a[2]), "r"(a[3]), "r"(b0), "r"(b1));
}

// ---------------- f32 -> fp16 (plain, for weights) ----------------------------
__global__ __launch_bounds__(256) void convh_kernel(
    const float* __restrict__ src, __half* __restrict__ dst)
{
    size_t base = (size_t)(blockIdx.x * blockDim.x + threadIdx.x) * 8;
    float4 v0 = *(const float4*)(src + base);
    float4 v1 = *(const float4*)(src + base + 4);
    __half o[8];
    o[0] = __float2half_rn(v0.x); o[1] = __float2half_rn(v0.y);
    o[2] = __float2half_rn(v0.z); o[3] = __float2half_rn(v0.w);
    o[4] = __float2half_rn(v1.x); o[5] = __float2half_rn(v1.y);
    o[6] = __float2half_rn(v1.z); o[7] = __float2half_rn(v1.w);
    *(uint4*)(dst + base) = *(const uint4*)o;
}

// ---------- fused x(f32) -> xh(fp16 row-major) + xt(fp16 transposed) ----------
__global__ __launch_bounds__(256) void convx_kernel(const float* __restrict__ x)
{
    int ib = blockIdx.x, nb = blockIdx.y, b = blockIdx.z;
    __shared__ __half Ts[64][64];
    int tid = threadIdx.x;
    const float* src = x + ((size_t)(b * SEQ + nb * 64)) * DIM + ib * 64;
    __half* xh = g_xh + ((size_t)(b * SEQ + nb * 64)) * DIM + ib * 64;
#pragma unroll
    for (int it = 0; it < 2; ++it) {
        int idx = tid + it * 256;
        int r  = idx >> 3;
        int cc = idx & 7;
        float4 v0 = *(const float4*)(src + (size_t)r * DIM + cc * 8);
        float4 v1 = *(const float4*)(src + (size_t)r * DIM + cc * 8 + 4);
        __half o[8];
        o[0] = __float2half_rn(v0.x); o[1] = __float2half_rn(v0.y);
        o[2] = __float2half_rn(v0.z); o[3] = __float2half_rn(v0.w);
        o[4] = __float2half_rn(v1.x); o[5] = __float2half_rn(v1.y);
        o[6] = __float2half_rn(v1.z); o[7] = __float2half_rn(v1.w);
        *(uint4*)(xh + (size_t)r * DIM + cc * 8) = *(const uint4*)o;
        int ccs = cc ^ ((r >> 3) & 7);
        *(uint4*)&Ts[r][ccs * 8] = *(const uint4*)o;
    }
    __syncthreads();
    __half* dst = g_xt + ((size_t)b * DIM + ib * 64) * SEQ + nb * 64;
#pragma unroll
    for (int it = 0; it < 2; ++it) {
        int idx = tid + it * 256;
        int ng = idx & 7;
        int i  = idx >> 3;
        __half o[8];
#pragma unroll
        for (int k = 0; k < 8; ++k) {
            int n = ng * 8 + k;
            int cc = (i >> 3) ^ ((n >> 3) & 7);
            o[k] = Ts[n][cc * 8 + (i & 7)];
        }
        *(uint4*)(dst + (size_t)i * SEQ + ng * 8) = *(const uint4*)o;
    }
}

// ------------- G split-K GEMM: triangle tiles, f32 partial out ----------------
// grid (8, 8, BATCH*2): z -> b=z>>1, split s=z&1; kc in [s*32, s*32+32)
__global__ __launch_bounds__(256) void gsplit_kernel()
{
    extern __shared__ __half sm[];
    const unsigned smem_base = (unsigned)__cvta_generic_to_shared(sm);
    const int tid  = threadIdx.x;
    const int lane = tid & 31;
    const int warp = tid >> 5;
    const int wm = (warp >> 2) * 64;
    const int wn = (warp & 3) * 32;
    const int bm = blockIdx.y * 128;
    const int bn = blockIdx.x * 128;
    if (bn > bm) return;
    const int b = blockIdx.z >> 1;
    const int sp = blockIdx.z & 1;
    const int g4 = lane >> 2;
    const int tg = lane & 3;

    const __half* A2 = g_xt + (size_t)b * DIM * SEQ;
    float* Cf = g_gp + (size_t)blockIdx.z * DIM * DIM;

    float acc[4][4][4];
#pragma unroll
    for (int t = 0; t < 4; ++t)
#pragma unroll
        for (int u = 0; u < 4; ++u)
#pragma unroll
            for (int r = 0; r < 4; ++r) acc[t][u][r] = 0.0f;

    auto load_chunk = [&](int kc, int bf) {
#pragma unroll
        for (int it = 0; it < 4; ++it) {
            int idx = tid + it * 256;
            int row = idx >> 3;
            int c8  = idx & 7;
            const __half* sa = A2 + (size_t)(bm + row) * SEQ + kc * 64 + c8 * 8;
            const __half* sb = A2 + (size_t)(bn + row) * SEQ + kc * 64 + c8 * 8;
            unsigned sw = (unsigned)((c8 ^ (row & 7)) * 16);
            CP16(smem_base + bf * 16384 + row * 128 + sw, sa);
            CP16(smem_base + 49152 + bf * 16384 + row * 128 + sw, sb);
        }
    };

    const int khalf = lane >> 4;
    int rowA[4], rowB[2];
#pragma unroll
    for (int t = 0; t < 4; ++t) rowA[t] = wm + t * 16 + (lane & 15);
#pragma unroll
    for (int p = 0; p < 2; ++p) rowB[p] = wn + p * 16 + (lane & 15);

    const int k0 = sp * 32;
    load_chunk(k0 + 0, 0); CPCOMMIT();
    load_chunk(k0 + 1, 1); CPCOMMIT();

    for (int kc = 0; kc < 32; ++kc) {
        CPWAIT1();
        __syncthreads();
        if (kc + 2 < 32) { load_chunk(k0 + kc + 2, (kc + 2) % 3); CPCOMMIT(); }

        const int bf = kc % 3;
        const unsigned abase = smem_base + bf * 16384;
        const unsigned bbase = smem_base + 49152 + bf * 16384;

#pragma unroll
        for (int s = 0; s < 4; ++s) {
            const int ch = s * 2 + khalf;
            unsigned a[4][4], bfr[2][4];
#pragma unroll
            for (int t = 0; t < 4; ++t)
                ldsm4(a[t], abase + rowA[t] * 128 +
                             (unsigned)((ch ^ (rowA[t] & 7)) * 16));
#pragma unroll
            for (int p = 0; p < 2; ++p)
                ldsm4(bfr[p], bbase + rowB[p] * 128 +
                              (unsigned)((ch ^ (rowB[p] & 7)) * 16));
#pragma unroll
            for (int t = 0; t < 4; ++t)
#pragma unroll
                for (int u = 0; u < 4; ++u) {
                    int p = u >> 1, h = u & 1;
                    mma16816(acc[t][u], a[t], bfr[p][h], bfr[p][2 + h]);
                }
        }
    }

#pragma unroll
    for (int t = 0; t < 4; ++t) {
        int r = bm + wm + t * 16 + g4;
#pragma unroll
        for (int u = 0; u < 4; ++u) {
            int c = bn + wn + u * 8 + tg * 2;
            *(float2*)&Cf[(size_t)r * DIM + c] =
                make_float2(acc[t][u][0], acc[t][u][1]);
            *(float2*)&Cf[(size_t)(r + 8) * DIM + c] =
                make_float2(acc[t][u][2], acc[t][u][3]);
        }
    }
}

// ------------- greduce: sum 2 partials -> fp16 G + symmetric mirror -----------
// grid (8, 8, BATCH), block 256; triangle only (bn<=bm)
__global__ __launch_bounds__(256) void greduce_kernel()
{
    int bm = blockIdx.y * 128, bn = blockIdx.x * 128;
    if (bn > bm) return;
    int b = blockIdx.z;
    int tid = threadIdx.x;
    __shared__ __half S[128][132];

    const float* p0 = g_gp + (size_t)(b * 2 + 0) * DIM * DIM;
    const float* p1 = g_gp + (size_t)(b * 2 + 1) * DIM * DIM;
    __half* Gm = g_gm + (size_t)b * DIM * DIM;

#pragma unroll
    for (int it = 0; it < 16; ++it) {
        int idx = tid + it * 256;              // 4096 float4 groups
        int r  = idx >> 5;                     // 32 float4 per 128-col row
        int c4 = (idx & 31) * 4;
        size_t off = (size_t)(bm + r) * DIM + bn + c4;
        float4 a = *(const float4*)(p0 + off);
        float4 c = *(const float4*)(p1 + off);
        __half2 h0 = __floats2half2_rn(a.x + c.x, a.y + c.y);
        __half2 h1 = __floats2half2_rn(a.z + c.z, a.w + c.w);
        __half o[4];
        *(__half2*)&o[0] = h0;
        *(__half2*)&o[2] = h1;
        *(uint2*)&Gm[off] = *(const uint2*)o;
        *(__half2*)&S[r][c4]     = h0;
        *(__half2*)&S[r][c4 + 2] = h1;
    }

    if (bn < bm) {
        __syncthreads();
#pragma unroll
        for (int it = 0; it < 8; ++it) {
            int idx = tid + it * 256;          // 2048 uint4 = 128 x 16 chunks
            int j  = idx >> 4;
            int i0 = (idx & 15) * 8;
            __half o[8];
#pragma unroll
            for (int k = 0; k < 8; ++k) o[k] = S[i0 + k][j];
            *(uint4*)&Gm[(size_t)(bn + j) * DIM + bm + i0] = *(const uint4*)o;
        }
    }
}

// ---------------- fp16 GEMM: C[m,n]=sum_k A[m,k]*B[n,k] (fp16 out) -----------
__global__ __launch_bounds__(256) void gemm_f16(
    const __half* __restrict__ A0, const __half* __restrict__ B0,
    const float* __restrict__ bias, __half* __restrict__ Ch0, int N,
    int nck, int lda, int ldb, size_t strA, size_t strB, size_t strC)
{
    extern __shared__ __half sm[];
    const unsigned smem_base = (unsigned)__cvta_generic_to_shared(sm);
    const int tid  = threadIdx.x;
    const int lane = tid & 31;
    const int warp = tid >> 5;
    const int wm = (warp >> 2) * 64;
    const int wn = (warp & 3) * 32;
    const int bm = blockIdx.y * 128;
    const int bn = blockIdx.x * 128;
    const int z  = blockIdx.z;
    const int g4 = lane >> 2;
    const int tg = lane & 3;

    const __half* A2 = A0 + (size_t)z * strA;
    const __half* B2 = B0 + (size_t)z * strB;
    __half* Ch = Ch0 + (size_t)z * strC;

    float acc[4][4][4];
#pragma unroll
    for (int t = 0; t < 4; ++t)
#pragma unroll
        for (int u = 0; u < 4; ++u)
#pragma unroll
            for (int r = 0; r < 4; ++r) acc[t][u][r] = 0.0f;

    auto load_chunk = [&](int kc, int bf) {
#pragma unroll
        for (int it = 0; it < 4; ++it) {
            int idx = tid + it * 256;
            int row = idx >> 3;
            int c8  = idx & 7;
            const __half* sa = A2 + (size_t)(bm + row) * lda + kc * 64 + c8 * 8;
            const __half* sb = B2 + (size_t)(bn + row) * ldb + kc * 64 + c8 * 8;
            unsigned sw = (unsigned)((c8 ^ (row & 7)) * 16);
            CP16(smem_base + bf * 16384 + row * 128 + sw, sa);
            CP16(smem_base + 49152 + bf * 16384 + row * 128 + sw, sb);
        }
    };

    const int khalf = lane >> 4;
    int rowA[4], rowB[2];
#pragma unroll
    for (int t = 0; t < 4; ++t) rowA[t] = wm + t * 16 + (lane & 15);
#pragma unroll
    for (int p = 0; p < 2; ++p) rowB[p] = wn + p * 16 + (lane & 15);

    load_chunk(0, 0); CPCOMMIT();
    load_chunk(1, 1); CPCOMMIT();

    for (int kc = 0; kc < nck; ++kc) {
        CPWAIT1();
        __syncthreads();
        if (kc + 2 < nck) { load_chunk(kc + 2, (kc + 2) % 3); CPCOMMIT(); }

        const int bf = kc % 3;
        const unsigned abase = smem_base + bf * 16384;
        const unsigned bbase = smem_base + 49152 + bf * 16384;

#pragma unroll
        for (int s = 0; s < 4; ++s) {
            const int ch = s * 2 + khalf;
            unsigned a[4][4], b[2][4];
#pragma unroll
            for (int t = 0; t < 4; ++t)
                ldsm4(a[t], abase + rowA[t] * 128 +
                             (unsigned)((ch ^ (rowA[t] & 7)) * 16));
#pragma unroll
            for (int p = 0; p < 2; ++p)
                ldsm4(b[p], bbase + rowB[p] * 128 +
                             (unsigned)((ch ^ (rowB[p] & 7)) * 16));
#pragma unroll
            for (int t = 0; t < 4; ++t)
#pragma unroll
                for (int u = 0; u < 4; ++u) {
                    int p = u >> 1, h = u & 1;
                    mma16816(acc[t][u], a[t], b[p][h], b[p][2 + h]);
                }
        }
    }

#pragma unroll
    for (int t = 0; t < 4; ++t) {
        int r = bm + wm + t * 16 + g4;
#pragma unroll
        for (int u = 0; u < 4; ++u) {
            int c = bn + wn + u * 8 + tg * 2;
            float b0 = 0.0f, b1 = 0.0f;
            if (bias) { b0 = bias[c]; b1 = bias[c + 1]; }
            *(__half2*)&Ch[(size_t)r * N + c] =
                __floats2half2_rn(acc[t][u][0] + b0, acc[t][u][1] + b1);
            *(__half2*)&Ch[(size_t)(r + 8) * N + c] =
                __floats2half2_rn(acc[t][u][2] + b0, acc[t][u][3] + b1);
        }
    }
}

// -------- kkt2: kk/kv partials from Hk_h · [Wk_h | Wv_h]^T, i-split -----------
// grid (BH, KS4): each block does 256 i-values (4 rounds of 64)
__global__ __launch_bounds__(256) void kkt2_kernel()
{
    int bh = blockIdx.x;
    int sp = blockIdx.y;
    int b = bh >> 4, h = bh & 15;
    const __half* hk = g_hk    + (size_t)b * DIM * DIM + (size_t)(h * HD) * DIM;
    const __half* wk = g_wh[1] + (size_t)(h * HD) * DIM;
    const __half* wv = g_wh[2] + (size_t)(h * HD) * DIM;

    __shared__ __half Hs[64][72];
    __shared__ __half Ts[128][72];
    const unsigned hb = (unsigned)__cvta_generic_to_shared(&Hs[0][0]);
    const unsigned tb = (unsigned)__cvta_generic_to_shared(&Ts[0][0]);
    const int tid = threadIdx.x;
    const int lane = tid & 31;
    const int warp = tid >> 5;
    const int wm = (warp >> 2) * 32;
    const int wn = (warp & 3) * 32;
    const int g4 = lane >> 2;
    const int tg = lane & 3;

    float acc[2][4][4];
#pragma unroll
    for (int mt = 0; mt < 2; ++mt)
#pragma unroll
        for (int u = 0; u < 4; ++u)
#pragma unroll
            for (int r = 0; r < 4; ++r) acc[mt][u][r] = 0.0f;

    const int khalf = lane >> 4;
    int rowA[2], rowB[2];
#pragma unroll
    for (int mt = 0; mt < 2; ++mt) rowA[mt] = wm + mt * 16 + (lane & 15);
#pragma unroll
    for (int p = 0; p < 2; ++p) rowB[p] = wn + p * 16 + (lane & 15);

    for (int i0 = sp * 256; i0 < sp * 256 + 256; i0 += 64) {
        __syncthreads();
#pragma unroll
        for (int it = 0; it < 2; ++it) {
            int idx = tid + it * 256;
            int r = idx >> 3, c8 = (idx & 7) * 8;
            *(uint4*)&Hs[r][c8] = *(const uint4*)(hk + (size_t)r * DIM + i0 + c8);
        }
#pragma unroll
        for (int it = 0; it < 4; ++it) {
            int idx = tid + it * 256;
            int r = idx >> 3, c8 = (idx & 7) * 8;
            const __half* src = (r < 64 ? wk + (size_t)r * DIM
                                        : wv + (size_t)(r - 64) * DIM) + i0 + c8;
            *(uint4*)&Ts[r][c8] = *(const uint4*)src;
        }
        __syncthreads();

#pragma unroll
        for (int ks = 0; ks < 4; ++ks) {
            unsigned a[2][4], bfr[2][4];
            unsigned colb = (unsigned)(ks * 32 + khalf * 16);
#pragma unroll
            for (int mt = 0; mt < 2; ++mt)
                ldsm4(a[mt], hb + rowA[mt] * 144 + colb);
#pragma unroll
            for (int p = 0; p < 2; ++p)
                ldsm4(bfr[p], tb + rowB[p] * 144 + colb);
#pragma unroll
            for (int mt = 0; mt < 2; ++mt)
#pragma unroll
                for (int u = 0; u < 4; ++u) {
                    int p = u >> 1, hh = u & 1;
                    mma16816(acc[mt][u], a[mt], bfr[p][hh], bfr[p][2 + hh]);
                }
        }
    }

    float* pkk = g_part + (size_t)(sp * BH + bh) * 2 * 4096;
    float* pkv = pkk + 4096;
#pragma unroll
    for (int mt = 0; mt < 2; ++mt) {
        int d = wm + mt * 16 + g4;
#pragma unroll
        for (int u = 0; u < 4; ++u) {
            int j = wn + u * 8 + tg * 2;
            float* dst = (j < 64) ? (pkk + d * 64 + j) : (pkv + d * 64 + (j - 64));
            *(float2*)dst = make_float2(acc[mt][u][0], acc[mt][u][1]);
            float* dst2 = (j < 64) ? (pkk + (d + 8) * 64 + j)
                                   : (pkv + (d + 8) * 64 + (j - 64));
            *(float2*)dst2 = make_float2(acc[mt][u][2], acc[mt][u][3]);
        }
    }
}

// ------- reduce partials, solve (kk+aI) X = ktv, column softmax ---------------
__global__ __launch_bounds__(256) void solve_kernel(
    const float* __restrict__ alpha_p, const float* __restrict__ temp_p)
{
    int bh = blockIdx.x;
    __shared__ float A[64][65];
    __shared__ float X[64][65];
    int tid = threadIdx.x;

    for (int i = tid; i < 4096; i += 256) {
        float skk = 0.0f, skv = 0.0f;
#pragma unroll
        for (int s = 0; s < KS4; ++s) {
            const float* p = g_part + ((size_t)(s * BH + bh) * 2) * 4096;
            skk += p[i];
            skv += p[4096 + i];
        }
        A[i >> 6][i & 63] = skk;
        X[i >> 6][i & 63] = skv;
    }
    __syncthreads();
    if (tid < 64) A[tid][tid] += alpha_p[0];

    int r  = tid >> 2;
    int c0 = (tid & 3) * 16;
    for (int pp = 0; pp < 64; ++pp) {
        __syncthreads();
        float pinv = 1.0f / A[pp][pp];
        __syncthreads();
        if (tid < 64)      A[pp][tid]      *= pinv;
        else if (tid < 128) X[pp][tid - 64] *= pinv;
        __syncthreads();
        float f = (r != pp) ? A[r][pp] : 0.0f;
        __syncthreads();
        if (r != pp) {
#pragma unroll
            for (int c = 0; c < 16; ++c) {
                A[r][c0 + c] = fmaf(-f, A[pp][c0 + c], A[r][c0 + c]);
                X[r][c0 + c] = fmaf(-f, X[pp][c0 + c], X[r][c0 + c]);
            }
        }
    }
    __syncthreads();

    if (tid < 64) {
        float invt = 1.0f / temp_p[0];
        float mx = -1e30f;
        for (int d = 0; d < 64; ++d) mx = fmaxf(mx, X[d][tid] * invt);
        float s = 0.0f;
        for (int d = 0; d < 64; ++d) s += expf(X[d][tid] * invt - mx);
        float inv_s = 1.0f / s;
        for (int d = 0; d < 64; ++d)
            g_amap[(size_t)bh * 4096 + d * 64 + tid] =
                expf(X[d][tid] * invt - mx) * inv_s;
    }
}

// ---------- fold1: W'_b[din, h*64+j] = sum_e Wq[h*64+e, din] * amap[e, j] -----
__global__ __launch_bounds__(256) void fold1_kernel()
{
    int bh = blockIdx.x;
    int chunk = blockIdx.y;
    int b = bh >> 4, h = bh & 15;

    __shared__ __half WqS[64][256];
    __shared__ float  AmS[64][64];
    int tid = threadIdx.x;

    const __half* wq = g_wh[0] + (size_t)(h * 64) * DIM + chunk * 256;
#pragma unroll
    for (int it = 0; it < 8; ++it) {
        int idx = tid + it * 256;
        int e = idx >> 5;
        int c8 = (idx & 31) * 8;
        *(uint4*)&WqS[e][c8] = *(const uint4*)(wq + (size_t)e * DIM + c8);
    }
#pragma unroll
    for (int it = 0; it < 4; ++it) {
        int idx = tid + it * 256;
        int e = idx >> 4;
        int j4 = (idx & 15) * 4;
        *(float4*)&AmS[e][j4] =
            *(const float4*)&g_amap[(size_t)bh * 4096 + e * 64 + j4];
    }
    __syncthreads();

    int ty = tid >> 3;
    int tx = tid & 7;
    float acc[8][8];
#pragma unroll
    for (int i = 0; i < 8; ++i)
#pragma unroll
        for (int j = 0; j < 8; ++j) acc[i][j] = 0.0f;

#pragma unroll 4
    for (int e = 0; e < 64; ++e) {
        __half ah[8];
        *(uint4*)ah = *(const uint4*)&WqS[e][ty * 8];
        float bv[8];
        float4 b0 = *(const float4*)&AmS[e][tx * 8];
        float4 b1 = *(const float4*)&AmS[e][tx * 8 + 4];
        bv[0]=b0.x; bv[1]=b0.y; bv[2]=b0.z; bv[3]=b0.w;
        bv[4]=b1.x; bv[5]=b1.y; bv[6]=b1.z; bv[7]=b1.w;
#pragma unroll
        for (int i = 0; i < 8; ++i) {
            float av = __half2float(ah[i]);
#pragma unroll
            for (int j = 0; j < 8; ++j) acc[i][j] = fmaf(av, bv[j], acc[i][j]);
        }
    }

    __half* wp = g_wp + (size_t)b * DIM * DIM;
#pragma unroll
    for (int i = 0; i < 8; ++i) {
        int din = chunk * 256 + ty * 8 + i;
        __half o[8];
#pragma unroll
        for (int j = 0; j < 8; ++j) o[j] = __float2half_rn(acc[i][j]);
        *(uint4*)&wp[(size_t)din * DIM + h * 64 + tx * 8] = *(const uint4*)o;
    }
}

// ---------------- LayerNorm(proj(fp16) + x(f32)) ------------------------------
__global__ __launch_bounds__(256) void ln_kernel(
    const float* __restrict__ x, const float* __restrict__ gamma,
    const float* __restrict__ beta, float* __restrict__ out)
{
    int row = blockIdx.x;
    int tid = threadIdx.x;
    const __half* pr = g_projh + (size_t)row * DIM;
    const float*  xr = x       + (size_t)row * DIM;

    uint2 pu = *(const uint2*)(pr + tid * 4);
    __half2 p0 = *reinterpret_cast<__half2*>(&pu.x);
    __half2 p1 = *reinterpret_cast<__half2*>(&pu.y);
    float4 xv = *(const float4*)(xr + tid * 4);
    float v[4] = { __low2float(p0) + xv.x, __high2float(p0) + xv.y,
                   __low2float(p1) + xv.z, __high2float(p1) + xv.w };

    float s = v[0] + v[1] + v[2] + v[3];
    float s2 = v[0]*v[0] + v[1]*v[1] + v[2]*v[2] + v[3]*v[3];

#pragma unroll
    for (int o = 16; o > 0; o >>= 1) {
        s  += __shfl_xor_sync(0xFFFFFFFFu, s,  o);
        s2 += __shfl_xor_sync(0xFFFFFFFFu, s2, o);
    }
    __shared__ float rs[8], rs2[8];
    int wid = tid >> 5, lane = tid & 31;
    if (lane == 0) { rs[wid] = s; rs2[wid] = s2; }
    __syncthreads();
    if (wid == 0) {
        float a  = (lane < 8) ? rs[lane]  : 0.0f;
        float a2 = (lane < 8) ? rs2[lane] : 0.0f;
#pragma unroll
        for (int o = 4; o > 0; o >>= 1) {
            a  += __shfl_xor_sync(0xFFFFFFFFu, a,  o);
            a2 += __shfl_xor_sync(0xFFFFFFFFu, a2, o);
        }
        if (lane == 0) { rs[0] = a; rs2[0] = a2; }
    }
    __syncthreads();
    float mu  = rs[0]  * (1.0f / DIM);
    float var = rs2[0] * (1.0f / DIM) - mu * mu;
    float rstd = rsqrtf(var + LNEPS);

    const float* gp = gamma + tid * 4;
    const float* bp = beta  + tid * 4;
    float4 o4;
    o4.x = (v[0] - mu) * rstd * gp[0] + bp[0];
    o4.y = (v[1] - mu) * rstd * gp[1] + bp[1];
    o4.z = (v[2] - mu) * rstd * gp[2] + bp[2];
    o4.w = (v[3] - mu) * rstd * gp[3] + bp[3];
    *(float4*)(out + (size_t)row * DIM + tid * 4) = o4;
}

// ---------------- host launcher ----------------------------------------------
extern "C" void kernel_launch(void* const* d_in, const int* in_sizes, int n_in,
                              void* d_out, int out_size)
{
    (void)in_sizes; (void)n_in; (void)out_size;
    const float* x     = (const float*)d_in[0];
    const float* Wq    = (const float*)d_in[1];
    const float* Wk    = (const float*)d_in[2];
    const float* Wv    = (const float*)d_in[3];
    const float* Wo    = (const float*)d_in[4];
    const float* bo    = (const float*)d_in[5];
    const float* alpha = (const float*)d_in[6];
    const float* temp  = (const float*)d_in[7];
    const float* gamma = (const float*)d_in[8];
    const float* beta  = (const float*)d_in[9];
    float* out = (float*)d_out;

    __half *xh, *wh, *gm, *hk, *wpp, *w2p, *projh;
    cudaGetSymbolAddress((void**)&xh,    g_xh);
    cudaGetSymbolAddress((void**)&wh,    g_wh);
    cudaGetSymbolAddress((void**)&gm,    g_gm);
    cudaGetSymbolAddress((void**)&hk,    g_hk);
    cudaGetSymbolAddress((void**)&wpp,   g_wp);
    cudaGetSymbolAddress((void**)&w2p,   g_w2);
    cudaGetSymbolAddress((void**)&projh, g_projh);

    const int SMEM_GEMM = 98304;
    cudaFuncSetAttribute(gemm_f16,
                         cudaFuncAttributeMaxDynamicSharedMemorySize, SMEM_GEMM);
    cudaFuncSetAttribute(gsplit_kernel,
                         cudaFuncAttributeMaxDynamicSharedMemorySize, SMEM_GEMM);

    const size_t WSZ = (size_t)DIM * DIM;
    convh_kernel<<<DIM*DIM/2048, 256>>>(Wq, wh + 0*WSZ);
    convh_kernel<<<DIM*DIM/2048, 256>>>(Wk, wh + 1*WSZ);
    convh_kernel<<<DIM*DIM/2048, 256>>>(Wv, wh + 2*WSZ);
    convh_kernel<<<DIM*DIM/2048, 256>>>(Wo, wh + 3*WSZ);

    // fused x conversion + transpose
    convx_kernel<<<dim3(DIM/64, SEQ/64, BATCH), 256>>>(x);

    // G_b = X_b^T X_b: split-K=2 f32 partials on triangle, then reduce+mirror
    gsplit_kernel<<<dim3(8, 8, BATCH*2), 256, SMEM_GEMM>>>();
    greduce_kernel<<<dim3(8, 8, BATCH), 256>>>();

    // Hk_b = Wk @ G_b
    gemm_f16<<<dim3(DIM/128, DIM/128, BATCH), 256, SMEM_GEMM>>>(
        wh + 1*WSZ, gm, nullptr, hk, DIM, DIM/64, DIM, DIM, 0, WSZ, WSZ);

    // per-head Gram blocks (i-split) + solve + softmax
    kkt2_kernel<<<dim3(BH, KS4), 256>>>();
    solve_kernel<<<BH, 256>>>(alpha, temp);

    // fold amap into weights
    fold1_kernel<<<dim3(BH, DIM/256), 256>>>();
    gemm_f16<<<dim3(DIM/128, DIM/128, BATCH), 256, SMEM_GEMM>>>(
        wh + 3*WSZ, wpp, nullptr, w2p, DIM, DIM/64, DIM, DIM, 0, WSZ, WSZ);

    // proj[b] = x[b] @ W2_b + bo  (fp16 out)
    gemm_f16<<<dim3(DIM/128, SEQ/128, BATCH), 256, SMEM_GEMM>>>(
        xh, w2p, bo, projh, DIM, DIM/64, DIM, DIM,
        (size_t)SEQ*DIM, WSZ, (size_t)SEQ*DIM);

    ln_kernel<<<MTOT, 256>>>(x, gamma, beta, out);
}